// round 13
// baseline (speedup 1.0000x reference)
#include <cuda_runtime.h>
#include <cuda_bf16.h>
#include <math.h>
#include <stdint.h>

// ---------------- problem constants ----------------
#define Bsz  8
#define Lseq 2049
#define Dmod 256
#define DI   512
#define DS   16
#define DRK  16
#define LB   1025
#define LC   1028
#define Stok 64
#define NXP  48
#define LCP  1040   // LC padded to 16
#define CT   8      // conv timesteps per block

#define SZ_U    (Bsz*LC*DI)
#define SZ_DBC  (Bsz*LC*NXP)
#define ML      (Bsz*Lseq)
#define MC      (Bsz*LC)

// ---------------- fp32 scratch ----------------
__device__ float g_xi[Bsz*Lseq*DI];
__device__ float g_u[2*SZ_U];          // f, b
__device__ float g_dbc[2*SZ_DBC];      // f, b (atomic accum; B/C interleaved cols)
__device__ float g_delta[2*SZ_U];
__device__ float g_ysc[2*SZ_U];        // scan outputs f, b
__device__ float g_y[Bsz*LC*DI];
__device__ float g_mf[Bsz*LC];
__device__ float g_mb[Bsz*LC];
__device__ float g_mc[Bsz*LC];
__device__ float g_dist[Bsz*LC*2];
__device__ float g_xpf[Bsz*Stok*Dmod];
__device__ float g_zpacc[Bsz*Stok*DI];     // atomic accum (pre-silu)
__device__ float g_scores[Bsz*LC*Stok];    // atomic accum
__device__ float g_atok[Bsz*Stok*LCP];
__device__ float g_tyacc[Bsz*Stok*DI];     // atomic accum
__device__ float g_Tacc[Bsz*Stok*DI];      // atomic accum (pre-gate)
__device__ float g_bxp[2*128];
__device__ float g_bdt[2*DI];

// ---------------- bf16 planes ----------------
__device__ __nv_bfloat16 g_xh[ML*Dmod],       g_xl[ML*Dmod];          // x pre-split
__device__ __nv_bfloat16 g_Winx_h[DI*Dmod],   g_Winx_l[DI*Dmod];
__device__ __nv_bfloat16 g_Winz_h[DI*Dmod],   g_Winz_l[DI*Dmod];
__device__ __nv_bfloat16 g_Wxp_h[2*128*DI],   g_Wxp_l[2*128*DI];      // rows permuted (B/C interleave)
__device__ __nv_bfloat16 g_Wdt_h[2*DI*DRK],   g_Wdt_l[2*DI*DRK];
__device__ __nv_bfloat16 g_Wpro_h[DI*2*DI],   g_Wpro_l[DI*2*DI];
__device__ __nv_bfloat16 g_wA_h[128*DI],      g_wA_l[128*DI];
__device__ __nv_bfloat16 g_wV_h[DI*DI],       g_wV_l[DI*DI];
__device__ __nv_bfloat16 g_Wout_h[Dmod*DI],   g_Wout_l[Dmod*DI];
__device__ __nv_bfloat16 g_yh[Bsz*LC*DI+16*DI], g_yl[Bsz*LC*DI+16*DI]; // slack rows stay 0

__device__ __forceinline__ void splitv(float v, __nv_bfloat16& h, __nv_bfloat16& l) {
    h = __float2bfloat16(v);
    l = __float2bfloat16(v - __bfloat162float(h));
}

// dbc column permutation: rows 0-15 identity (dr); output row 16+2j <- B_j (src 16+j);
// output row 17+2j <- C_j (src 32+j); rows >= 48 zero.
__device__ __forceinline__ int wxp_srcrow(int r) {
    if (r < 16) return r;
    if (r >= 48) return -1;
    int q = r - 16;
    return (q & 1) ? (32 + (q >> 1)) : (16 + (q >> 1));
}

// ---------------- fused init: zero accums + weight splits + x split + pool ----------------
#define Z1 (Bsz*Stok*DI)
#define Z2 (2*SZ_DBC)
#define Z3 (Bsz*LC*Stok)
#define Z4 (Bsz*Stok*DI)
#define Z5 (Bsz*Stok*DI)
#define Z6 (Bsz*Stok*Dmod)
#define ZTOT (Z1+Z2+Z3+Z4+Z5+Z6)
#define WTOT 1393920
#define XTOT (ML*Dmod)
#define PTOT (Bsz*Stok*Dmod)
#define INIT_TOT (ZTOT + WTOT + XTOT + PTOT)

__global__ void init_kernel(const float* __restrict__ x,
                            const float* __restrict__ Winx, const float* __restrict__ Winz,
                            const float* __restrict__ Wxpf, const float* __restrict__ Wxpb,
                            const float* __restrict__ Wdtf, const float* __restrict__ Wdtb,
                            const float* __restrict__ Wpro, const float* __restrict__ wA,
                            const float* __restrict__ wV,   const float* __restrict__ Wout,
                            const float* __restrict__ bxpf, const float* __restrict__ bxpb,
                            const float* __restrict__ bdtf, const float* __restrict__ bdtb,
                            float* __restrict__ dout)
{
    long long i = (long long)blockIdx.x * 256 + threadIdx.x;
    __nv_bfloat16 h, l;
    if (i < Z1) { g_zpacc[i] = 0.f; return; }  i -= Z1;
    if (i < Z2) { g_dbc[i] = 0.f; return; }    i -= Z2;
    if (i < Z3) { g_scores[i] = 0.f; return; } i -= Z3;
    if (i < Z4) { g_tyacc[i] = 0.f; return; }  i -= Z4;
    if (i < Z5) { g_Tacc[i] = 0.f; return; }   i -= Z5;
    if (i < Z6) { dout[i] = 0.f; return; }     i -= Z6;
    if (i < 131072) { splitv(Winx[i], h, l); g_Winx_h[i] = h; g_Winx_l[i] = l; return; }
    i -= 131072;
    if (i < 131072) { splitv(Winz[i], h, l); g_Winz_h[i] = h; g_Winz_l[i] = l; return; }
    i -= 131072;
    if (i < 131072) { int dir = i >> 16, j = i & 65535;
        int r = j >> 9, c = j & 511;
        const float* W = dir ? Wxpb : Wxpf;
        int sr = wxp_srcrow(r);
        splitv(sr >= 0 ? W[sr * DI + c] : 0.f, h, l);
        g_Wxp_h[i] = h; g_Wxp_l[i] = l; return; }
    i -= 131072;
    if (i < 16384) { int dir = i >> 13, j = i & 8191;
        const float* W = dir ? Wdtb : Wdtf;
        splitv(W[j], h, l); g_Wdt_h[i] = h; g_Wdt_l[i] = l; return; }
    i -= 16384;
    if (i < 524288) { splitv(Wpro[i], h, l); g_Wpro_h[i] = h; g_Wpro_l[i] = l; return; }
    i -= 524288;
    if (i < 65536) { int r = i >> 9, c = i & 511;
        splitv(r < Stok ? wA[r * DI + c] : 0.f, h, l);
        g_wA_h[i] = h; g_wA_l[i] = l; return; }
    i -= 65536;
    if (i < 262144) { splitv(wV[i], h, l); g_wV_h[i] = h; g_wV_l[i] = l; return; }
    i -= 262144;
    if (i < 131072) { splitv(Wout[i], h, l); g_Wout_h[i] = h; g_Wout_l[i] = l; return; }
    i -= 131072;
    if (i < 256) { int dir = i >> 7, r = i & 127;
        const float* bsrc = dir ? bxpb : bxpf;
        int sr = wxp_srcrow(r);
        g_bxp[i] = (sr >= 0) ? bsrc[sr] : 0.f; return; }
    i -= 256;
    if (i < 1024) { int dir = i >> 9, r = i & 511;
        g_bdt[i] = dir ? bdtb[r] : bdtf[r]; return; }
    i -= 1024;
    if (i < XTOT) { splitv(x[i], h, l); g_xh[i] = h; g_xl[i] = l; return; }
    i -= XTOT;
    if (i < PTOT) {   // pooling: xp[b,s,d] = mean_l x[b, l in [s0,e), d]
        int d = (int)(i % Dmod);
        int rest = (int)(i / Dmod);
        int s = rest % Stok;
        int b = rest / Stok;
        int s0 = (s * Lseq) / Stok;
        int e  = ((s + 1) * Lseq + Stok - 1) / Stok;
        float acc = 0.f;
        for (int lq = s0; lq < e; lq++) acc += x[((long long)b * Lseq + lq) * Dmod + d];
        g_xpf[((long long)b * Stok + s) * Dmod + d] = acc / (float)(e - s0);
    }
}

// ---------------- shared helpers ----------------
#define SAS 24

__device__ __forceinline__ uint32_t s2u(const void* p) {
    return (uint32_t)__cvta_generic_to_shared(p);
}
__device__ __forceinline__ void ldsm4(uint32_t r[4], uint32_t addr) {
    asm volatile("ldmatrix.sync.aligned.m8n8.x4.shared.b16 {%0,%1,%2,%3}, [%4];"
                 : "=r"(r[0]), "=r"(r[1]), "=r"(r[2]), "=r"(r[3]) : "r"(addr));
}
__device__ __forceinline__ void mma16816(float c[4], const uint32_t a[4],
                                         uint32_t b0, uint32_t b1) {
    asm volatile(
        "mma.sync.aligned.m16n8k16.row.col.f32.bf16.bf16.f32 "
        "{%0,%1,%2,%3},{%4,%5,%6,%7},{%8,%9},{%0,%1,%2,%3};"
        : "+f"(c[0]), "+f"(c[1]), "+f"(c[2]), "+f"(c[3])
        : "r"(a[0]), "r"(a[1]), "r"(a[2]), "r"(a[3]), "r"(b0), "r"(b1));
}
__device__ __forceinline__ void cpasync16(uint32_t dst, const void* src, int szbytes) {
    asm volatile("cp.async.ca.shared.global [%0], [%1], 16, %2;"
                 :: "r"(dst), "l"(src), "r"(szbytes));
}

// =====================================================================
// hgemm4: C = A * op(B planes), 3-split bf16 MMA (round-6 core).
// AMODE: 0 = plain fp32 A; 1 = A * silu(Ag); 2 = concat A built on the
// fly from g_ysc/g_mf/g_mb (row=(b,t); cols<512 = yf*mf, >=512 = yb*mbrev).
// =====================================================================
template<int TB, int AMODE>
__global__ __launch_bounds__(256, 2)
void hgemm4(const float* __restrict__ A, const float* __restrict__ Ag,
            const __nv_bfloat16* __restrict__ Bh, const __nv_bfloat16* __restrict__ Bl,
            const float* __restrict__ bias, const float* __restrict__ emul,
            float* __restrict__ C,
            int M, int N, int K, int lda, int ldb, int ldc, int Nout, int act, int KS,
            long long sA, long long sB, long long sC, long long sBias)
{
    __shared__ __align__(16) __nv_bfloat16 As_hi[128][SAS];
    __shared__ __align__(16) __nv_bfloat16 As_lo[128][SAS];
    __shared__ __align__(16) __nv_bfloat16 Bs_hi[128][SAS];
    __shared__ __align__(16) __nv_bfloat16 Bs_lo[128][SAS];

    int bz  = blockIdx.z;
    int dir = bz / KS;
    int ks  = bz % KS;
    A  += dir * sA;
    Bh += dir * sB; Bl += dir * sB;
    if (bias) bias += dir * sBias;
    int kchunk = K / KS;
    int kb = ks * kchunk, ke = kb + kchunk;

    int tid  = threadIdx.x;
    int lane = tid & 31;
    int wid  = tid >> 5;
    int wm0  = (wid >> 2) * 64;
    int wn0  = (wid & 3) * 32;
    int row0 = blockIdx.y * 128;
    int col0 = blockIdx.x * 128;

    int lr = lane & 15;
    int lc = (lane >> 4) * 8;

    int ar = tid >> 1;
    int ac = (tid & 1) * 8;
    int gm = row0 + ar;
    bool mok = gm < M;
    const float* Ap = A + (long long)gm * lda + ac;
    const float* Gp = (AMODE == 1) ? (Ag + (long long)gm * lda + ac) : nullptr;

    // AMODE 2 setup: row -> (b,t), masks and source rows
    const float* src0 = nullptr;
    const float* src1 = nullptr;
    float mk0 = 0.f, mk1 = 0.f;
    if (AMODE == 2) {
        if (mok) {
            int bq = gm / LC;
            int tq = gm - bq * LC;
            mk0 = g_mf[bq * LC + tq];
            mk1 = g_mb[bq * LC + (LC - 1 - tq)];
            src0 = g_ysc + ((long long)bq * LC + tq) * DI + ac;
            src1 = g_ysc + (long long)SZ_U + ((long long)bq * LC + tq) * DI + ac;
        }
    }

    const __nv_bfloat16 *Bph = nullptr, *Bpl = nullptr;
    int bkk = 0, bnc = 0;
    if (TB == 1) {
        Bph = Bh + (long long)(col0 + ar) * ldb + ac;
        Bpl = Bl + (long long)(col0 + ar) * ldb + ac;
    } else {
        bkk = tid >> 4;
        bnc = (tid & 15) * 8;
        Bph = Bh + col0 + bnc;
        Bpl = Bl + col0 + bnc;
    }

    float4 ra0 = make_float4(0,0,0,0), ra1 = make_float4(0,0,0,0);
    float4 rg0 = make_float4(0,0,0,0), rg1 = make_float4(0,0,0,0);
    uint4 rbh, rbl;

    // preload kb
    if (AMODE == 2) {
        if (mok) {
            const float* s; float sc;
            if (kb < DI) { s = src0 + kb; sc = mk0; }
            else         { s = src1 + (kb - DI); sc = mk1; }
            ra0 = *(const float4*)(s); ra1 = *(const float4*)(s + 4);
            ra0.x*=sc; ra0.y*=sc; ra0.z*=sc; ra0.w*=sc;
            ra1.x*=sc; ra1.y*=sc; ra1.z*=sc; ra1.w*=sc;
        }
    } else if (mok) {
        ra0 = *(const float4*)(Ap + kb); ra1 = *(const float4*)(Ap + kb + 4);
        if (AMODE == 1) { rg0 = *(const float4*)(Gp + kb); rg1 = *(const float4*)(Gp + kb + 4); }
    }
    if (TB == 1) {
        rbh = *(const uint4*)(Bph + kb); rbl = *(const uint4*)(Bpl + kb);
    } else {
        rbh = *(const uint4*)(Bph + (long long)(kb + bkk) * ldb);
        rbl = *(const uint4*)(Bpl + (long long)(kb + bkk) * ldb);
    }

    float acc[4][4][4];
    #pragma unroll
    for (int i = 0; i < 4; i++)
        #pragma unroll
        for (int j = 0; j < 4; j++)
            #pragma unroll
            for (int q = 0; q < 4; q++) acc[i][j][q] = 0.f;

    for (int k0 = kb; k0 < ke; k0 += 16) {
        {
            float av[8] = {ra0.x, ra0.y, ra0.z, ra0.w, ra1.x, ra1.y, ra1.z, ra1.w};
            if (AMODE == 1) {
                float gv[8] = {rg0.x, rg0.y, rg0.z, rg0.w, rg1.x, rg1.y, rg1.z, rg1.w};
                #pragma unroll
                for (int j = 0; j < 8; j++) av[j] *= gv[j] / (1.f + expf(-gv[j]));
            }
            __nv_bfloat16 hh[8], ll[8];
            #pragma unroll
            for (int j = 0; j < 8; j++) splitv(av[j], hh[j], ll[j]);
            *(uint4*)&As_hi[ar][ac] = *(uint4*)hh;
            *(uint4*)&As_lo[ar][ac] = *(uint4*)ll;
        }
        if (TB == 1) {
            *(uint4*)&Bs_hi[ar][ac] = rbh;
            *(uint4*)&Bs_lo[ar][ac] = rbl;
        } else {
            __nv_bfloat16 th[8], tl[8];
            *(uint4*)th = rbh; *(uint4*)tl = rbl;
            #pragma unroll
            for (int j = 0; j < 8; j++) {
                Bs_hi[bnc + j][bkk] = th[j];
                Bs_lo[bnc + j][bkk] = tl[j];
            }
        }
        __syncthreads();

        if (k0 + 16 < ke) {
            int kn = k0 + 16;
            if (AMODE == 2) {
                if (mok) {
                    const float* s; float sc;
                    if (kn < DI) { s = src0 + kn; sc = mk0; }
                    else         { s = src1 + (kn - DI); sc = mk1; }
                    ra0 = *(const float4*)(s); ra1 = *(const float4*)(s + 4);
                    ra0.x*=sc; ra0.y*=sc; ra0.z*=sc; ra0.w*=sc;
                    ra1.x*=sc; ra1.y*=sc; ra1.z*=sc; ra1.w*=sc;
                }
            } else if (mok) {
                ra0 = *(const float4*)(Ap + kn);
                ra1 = *(const float4*)(Ap + kn + 4);
                if (AMODE == 1) {
                    rg0 = *(const float4*)(Gp + kn);
                    rg1 = *(const float4*)(Gp + kn + 4);
                }
            }
            if (TB == 1) {
                rbh = *(const uint4*)(Bph + kn);
                rbl = *(const uint4*)(Bpl + kn);
            } else {
                rbh = *(const uint4*)(Bph + (long long)(kn + bkk) * ldb);
                rbl = *(const uint4*)(Bpl + (long long)(kn + bkk) * ldb);
            }
        }

        uint32_t bhf[2][4], blf[2][4];
        #pragma unroll
        for (int ng = 0; ng < 2; ng++) {
            ldsm4(bhf[ng], s2u(&Bs_hi[wn0 + ng * 16 + lr][lc]));
            ldsm4(blf[ng], s2u(&Bs_lo[wn0 + ng * 16 + lr][lc]));
        }
        #pragma unroll
        for (int mt = 0; mt < 4; mt++) {
            uint32_t a_h[4], a_l[4];
            ldsm4(a_h, s2u(&As_hi[wm0 + mt * 16 + lr][lc]));
            ldsm4(a_l, s2u(&As_lo[wm0 + mt * 16 + lr][lc]));
            #pragma unroll
            for (int nt = 0; nt < 4; nt++) {
                int ng = nt >> 1, sl = nt & 1;
                mma16816(acc[mt][nt], a_h, bhf[ng][sl], bhf[ng][sl + 2]);
                mma16816(acc[mt][nt], a_h, blf[ng][sl], blf[ng][sl + 2]);
                mma16816(acc[mt][nt], a_l, bhf[ng][sl], bhf[ng][sl + 2]);
            }
        }
        __syncthreads();
    }

    int g = lane >> 2, t4 = lane & 3;
    #pragma unroll
    for (int mt = 0; mt < 4; mt++) {
        #pragma unroll
        for (int nt = 0; nt < 4; nt++) {
            int cb = col0 + wn0 + nt * 8 + 2 * t4;
            if (cb >= Nout) continue;
            float b0 = 0.f, b1 = 0.f;
            if (bias && (KS == 1 || ks == 0)) { b0 = bias[cb]; b1 = bias[cb + 1]; }
            #pragma unroll
            for (int hrow = 0; hrow < 2; hrow++) {
                int m = row0 + wm0 + mt * 16 + g + hrow * 8;
                if (m >= M) continue;
                float v0 = acc[mt][nt][hrow * 2 + 0] + b0;
                float v1 = acc[mt][nt][hrow * 2 + 1] + b1;
                long long co = dir * sC + (long long)m * ldc + cb;
                if (KS > 1) {
                    atomicAdd(C + co, v0);
                    atomicAdd(C + co + 1, v1);
                } else {
                    if (act == 1) {
                        v0 = v0 / (1.f + expf(-v0));
                        v1 = v1 / (1.f + expf(-v1));
                    } else if (act == 2) {
                        v0 = (v0 > 20.f) ? v0 : log1pf(expf(v0));
                        v1 = (v1 > 20.f) ? v1 : log1pf(expf(v1));
                    }
                    if (emul) { v0 *= emul[co]; v1 *= emul[co + 1]; }
                    *(float2*)(C + co) = make_float2(v0, v1);
                }
            }
        }
    }
}

// =====================================================================
// hgemm_ca: big-GEMM specialist (xi only now).
// =====================================================================
#define CA_PL  (128*SAS)
#define CA_STG (4*CA_PL)
#define CA_SMEM_BYTES (3*CA_STG*2)

__global__ __launch_bounds__(256, 2)
void hgemm_ca(const __nv_bfloat16* __restrict__ Ah, const __nv_bfloat16* __restrict__ Al,
              const __nv_bfloat16* __restrict__ Bh, const __nv_bfloat16* __restrict__ Bl,
              const float* __restrict__ bias, float* __restrict__ C,
              int M, int N, int K, int lda, int ldb, int ldc)
{
    extern __shared__ __align__(16) __nv_bfloat16 sm[];
    uint32_t smb = s2u(sm);

    int tid  = threadIdx.x;
    int lane = tid & 31;
    int wid  = tid >> 5;
    int wm0  = (wid >> 2) * 64;
    int wn0  = (wid & 3) * 32;
    int row0 = blockIdx.y * 128;
    int col0 = blockIdx.x * 128;

    int lr = lane & 15;
    int lc = (lane >> 4) * 8;

    int ar = tid >> 1;
    int ac = (tid & 1) * 8;
    int gm = row0 + ar;
    int asz = (gm < M) ? 16 : 0;
    const __nv_bfloat16* Aph = Ah + (long long)gm * lda + ac;
    const __nv_bfloat16* Apl = Al + (long long)gm * lda + ac;
    const __nv_bfloat16* Bph = Bh + (long long)(col0 + ar) * ldb + ac;
    const __nv_bfloat16* Bpl = Bl + (long long)(col0 + ar) * ldb + ac;

    uint32_t offA_h = (uint32_t)(0 * CA_PL + ar * SAS + ac) * 2;
    uint32_t offA_l = (uint32_t)(1 * CA_PL + ar * SAS + ac) * 2;
    uint32_t offB_h = (uint32_t)(2 * CA_PL + ar * SAS + ac) * 2;
    uint32_t offB_l = (uint32_t)(3 * CA_PL + ar * SAS + ac) * 2;

    float acc[4][4][4];
    #pragma unroll
    for (int i = 0; i < 4; i++)
        #pragma unroll
        for (int j = 0; j < 4; j++)
            #pragma unroll
            for (int q = 0; q < 4; q++) acc[i][j][q] = 0.f;

    {
        uint32_t sb = smb;
        cpasync16(sb + offA_h, Aph + 0, asz);
        cpasync16(sb + offA_l, Apl + 0, asz);
        cpasync16(sb + offB_h, Bph + 0, 16);
        cpasync16(sb + offB_l, Bpl + 0, 16);
        asm volatile("cp.async.commit_group;" ::: "memory");
    }
    if (16 < K) {
        uint32_t sb = smb + CA_STG * 2;
        cpasync16(sb + offA_h, Aph + 16, asz);
        cpasync16(sb + offA_l, Apl + 16, asz);
        cpasync16(sb + offB_h, Bph + 16, 16);
        cpasync16(sb + offB_l, Bpl + 16, 16);
        asm volatile("cp.async.commit_group;" ::: "memory");
    } else {
        asm volatile("cp.async.commit_group;" ::: "memory");
    }

    int cur = 0;
    for (int k0 = 0; k0 < K; k0 += 16) {
        asm volatile("cp.async.wait_group 1;" ::: "memory");
        __syncthreads();

        uint32_t sb = smb + (uint32_t)cur * (CA_STG * 2);

        uint32_t bhf[2][4], blf[2][4];
        #pragma unroll
        for (int ng = 0; ng < 2; ng++) {
            uint32_t rb = (uint32_t)(wn0 + ng * 16 + lr) * SAS + lc;
            ldsm4(bhf[ng], sb + (uint32_t)(2 * CA_PL) * 2 + rb * 2);
            ldsm4(blf[ng], sb + (uint32_t)(3 * CA_PL) * 2 + rb * 2);
        }
        #pragma unroll
        for (int mt = 0; mt < 4; mt++) {
            uint32_t raddr = (uint32_t)(wm0 + mt * 16 + lr) * SAS + lc;
            uint32_t a_h[4], a_l[4];
            ldsm4(a_h, sb + raddr * 2);
            ldsm4(a_l, sb + (uint32_t)(CA_PL) * 2 + raddr * 2);
            #pragma unroll
            for (int nt = 0; nt < 4; nt++) {
                int ng = nt >> 1, sl = nt & 1;
                mma16816(acc[mt][nt], a_h, bhf[ng][sl], bhf[ng][sl + 2]);
                mma16816(acc[mt][nt], a_h, blf[ng][sl], blf[ng][sl + 2]);
                mma16816(acc[mt][nt], a_l, bhf[ng][sl], bhf[ng][sl + 2]);
            }
        }

        int nk = k0 + 32;
        if (nk < K) {
            int nst = cur + 2; if (nst >= 3) nst -= 3;
            uint32_t nb = smb + (uint32_t)nst * (CA_STG * 2);
            cpasync16(nb + offA_h, Aph + nk, asz);
            cpasync16(nb + offA_l, Apl + nk, asz);
            cpasync16(nb + offB_h, Bph + nk, 16);
            cpasync16(nb + offB_l, Bpl + nk, 16);
        }
        asm volatile("cp.async.commit_group;" ::: "memory");

        cur++; if (cur == 3) cur = 0;
    }

    int g = lane >> 2, t4 = lane & 3;
    #pragma unroll
    for (int mt = 0; mt < 4; mt++) {
        #pragma unroll
        for (int nt = 0; nt < 4; nt++) {
            int cb = col0 + wn0 + nt * 8 + 2 * t4;
            float b0 = 0.f, b1 = 0.f;
            if (bias) { b0 = bias[cb]; b1 = bias[cb + 1]; }
            #pragma unroll
            for (int hrow = 0; hrow < 2; hrow++) {
                int m = row0 + wm0 + mt * 16 + g + hrow * 8;
                if (m >= M) continue;
                float v0 = acc[mt][nt][hrow * 2 + 0] + b0;
                float v1 = acc[mt][nt][hrow * 2 + 1] + b1;
                *(float2*)(C + (long long)m * ldc + cb) = make_float2(v0, v1);
            }
        }
    }
}

// ---------------- depthwise conv + SiLU, t-tiled (CT steps/block), both dirs ----------------
__global__ void conv_silu2_kernel(const float* __restrict__ xi,
                                  const float* __restrict__ wf, const float* __restrict__ bf,
                                  const float* __restrict__ wb, const float* __restrict__ bb)
{
    int t0 = blockIdx.x * CT;
    int b = blockIdx.y;
    int back = blockIdx.z;
    int c = threadIdx.x;
    const float* w  = back ? wb : wf;
    float bias      = back ? bb[c] : bf[c];
    float* out      = g_u + (long long)back * SZ_U;

    float w0 = w[c * 4 + 0], w1 = w[c * 4 + 1], w2 = w[c * 4 + 2], w3 = w[c * 4 + 3];

    float xv[CT + 3];
    #pragma unroll
    for (int j = 0; j < CT + 3; j++) {
        int i = t0 + j - 3;
        float v = 0.f;
        if (i >= 0 && i < LB) {
            int l = back ? (Lseq - 1 - i) : i;
            v = xi[((long long)b * Lseq + l) * DI + c];
        }
        xv[j] = v;
    }
    #pragma unroll
    for (int j = 0; j < CT; j++) {
        int t = t0 + j;
        if (t >= LC) break;
        float acc = bias;
        acc = fmaf(w0, xv[j],     acc);
        acc = fmaf(w1, xv[j + 1], acc);
        acc = fmaf(w2, xv[j + 2], acc);
        acc = fmaf(w3, xv[j + 3], acc);
        out[((long long)b * LC + t) * DI + c] = acc / (1.f + expf(-acc));
    }
}

// ---------------- selective scans: 4 states/lane, 4 lanes/channel ----------------
__global__ __launch_bounds__(256)
void scan2_kernel(const float* __restrict__ A_log_f, const float* __restrict__ D_f,
                  const float* __restrict__ A_log_b, const float* __restrict__ D_b)
{
    int back = blockIdx.y;
    const float* u     = g_u     + (long long)back * SZ_U;
    const float* delta = g_delta + (long long)back * SZ_U;
    const float* dbc   = g_dbc   + (long long)back * SZ_DBC;
    const float* A_log = back ? A_log_b : A_log_f;
    const float* Dp    = back ? D_b : D_f;
    float* y           = g_ysc   + (long long)back * SZ_U;

    int gid = blockIdx.x * 64 + (threadIdx.x >> 2);   // channel = b*512 + d
    int q = threadIdx.x & 3;                          // states 4q..4q+3
    int b = gid >> 9;
    int d = gid & 511;
    float4 al = *(const float4*)(A_log + d * 16 + 4 * q);
    float Av0 = -expf(al.x), Av1 = -expf(al.y), Av2 = -expf(al.z), Av3 = -expf(al.w);
    float Dd = Dp[d];
    float h0 = 0.f, h1 = 0.f, h2 = 0.f, h3 = 0.f;
    const float* db = dbc + (long long)b * LC * NXP + 16 + 8 * q; // interleaved (B,C) pairs
    const float* dl = delta + ((long long)b * LC) * DI + d;
    const float* uu = u     + ((long long)b * LC) * DI + d;
    float*       yy = y     + ((long long)b * LC) * DI + d;
    #pragma unroll 4
    for (int t = 0; t < LC; t++) {
        float de = __ldg(dl + (long long)t * DI);
        float uv = __ldg(uu + (long long)t * DI);
        float4 bc0 = __ldg((const float4*)(db + t * NXP));       // B0,C0,B1,C1
        float4 bc1 = __ldg((const float4*)(db + t * NXP + 4));   // B2,C2,B3,C3
        float deu = de * uv;
        h0 = fmaf(__expf(de * Av0), h0, deu * bc0.x);
        h1 = fmaf(__expf(de * Av1), h1, deu * bc0.z);
        h2 = fmaf(__expf(de * Av2), h2, deu * bc1.x);
        h3 = fmaf(__expf(de * Av3), h3, deu * bc1.z);
        float v = fmaf(h0, bc0.y, fmaf(h1, bc0.w, fmaf(h2, bc1.y, h3 * bc1.w)));
        v += __shfl_xor_sync(0xffffffffu, v, 2);
        v += __shfl_xor_sync(0xffffffffu, v, 1);
        if (q == 0) yy[(long long)t * DI] = fmaf(Dd, uv, v);
    }
}

// ---------------- gaussian masks ----------------
__global__ void dist2_kernel(int ref)
{
    int back = blockIdx.z;
    const float* y = g_ysc + (long long)back * SZ_U;
    float* dist = g_dist + back * (Bsz * LC);
    int b = blockIdx.y;
    int t = blockIdx.x * 8 + (threadIdx.x >> 5);
    int lane = threadIdx.x & 31;
    if (t >= LC) return;
    const float* yt = y + ((long long)b * LC + t) * DI;
    const float* yr = y + ((long long)b * LC + ref) * DI;
    float acc = 0.f;
    for (int d = lane; d < DI; d += 32) {
        float df = yt[d] - yr[d];
        acc = fmaf(df, df, acc);
    }
    #pragma unroll
    for (int o = 16; o; o >>= 1) acc += __shfl_xor_sync(0xffffffffu, acc, o);
    if (lane == 0) dist[b * LC + t] = sqrtf(fmaxf(acc, 1e-12f));
}

__global__ void dist_kernel(const float* __restrict__ y, float* __restrict__ dist, int ref)
{
    int b = blockIdx.y;
    int t = blockIdx.x * 8 + (threadIdx.x >> 5);
    int lane = threadIdx.x & 31;
    if (t >= LC) return;
    const float* yt = y + ((long long)b * LC + t) * DI;
    const float* yr = y + ((long long)b * LC + ref) * DI;
    float acc = 0.f;
    for (int d = lane; d < DI; d += 32) {
        float df = yt[d] - yr[d];
        acc = fmaf(df, df, acc);
    }
    #pragma unroll
    for (int o = 16; o; o >>= 1) acc += __shfl_xor_sync(0xffffffffu, acc, o);
    if (lane == 0) dist[b * LC + t] = sqrtf(fmaxf(acc, 1e-12f));
}

__device__ __forceinline__ void maskfin_body(const float* dist, float* m, int ref,
                                             float* red, int tid)
{
    float s = 0.f;
    for (int t = tid; t < LC; t += 512) s += dist[t];
    red[tid] = s; __syncthreads();
    for (int o = 256; o; o >>= 1) { if (tid < o) red[tid] += red[tid + o]; __syncthreads(); }
    float sigv = red[0] / (float)LC;
    __syncthreads();
    float si = ((float)ref * (float)(ref + 1) * 0.5f +
                (float)(LC - 1 - ref) * (float)(LC - ref) * 0.5f) / (float)LC;
    float c_i = 0.5f / (si * si);
    float c_v = 0.5f / (sigv * sigv);
    float nrm = 0.f;
    for (int t = tid; t < LC; t += 512) {
        float dt = (float)(t - ref);
        float dv = dist[t];
        float p = expf(-dt * dt * c_i - dv * dv * c_v);
        m[t] = p;
        nrm = fmaf(p, p, nrm);
    }
    red[tid] = nrm; __syncthreads();
    for (int o = 256; o; o >>= 1) { if (tid < o) red[tid] += red[tid + o]; __syncthreads(); }
    float inv = 1.f / fmaxf(sqrtf(red[0]), 1e-12f);
    __syncthreads();
    for (int t = tid; t < LC; t += 512) m[t] *= inv;
}

__global__ void maskfin2_kernel(int ref)
{
    __shared__ float red[512];
    int back = blockIdx.y;
    int b = blockIdx.x;
    const float* dist = g_dist + back * (Bsz * LC) + b * LC;
    float* m = (back ? g_mb : g_mf) + b * LC;
    maskfin_body(dist, m, ref, red, threadIdx.x);
}

__global__ void maskfin_kernel(const float* __restrict__ dist, float* __restrict__ m, int ref)
{
    __shared__ float red[512];
    int b = blockIdx.x;
    maskfin_body(dist + b * LC, m + b * LC, ref, red, threadIdx.x);
}

// y *= mc (in place) + bf16 split planes
__global__ void scale_y_kernel()
{
    int t = blockIdx.x, b = blockIdx.y, c = threadIdx.x;
    long long r = (long long)b * LC + t;
    float v = g_y[r * DI + c] * g_mc[b * LC + t];
    g_y[r * DI + c] = v;
    __nv_bfloat16 h, l; splitv(v, h, l);
    g_yh[r * DI + c] = h; g_yl[r * DI + c] = l;
}

// softmax over l per (b, token): fp32 Atok (B, Stok, LCP), pad zeroed
__global__ void softmax_kernel()
{
    __shared__ float sv[LC];
    __shared__ float red[256];
    int tt = blockIdx.x, b = blockIdx.y, tid = threadIdx.x;
    float mx = -1e30f;
    for (int l = tid; l < LC; l += 256) {
        float v = g_scores[((long long)b * LC + l) * Stok + tt];
        sv[l] = v; mx = fmaxf(mx, v);
    }
    red[tid] = mx; __syncthreads();
    for (int o = 128; o; o >>= 1) { if (tid < o) red[tid] = fmaxf(red[tid], red[tid + o]); __syncthreads(); }
    mx = red[0]; __syncthreads();
    float sum = 0.f;
    for (int l = tid; l < LC; l += 256) { float e = expf(sv[l] - mx); sv[l] = e; sum += e; }
    red[tid] = sum; __syncthreads();
    for (int o = 128; o; o >>= 1) { if (tid < o) red[tid] += red[tid + o]; __syncthreads(); }
    float inv = 1.f / red[0]; __syncthreads();
    long long base = ((long long)b * Stok + tt) * LCP;
    for (int l = tid; l < LC; l += 256) g_atok[base + l] = sv[l] * inv;
    if (tid < LCP - LC) g_atok[base + LC + tid] = 0.f;
}

// ---------------- host launcher ----------------
static inline int ceildiv(int a, int b) { return (a + b - 1) / b; }

extern "C" void kernel_launch(void* const* d_in, const int* in_sizes, int n_in,
                              void* d_out, int out_size)
{
    const float* x        = (const float*)d_in[0];
    const float* W_in_x   = (const float*)d_in[1];
    const float* W_in_z   = (const float*)d_in[2];
    const float* conv_w_f = (const float*)d_in[3];
    const float* conv_b_f = (const float*)d_in[4];
    const float* conv_w_b = (const float*)d_in[5];
    const float* conv_b_b = (const float*)d_in[6];
    const float* W_xp_f   = (const float*)d_in[7];
    const float* b_xp_f   = (const float*)d_in[8];
    const float* W_dt_f   = (const float*)d_in[9];
    const float* b_dt_f   = (const float*)d_in[10];
    const float* A_log_f  = (const float*)d_in[11];
    const float* D_f      = (const float*)d_in[12];
    const float* W_xp_b   = (const float*)d_in[13];
    const float* b_xp_b   = (const float*)d_in[14];
    const float* W_dt_b   = (const float*)d_in[15];
    const float* b_dt_b   = (const float*)d_in[16];
    const float* A_log_b  = (const float*)d_in[17];
    const float* D_b      = (const float*)d_in[18];
    const float* W_pro_to = (const float*)d_in[19];
    const float* b_pro_to = (const float*)d_in[20];
    const float* token_wA = (const float*)d_in[21];
    const float* token_wV = (const float*)d_in[22];
    const float* W_out    = (const float*)d_in[23];
    float* out = (float*)d_out;

    float *xi, *u, *dbc, *delta, *yy, *mc, *dist, *xpf, *zpacc;
    float *scores, *atok, *tyacc, *Tacc, *bxp, *bdt;
    cudaGetSymbolAddress((void**)&xi,    g_xi);
    cudaGetSymbolAddress((void**)&u,     g_u);
    cudaGetSymbolAddress((void**)&dbc,   g_dbc);
    cudaGetSymbolAddress((void**)&delta, g_delta);
    cudaGetSymbolAddress((void**)&yy,    g_y);
    cudaGetSymbolAddress((void**)&mc,    g_mc);
    cudaGetSymbolAddress((void**)&dist,  g_dist);
    cudaGetSymbolAddress((void**)&xpf,   g_xpf);
    cudaGetSymbolAddress((void**)&zpacc, g_zpacc);
    cudaGetSymbolAddress((void**)&scores, g_scores);
    cudaGetSymbolAddress((void**)&atok,  g_atok);
    cudaGetSymbolAddress((void**)&tyacc, g_tyacc);
    cudaGetSymbolAddress((void**)&Tacc,  g_Tacc);
    cudaGetSymbolAddress((void**)&bxp,   g_bxp);
    cudaGetSymbolAddress((void**)&bdt,   g_bdt);

    __nv_bfloat16 *xh,*xl,*Winxh,*Winxl,*Winzh,*Winzl,*Wxph,*Wxpl,*Wdth,*Wdtl;
    __nv_bfloat16 *Wproh,*Wprol,*wAh,*wAl,*wVh,*wVl,*Wouth,*Woutl,*yh2,*yl2;
    cudaGetSymbolAddress((void**)&xh, g_xh);         cudaGetSymbolAddress((void**)&xl, g_xl);
    cudaGetSymbolAddress((void**)&Winxh, g_Winx_h);  cudaGetSymbolAddress((void**)&Winxl, g_Winx_l);
    cudaGetSymbolAddress((void**)&Winzh, g_Winz_h);  cudaGetSymbolAddress((void**)&Winzl, g_Winz_l);
    cudaGetSymbolAddress((void**)&Wxph, g_Wxp_h);    cudaGetSymbolAddress((void**)&Wxpl, g_Wxp_l);
    cudaGetSymbolAddress((void**)&Wdth, g_Wdt_h);    cudaGetSymbolAddress((void**)&Wdtl, g_Wdt_l);
    cudaGetSymbolAddress((void**)&Wproh, g_Wpro_h);  cudaGetSymbolAddress((void**)&Wprol, g_Wpro_l);
    cudaGetSymbolAddress((void**)&wAh, g_wA_h);      cudaGetSymbolAddress((void**)&wAl, g_wA_l);
    cudaGetSymbolAddress((void**)&wVh, g_wV_h);      cudaGetSymbolAddress((void**)&wVl, g_wV_l);
    cudaGetSymbolAddress((void**)&Wouth, g_Wout_h);  cudaGetSymbolAddress((void**)&Woutl, g_Wout_l);
    cudaGetSymbolAddress((void**)&yh2, g_yh);        cudaGetSymbolAddress((void**)&yl2, g_yl);

    cudaFuncSetAttribute(hgemm_ca, cudaFuncAttributeMaxDynamicSharedMemorySize, CA_SMEM_BYTES);

    // 0) fused init: zero accums + weight splits (Wxp permuted) + x split + pooling
    init_kernel<<<ceildiv(INIT_TOT, 256), 256>>>(
        x, W_in_x, W_in_z, W_xp_f, W_xp_b, W_dt_f, W_dt_b, W_pro_to,
        token_wA, token_wV, W_out, b_xp_f, b_xp_b, b_dt_f, b_dt_b, out);

    // 1) xi = x @ W_in_x^T  (cp.async pipeline, pre-split planes)
    hgemm_ca<<<dim3(DI / 128, ceildiv(ML, 128)), 256, CA_SMEM_BYTES>>>(
        xh, xl, Winxh, Winxl, nullptr, xi, ML, DI, Dmod, Dmod, Dmod, DI);

    // 2) zpacc = xp @ W_in_z^T (split-K4; silu applied in gated out-GEMM)
    hgemm4<1,0><<<dim3(DI / 128, 4, 4), 256>>>(
        xpf, nullptr, Winzh, Winzl, nullptr, nullptr, zpacc,
        Bsz * Stok, DI, Dmod, Dmod, Dmod, DI, DI, 0, 4, 0, 0, 0, 0);

    // 3) conv + silu (both dirs, t-tiled)
    conv_silu2_kernel<<<dim3(ceildiv(LC, CT), Bsz, 2), DI>>>(
        xi, conv_w_f, conv_b_f, conv_w_b, conv_b_b);

    // 4) dbc = u @ W_xp^T + b  (merged dirs, split-K2, atomic; cols permuted)
    hgemm4<1,0><<<dim3(1, ceildiv(MC, 128), 4), 256>>>(
        u, nullptr, Wxph, Wxpl, bxp, nullptr, dbc,
        MC, 128, DI, DI, DI, NXP, NXP, 0, 2,
        (long long)SZ_U, (long long)128 * DI, (long long)SZ_DBC, 128);

    // 5) delta = softplus(dr @ W_dt^T + b_dt)  (merged dirs, K=16)
    hgemm4<1,0><<<dim3(DI / 128, ceildiv(MC, 128), 2), 256>>>(
        dbc, nullptr, Wdth, Wdtl, bdt, nullptr, delta,
        MC, DI, DRK, NXP, DRK, DI, DI, 2, 1,
        (long long)SZ_DBC, (long long)DI * DRK, (long long)SZ_U, DI);

    // 6) selective scans (both dirs, 4 states/lane)
    scan2_kernel<<<dim3(Bsz * DI / 64, 2), 256>>>(A_log_f, D_f, A_log_b, D_b);

    // 7) masks ('last'), both dirs
    dist2_kernel<<<dim3(ceildiv(LC, 8), Bsz, 2), 256>>>(LC - 1);
    maskfin2_kernel<<<dim3(Bsz, 2), 512>>>(LC - 1);

    // 8) y = [yf*mf | yb*rev(mb)] @ W_pro^T + b  (concat fused into A-loader)
    hgemm4<1,2><<<dim3(DI / 128, ceildiv(MC, 128)), 256>>>(
        nullptr, nullptr, Wproh, Wprol, b_pro_to, nullptr, yy,
        MC, DI, 2 * DI, 2 * DI, 2 * DI, DI, DI, 0, 1, 0, 0, 0, 0);

    // 9) center mask; scale y + split planes
    dist_kernel<<<dim3(ceildiv(LC, 8), Bsz), 256>>>(yy, dist, (LC + 1) / 2);
    maskfin_kernel<<<Bsz, 512>>>(dist, mc, (LC + 1) / 2);
    scale_y_kernel<<<dim3(LC, Bsz), DI>>>();

    // 10) scores = y @ wA^T (split-K2, atomic); softmax -> Atok
    hgemm4<1,0><<<dim3(1, ceildiv(MC, 128), 2), 256>>>(
        yy, nullptr, wAh, wAl, nullptr, nullptr, scores,
        MC, 128, DI, DI, DI, Stok, Stok, 0, 2, 0, 0, 0, 0);
    softmax_kernel<<<dim3(Stok, Bsz), 256>>>();

    // 11) Ty = Atok @ y  (TB=0, batched over b, split-K5, atomic)
    hgemm4<0,0><<<dim3(DI / 128, 1, Bsz * 5), 256>>>(
        atok, nullptr, yh2, yl2, nullptr, nullptr, tyacc,
        Stok, DI, LCP, LCP, DI, DI, DI, 0, 5,
        (long long)Stok * LCP, (long long)LC * DI, (long long)Stok * DI, 0);

    // 12) Tacc = Ty @ wV  (TB=0, batched, split-K4, atomic)
    hgemm4<0,0><<<dim3(DI / 128, 1, Bsz * 4), 256>>>(
        tyacc, nullptr, wVh, wVl, nullptr, nullptr, Tacc,
        Stok, DI, DI, DI, DI, DI, DI, 0, 4,
        (long long)Stok * DI, 0, (long long)Stok * DI, 0);

    // 13) out = (Tacc * silu(zpacc)) @ W_out^T  (gated A, split-K4, atomic)
    hgemm4<1,1><<<dim3(Dmod / 128, 4, 4), 256>>>(
        Tacc, zpacc, Wouth, Woutl, nullptr, nullptr, out,
        Bsz * Stok, Dmod, DI, DI, DI, Dmod, Dmod, 0, 4, 0, 0, 0, 0);
}

// round 14
// speedup vs baseline: 1.2855x; 1.2855x over previous
#include <cuda_runtime.h>
#include <cuda_bf16.h>
#include <math.h>
#include <stdint.h>

// ---------------- problem constants ----------------
#define Bsz  8
#define Lseq 2049
#define Dmod 256
#define DI   512
#define DS   16
#define DRK  16
#define LB   1025
#define LC   1028
#define Stok 64
#define NXP  48
#define LCP  1040   // LC padded to 16
#define CT   8      // conv timesteps per block

#define SZ_U    (Bsz*LC*DI)
#define SZ_DBC  (Bsz*LC*NXP)
#define ML      (Bsz*Lseq)
#define MC      (Bsz*LC)

// ---------------- fp32 scratch ----------------
__device__ float g_xi[Bsz*Lseq*DI];
__device__ float g_u[2*SZ_U];          // f, b
__device__ float g_dbc[2*SZ_DBC];      // f, b (atomic accum; B/C interleaved cols)
__device__ float g_delta[2*SZ_U];
__device__ float g_ysc[2*SZ_U];        // scan outputs f, b
__device__ float g_y[Bsz*LC*DI];
__device__ float g_mf[Bsz*LC];
__device__ float g_mb[Bsz*LC];
__device__ float g_mc[Bsz*LC];
__device__ float g_dist[Bsz*LC*2];
__device__ float g_xpf[Bsz*Stok*Dmod];
__device__ float g_zpacc[Bsz*Stok*DI];     // atomic accum (pre-silu)
__device__ float g_scores[Bsz*LC*Stok];    // atomic accum
__device__ float g_atok[Bsz*Stok*LCP];
__device__ float g_tyacc[Bsz*Stok*DI];     // atomic accum
__device__ float g_Tacc[Bsz*Stok*DI];      // atomic accum (pre-gate)
__device__ float g_bxp[2*128];
__device__ float g_bdt[2*DI];

// ---------------- bf16 planes ----------------
__device__ __nv_bfloat16 g_xh[ML*Dmod],       g_xl[ML*Dmod];          // x pre-split
__device__ __nv_bfloat16 g_Winx_h[DI*Dmod],   g_Winx_l[DI*Dmod];
__device__ __nv_bfloat16 g_Winz_h[DI*Dmod],   g_Winz_l[DI*Dmod];
__device__ __nv_bfloat16 g_Wxp_h[2*128*DI],   g_Wxp_l[2*128*DI];      // rows permuted (B/C interleave)
__device__ __nv_bfloat16 g_Wdt_h[2*DI*DRK],   g_Wdt_l[2*DI*DRK];
__device__ __nv_bfloat16 g_Wpro_h[DI*2*DI],   g_Wpro_l[DI*2*DI];
__device__ __nv_bfloat16 g_wA_h[128*DI],      g_wA_l[128*DI];
__device__ __nv_bfloat16 g_wV_h[DI*DI],       g_wV_l[DI*DI];
__device__ __nv_bfloat16 g_Wout_h[Dmod*DI],   g_Wout_l[Dmod*DI];
__device__ __nv_bfloat16 g_yh[Bsz*LC*DI+16*DI], g_yl[Bsz*LC*DI+16*DI]; // slack rows stay 0

__device__ __forceinline__ void splitv(float v, __nv_bfloat16& h, __nv_bfloat16& l) {
    h = __float2bfloat16(v);
    l = __float2bfloat16(v - __bfloat162float(h));
}

// dbc column permutation: rows 0-15 identity (dr); output row 16+2j <- B_j (src 16+j);
// output row 17+2j <- C_j (src 32+j); rows >= 48 zero.
__device__ __forceinline__ int wxp_srcrow(int r) {
    if (r < 16) return r;
    if (r >= 48) return -1;
    int q = r - 16;
    return (q & 1) ? (32 + (q >> 1)) : (16 + (q >> 1));
}

// ---------------- fused init: zero accums + weight splits + x split + pool ----------------
#define Z1 (Bsz*Stok*DI)
#define Z2 (2*SZ_DBC)
#define Z3 (Bsz*LC*Stok)
#define Z4 (Bsz*Stok*DI)
#define Z5 (Bsz*Stok*DI)
#define Z6 (Bsz*Stok*Dmod)
#define ZTOT (Z1+Z2+Z3+Z4+Z5+Z6)
#define WTOT 1393920
#define XTOT (ML*Dmod)
#define PTOT (Bsz*Stok*Dmod)
#define INIT_TOT (ZTOT + WTOT + XTOT + PTOT)

__global__ void init_kernel(const float* __restrict__ x,
                            const float* __restrict__ Winx, const float* __restrict__ Winz,
                            const float* __restrict__ Wxpf, const float* __restrict__ Wxpb,
                            const float* __restrict__ Wdtf, const float* __restrict__ Wdtb,
                            const float* __restrict__ Wpro, const float* __restrict__ wA,
                            const float* __restrict__ wV,   const float* __restrict__ Wout,
                            const float* __restrict__ bxpf, const float* __restrict__ bxpb,
                            const float* __restrict__ bdtf, const float* __restrict__ bdtb,
                            float* __restrict__ dout)
{
    long long i = (long long)blockIdx.x * 256 + threadIdx.x;
    __nv_bfloat16 h, l;
    if (i < Z1) { g_zpacc[i] = 0.f; return; }  i -= Z1;
    if (i < Z2) { g_dbc[i] = 0.f; return; }    i -= Z2;
    if (i < Z3) { g_scores[i] = 0.f; return; } i -= Z3;
    if (i < Z4) { g_tyacc[i] = 0.f; return; }  i -= Z4;
    if (i < Z5) { g_Tacc[i] = 0.f; return; }   i -= Z5;
    if (i < Z6) { dout[i] = 0.f; return; }     i -= Z6;
    if (i < 131072) { splitv(Winx[i], h, l); g_Winx_h[i] = h; g_Winx_l[i] = l; return; }
    i -= 131072;
    if (i < 131072) { splitv(Winz[i], h, l); g_Winz_h[i] = h; g_Winz_l[i] = l; return; }
    i -= 131072;
    if (i < 131072) { int dir = i >> 16, j = i & 65535;
        int r = j >> 9, c = j & 511;
        const float* W = dir ? Wxpb : Wxpf;
        int sr = wxp_srcrow(r);
        splitv(sr >= 0 ? W[sr * DI + c] : 0.f, h, l);
        g_Wxp_h[i] = h; g_Wxp_l[i] = l; return; }
    i -= 131072;
    if (i < 16384) { int dir = i >> 13, j = i & 8191;
        const float* W = dir ? Wdtb : Wdtf;
        splitv(W[j], h, l); g_Wdt_h[i] = h; g_Wdt_l[i] = l; return; }
    i -= 16384;
    if (i < 524288) { splitv(Wpro[i], h, l); g_Wpro_h[i] = h; g_Wpro_l[i] = l; return; }
    i -= 524288;
    if (i < 65536) { int r = i >> 9, c = i & 511;
        splitv(r < Stok ? wA[r * DI + c] : 0.f, h, l);
        g_wA_h[i] = h; g_wA_l[i] = l; return; }
    i -= 65536;
    if (i < 262144) { splitv(wV[i], h, l); g_wV_h[i] = h; g_wV_l[i] = l; return; }
    i -= 262144;
    if (i < 131072) { splitv(Wout[i], h, l); g_Wout_h[i] = h; g_Wout_l[i] = l; return; }
    i -= 131072;
    if (i < 256) { int dir = i >> 7, r = i & 127;
        const float* bsrc = dir ? bxpb : bxpf;
        int sr = wxp_srcrow(r);
        g_bxp[i] = (sr >= 0) ? bsrc[sr] : 0.f; return; }
    i -= 256;
    if (i < 1024) { int dir = i >> 9, r = i & 511;
        g_bdt[i] = dir ? bdtb[r] : bdtf[r]; return; }
    i -= 1024;
    if (i < XTOT) { splitv(x[i], h, l); g_xh[i] = h; g_xl[i] = l; return; }
    i -= XTOT;
    if (i < PTOT) {   // pooling: xp[b,s,d] = mean_l x[b, l in [s0,e), d]
        int d = (int)(i % Dmod);
        int rest = (int)(i / Dmod);
        int s = rest % Stok;
        int b = rest / Stok;
        int s0 = (s * Lseq) / Stok;
        int e  = ((s + 1) * Lseq + Stok - 1) / Stok;
        float acc = 0.f;
        for (int lq = s0; lq < e; lq++) acc += x[((long long)b * Lseq + lq) * Dmod + d];
        g_xpf[((long long)b * Stok + s) * Dmod + d] = acc / (float)(e - s0);
    }
}

// ---------------- shared helpers ----------------
#define SAS 24

__device__ __forceinline__ uint32_t s2u(const void* p) {
    return (uint32_t)__cvta_generic_to_shared(p);
}
__device__ __forceinline__ void ldsm4(uint32_t r[4], uint32_t addr) {
    asm volatile("ldmatrix.sync.aligned.m8n8.x4.shared.b16 {%0,%1,%2,%3}, [%4];"
                 : "=r"(r[0]), "=r"(r[1]), "=r"(r[2]), "=r"(r[3]) : "r"(addr));
}
__device__ __forceinline__ void mma16816(float c[4], const uint32_t a[4],
                                         uint32_t b0, uint32_t b1) {
    asm volatile(
        "mma.sync.aligned.m16n8k16.row.col.f32.bf16.bf16.f32 "
        "{%0,%1,%2,%3},{%4,%5,%6,%7},{%8,%9},{%0,%1,%2,%3};"
        : "+f"(c[0]), "+f"(c[1]), "+f"(c[2]), "+f"(c[3])
        : "r"(a[0]), "r"(a[1]), "r"(a[2]), "r"(a[3]), "r"(b0), "r"(b1));
}
__device__ __forceinline__ void cpasync16(uint32_t dst, const void* src, int szbytes) {
    asm volatile("cp.async.ca.shared.global [%0], [%1], 16, %2;"
                 :: "r"(dst), "l"(src), "r"(szbytes));
}

// =====================================================================
// hgemm4: C = A * op(B planes), 3-split bf16 MMA (round-6 core).
// AMODE: 0 = plain fp32 A; 1 = A * silu(Ag); 2 = concat A built on the
// fly from g_ysc/g_mf/g_mb (row=(b,t); cols<512 = yf*mf, >=512 = yb*mbrev).
// =====================================================================
template<int TB, int AMODE>
__global__ __launch_bounds__(256, 2)
void hgemm4(const float* __restrict__ A, const float* __restrict__ Ag,
            const __nv_bfloat16* __restrict__ Bh, const __nv_bfloat16* __restrict__ Bl,
            const float* __restrict__ bias, const float* __restrict__ emul,
            float* __restrict__ C,
            int M, int N, int K, int lda, int ldb, int ldc, int Nout, int act, int KS,
            long long sA, long long sB, long long sC, long long sBias)
{
    __shared__ __align__(16) __nv_bfloat16 As_hi[128][SAS];
    __shared__ __align__(16) __nv_bfloat16 As_lo[128][SAS];
    __shared__ __align__(16) __nv_bfloat16 Bs_hi[128][SAS];
    __shared__ __align__(16) __nv_bfloat16 Bs_lo[128][SAS];

    int bz  = blockIdx.z;
    int dir = bz / KS;
    int ks  = bz % KS;
    A  += dir * sA;
    Bh += dir * sB; Bl += dir * sB;
    if (bias) bias += dir * sBias;
    int kchunk = K / KS;
    int kb = ks * kchunk, ke = kb + kchunk;

    int tid  = threadIdx.x;
    int lane = tid & 31;
    int wid  = tid >> 5;
    int wm0  = (wid >> 2) * 64;
    int wn0  = (wid & 3) * 32;
    int row0 = blockIdx.y * 128;
    int col0 = blockIdx.x * 128;

    int lr = lane & 15;
    int lc = (lane >> 4) * 8;

    int ar = tid >> 1;
    int ac = (tid & 1) * 8;
    int gm = row0 + ar;
    bool mok = gm < M;
    const float* Ap = A + (long long)gm * lda + ac;
    const float* Gp = (AMODE == 1) ? (Ag + (long long)gm * lda + ac) : nullptr;

    // AMODE 2 setup: row -> (b,t), masks and source rows
    const float* src0 = nullptr;
    const float* src1 = nullptr;
    float mk0 = 0.f, mk1 = 0.f;
    if (AMODE == 2) {
        if (mok) {
            int bq = gm / LC;
            int tq = gm - bq * LC;
            mk0 = g_mf[bq * LC + tq];
            mk1 = g_mb[bq * LC + (LC - 1 - tq)];
            src0 = g_ysc + ((long long)bq * LC + tq) * DI + ac;
            src1 = g_ysc + (long long)SZ_U + ((long long)bq * LC + tq) * DI + ac;
        }
    }

    const __nv_bfloat16 *Bph = nullptr, *Bpl = nullptr;
    int bkk = 0, bnc = 0;
    if (TB == 1) {
        Bph = Bh + (long long)(col0 + ar) * ldb + ac;
        Bpl = Bl + (long long)(col0 + ar) * ldb + ac;
    } else {
        bkk = tid >> 4;
        bnc = (tid & 15) * 8;
        Bph = Bh + col0 + bnc;
        Bpl = Bl + col0 + bnc;
    }

    float4 ra0 = make_float4(0,0,0,0), ra1 = make_float4(0,0,0,0);
    float4 rg0 = make_float4(0,0,0,0), rg1 = make_float4(0,0,0,0);
    uint4 rbh, rbl;

    // preload kb
    if (AMODE == 2) {
        if (mok) {
            const float* s; float sc;
            if (kb < DI) { s = src0 + kb; sc = mk0; }
            else         { s = src1 + (kb - DI); sc = mk1; }
            ra0 = *(const float4*)(s); ra1 = *(const float4*)(s + 4);
            ra0.x*=sc; ra0.y*=sc; ra0.z*=sc; ra0.w*=sc;
            ra1.x*=sc; ra1.y*=sc; ra1.z*=sc; ra1.w*=sc;
        }
    } else if (mok) {
        ra0 = *(const float4*)(Ap + kb); ra1 = *(const float4*)(Ap + kb + 4);
        if (AMODE == 1) { rg0 = *(const float4*)(Gp + kb); rg1 = *(const float4*)(Gp + kb + 4); }
    }
    if (TB == 1) {
        rbh = *(const uint4*)(Bph + kb); rbl = *(const uint4*)(Bpl + kb);
    } else {
        rbh = *(const uint4*)(Bph + (long long)(kb + bkk) * ldb);
        rbl = *(const uint4*)(Bpl + (long long)(kb + bkk) * ldb);
    }

    float acc[4][4][4];
    #pragma unroll
    for (int i = 0; i < 4; i++)
        #pragma unroll
        for (int j = 0; j < 4; j++)
            #pragma unroll
            for (int q = 0; q < 4; q++) acc[i][j][q] = 0.f;

    for (int k0 = kb; k0 < ke; k0 += 16) {
        {
            float av[8] = {ra0.x, ra0.y, ra0.z, ra0.w, ra1.x, ra1.y, ra1.z, ra1.w};
            if (AMODE == 1) {
                float gv[8] = {rg0.x, rg0.y, rg0.z, rg0.w, rg1.x, rg1.y, rg1.z, rg1.w};
                #pragma unroll
                for (int j = 0; j < 8; j++) av[j] *= gv[j] / (1.f + expf(-gv[j]));
            }
            __nv_bfloat16 hh[8], ll[8];
            #pragma unroll
            for (int j = 0; j < 8; j++) splitv(av[j], hh[j], ll[j]);
            *(uint4*)&As_hi[ar][ac] = *(uint4*)hh;
            *(uint4*)&As_lo[ar][ac] = *(uint4*)ll;
        }
        if (TB == 1) {
            *(uint4*)&Bs_hi[ar][ac] = rbh;
            *(uint4*)&Bs_lo[ar][ac] = rbl;
        } else {
            __nv_bfloat16 th[8], tl[8];
            *(uint4*)th = rbh; *(uint4*)tl = rbl;
            #pragma unroll
            for (int j = 0; j < 8; j++) {
                Bs_hi[bnc + j][bkk] = th[j];
                Bs_lo[bnc + j][bkk] = tl[j];
            }
        }
        __syncthreads();

        if (k0 + 16 < ke) {
            int kn = k0 + 16;
            if (AMODE == 2) {
                if (mok) {
                    const float* s; float sc;
                    if (kn < DI) { s = src0 + kn; sc = mk0; }
                    else         { s = src1 + (kn - DI); sc = mk1; }
                    ra0 = *(const float4*)(s); ra1 = *(const float4*)(s + 4);
                    ra0.x*=sc; ra0.y*=sc; ra0.z*=sc; ra0.w*=sc;
                    ra1.x*=sc; ra1.y*=sc; ra1.z*=sc; ra1.w*=sc;
                }
            } else if (mok) {
                ra0 = *(const float4*)(Ap + kn);
                ra1 = *(const float4*)(Ap + kn + 4);
                if (AMODE == 1) {
                    rg0 = *(const float4*)(Gp + kn);
                    rg1 = *(const float4*)(Gp + kn + 4);
                }
            }
            if (TB == 1) {
                rbh = *(const uint4*)(Bph + kn);
                rbl = *(const uint4*)(Bpl + kn);
            } else {
                rbh = *(const uint4*)(Bph + (long long)(kn + bkk) * ldb);
                rbl = *(const uint4*)(Bpl + (long long)(kn + bkk) * ldb);
            }
        }

        uint32_t bhf[2][4], blf[2][4];
        #pragma unroll
        for (int ng = 0; ng < 2; ng++) {
            ldsm4(bhf[ng], s2u(&Bs_hi[wn0 + ng * 16 + lr][lc]));
            ldsm4(blf[ng], s2u(&Bs_lo[wn0 + ng * 16 + lr][lc]));
        }
        #pragma unroll
        for (int mt = 0; mt < 4; mt++) {
            uint32_t a_h[4], a_l[4];
            ldsm4(a_h, s2u(&As_hi[wm0 + mt * 16 + lr][lc]));
            ldsm4(a_l, s2u(&As_lo[wm0 + mt * 16 + lr][lc]));
            #pragma unroll
            for (int nt = 0; nt < 4; nt++) {
                int ng = nt >> 1, sl = nt & 1;
                mma16816(acc[mt][nt], a_h, bhf[ng][sl], bhf[ng][sl + 2]);
                mma16816(acc[mt][nt], a_h, blf[ng][sl], blf[ng][sl + 2]);
                mma16816(acc[mt][nt], a_l, bhf[ng][sl], bhf[ng][sl + 2]);
            }
        }
        __syncthreads();
    }

    int g = lane >> 2, t4 = lane & 3;
    #pragma unroll
    for (int mt = 0; mt < 4; mt++) {
        #pragma unroll
        for (int nt = 0; nt < 4; nt++) {
            int cb = col0 + wn0 + nt * 8 + 2 * t4;
            if (cb >= Nout) continue;
            float b0 = 0.f, b1 = 0.f;
            if (bias && (KS == 1 || ks == 0)) { b0 = bias[cb]; b1 = bias[cb + 1]; }
            #pragma unroll
            for (int hrow = 0; hrow < 2; hrow++) {
                int m = row0 + wm0 + mt * 16 + g + hrow * 8;
                if (m >= M) continue;
                float v0 = acc[mt][nt][hrow * 2 + 0] + b0;
                float v1 = acc[mt][nt][hrow * 2 + 1] + b1;
                long long co = dir * sC + (long long)m * ldc + cb;
                if (KS > 1) {
                    atomicAdd(C + co, v0);
                    atomicAdd(C + co + 1, v1);
                } else {
                    if (act == 1) {
                        v0 = v0 / (1.f + expf(-v0));
                        v1 = v1 / (1.f + expf(-v1));
                    } else if (act == 2) {
                        v0 = (v0 > 20.f) ? v0 : log1pf(expf(v0));
                        v1 = (v1 > 20.f) ? v1 : log1pf(expf(v1));
                    }
                    if (emul) { v0 *= emul[co]; v1 *= emul[co + 1]; }
                    *(float2*)(C + co) = make_float2(v0, v1);
                }
            }
        }
    }
}

// =====================================================================
// hgemm_ca: big-GEMM specialist (xi only).
// =====================================================================
#define CA_PL  (128*SAS)
#define CA_STG (4*CA_PL)
#define CA_SMEM_BYTES (3*CA_STG*2)

__global__ __launch_bounds__(256, 2)
void hgemm_ca(const __nv_bfloat16* __restrict__ Ah, const __nv_bfloat16* __restrict__ Al,
              const __nv_bfloat16* __restrict__ Bh, const __nv_bfloat16* __restrict__ Bl,
              const float* __restrict__ bias, float* __restrict__ C,
              int M, int N, int K, int lda, int ldb, int ldc)
{
    extern __shared__ __align__(16) __nv_bfloat16 sm[];
    uint32_t smb = s2u(sm);

    int tid  = threadIdx.x;
    int lane = tid & 31;
    int wid  = tid >> 5;
    int wm0  = (wid >> 2) * 64;
    int wn0  = (wid & 3) * 32;
    int row0 = blockIdx.y * 128;
    int col0 = blockIdx.x * 128;

    int lr = lane & 15;
    int lc = (lane >> 4) * 8;

    int ar = tid >> 1;
    int ac = (tid & 1) * 8;
    int gm = row0 + ar;
    int asz = (gm < M) ? 16 : 0;
    const __nv_bfloat16* Aph = Ah + (long long)gm * lda + ac;
    const __nv_bfloat16* Apl = Al + (long long)gm * lda + ac;
    const __nv_bfloat16* Bph = Bh + (long long)(col0 + ar) * ldb + ac;
    const __nv_bfloat16* Bpl = Bl + (long long)(col0 + ar) * ldb + ac;

    uint32_t offA_h = (uint32_t)(0 * CA_PL + ar * SAS + ac) * 2;
    uint32_t offA_l = (uint32_t)(1 * CA_PL + ar * SAS + ac) * 2;
    uint32_t offB_h = (uint32_t)(2 * CA_PL + ar * SAS + ac) * 2;
    uint32_t offB_l = (uint32_t)(3 * CA_PL + ar * SAS + ac) * 2;

    float acc[4][4][4];
    #pragma unroll
    for (int i = 0; i < 4; i++)
        #pragma unroll
        for (int j = 0; j < 4; j++)
            #pragma unroll
            for (int q = 0; q < 4; q++) acc[i][j][q] = 0.f;

    {
        uint32_t sb = smb;
        cpasync16(sb + offA_h, Aph + 0, asz);
        cpasync16(sb + offA_l, Apl + 0, asz);
        cpasync16(sb + offB_h, Bph + 0, 16);
        cpasync16(sb + offB_l, Bpl + 0, 16);
        asm volatile("cp.async.commit_group;" ::: "memory");
    }
    if (16 < K) {
        uint32_t sb = smb + CA_STG * 2;
        cpasync16(sb + offA_h, Aph + 16, asz);
        cpasync16(sb + offA_l, Apl + 16, asz);
        cpasync16(sb + offB_h, Bph + 16, 16);
        cpasync16(sb + offB_l, Bpl + 16, 16);
        asm volatile("cp.async.commit_group;" ::: "memory");
    } else {
        asm volatile("cp.async.commit_group;" ::: "memory");
    }

    int cur = 0;
    for (int k0 = 0; k0 < K; k0 += 16) {
        asm volatile("cp.async.wait_group 1;" ::: "memory");
        __syncthreads();

        uint32_t sb = smb + (uint32_t)cur * (CA_STG * 2);

        uint32_t bhf[2][4], blf[2][4];
        #pragma unroll
        for (int ng = 0; ng < 2; ng++) {
            uint32_t rb = (uint32_t)(wn0 + ng * 16 + lr) * SAS + lc;
            ldsm4(bhf[ng], sb + (uint32_t)(2 * CA_PL) * 2 + rb * 2);
            ldsm4(blf[ng], sb + (uint32_t)(3 * CA_PL) * 2 + rb * 2);
        }
        #pragma unroll
        for (int mt = 0; mt < 4; mt++) {
            uint32_t raddr = (uint32_t)(wm0 + mt * 16 + lr) * SAS + lc;
            uint32_t a_h[4], a_l[4];
            ldsm4(a_h, sb + raddr * 2);
            ldsm4(a_l, sb + (uint32_t)(CA_PL) * 2 + raddr * 2);
            #pragma unroll
            for (int nt = 0; nt < 4; nt++) {
                int ng = nt >> 1, sl = nt & 1;
                mma16816(acc[mt][nt], a_h, bhf[ng][sl], bhf[ng][sl + 2]);
                mma16816(acc[mt][nt], a_h, blf[ng][sl], blf[ng][sl + 2]);
                mma16816(acc[mt][nt], a_l, bhf[ng][sl], bhf[ng][sl + 2]);
            }
        }

        int nk = k0 + 32;
        if (nk < K) {
            int nst = cur + 2; if (nst >= 3) nst -= 3;
            uint32_t nb = smb + (uint32_t)nst * (CA_STG * 2);
            cpasync16(nb + offA_h, Aph + nk, asz);
            cpasync16(nb + offA_l, Apl + nk, asz);
            cpasync16(nb + offB_h, Bph + nk, 16);
            cpasync16(nb + offB_l, Bpl + nk, 16);
        }
        asm volatile("cp.async.commit_group;" ::: "memory");

        cur++; if (cur == 3) cur = 0;
    }

    int g = lane >> 2, t4 = lane & 3;
    #pragma unroll
    for (int mt = 0; mt < 4; mt++) {
        #pragma unroll
        for (int nt = 0; nt < 4; nt++) {
            int cb = col0 + wn0 + nt * 8 + 2 * t4;
            float b0 = 0.f, b1 = 0.f;
            if (bias) { b0 = bias[cb]; b1 = bias[cb + 1]; }
            #pragma unroll
            for (int hrow = 0; hrow < 2; hrow++) {
                int m = row0 + wm0 + mt * 16 + g + hrow * 8;
                if (m >= M) continue;
                float v0 = acc[mt][nt][hrow * 2 + 0] + b0;
                float v1 = acc[mt][nt][hrow * 2 + 1] + b1;
                *(float2*)(C + (long long)m * ldc + cb) = make_float2(v0, v1);
            }
        }
    }
}

// ---------------- depthwise conv + SiLU, t-tiled (CT steps/block), both dirs ----------------
__global__ void conv_silu2_kernel(const float* __restrict__ xi,
                                  const float* __restrict__ wf, const float* __restrict__ bf,
                                  const float* __restrict__ wb, const float* __restrict__ bb)
{
    int t0 = blockIdx.x * CT;
    int b = blockIdx.y;
    int back = blockIdx.z;
    int c = threadIdx.x;
    const float* w  = back ? wb : wf;
    float bias      = back ? bb[c] : bf[c];
    float* out      = g_u + (long long)back * SZ_U;

    float w0 = w[c * 4 + 0], w1 = w[c * 4 + 1], w2 = w[c * 4 + 2], w3 = w[c * 4 + 3];

    float xv[CT + 3];
    #pragma unroll
    for (int j = 0; j < CT + 3; j++) {
        int i = t0 + j - 3;
        float v = 0.f;
        if (i >= 0 && i < LB) {
            int l = back ? (Lseq - 1 - i) : i;
            v = xi[((long long)b * Lseq + l) * DI + c];
        }
        xv[j] = v;
    }
    #pragma unroll
    for (int j = 0; j < CT; j++) {
        int t = t0 + j;
        if (t >= LC) break;
        float acc = bias;
        acc = fmaf(w0, xv[j],     acc);
        acc = fmaf(w1, xv[j + 1], acc);
        acc = fmaf(w2, xv[j + 2], acc);
        acc = fmaf(w3, xv[j + 3], acc);
        out[((long long)b * LC + t) * DI + c] = acc / (1.f + expf(-acc));
    }
}

// ---------------- selective scans: 16 lanes/channel, float2 B/C (round-12 proven) ----------------
__global__ __launch_bounds__(256)
void scan2_kernel(const float* __restrict__ A_log_f, const float* __restrict__ D_f,
                  const float* __restrict__ A_log_b, const float* __restrict__ D_b)
{
    int back = blockIdx.y;
    const float* u     = g_u     + (long long)back * SZ_U;
    const float* delta = g_delta + (long long)back * SZ_U;
    const float* dbc   = g_dbc   + (long long)back * SZ_DBC;
    const float* A_log = back ? A_log_b : A_log_f;
    const float* Dp    = back ? D_b : D_f;
    float* y           = g_ysc   + (long long)back * SZ_U;

    int gid = blockIdx.x * 16 + (threadIdx.x >> 4);
    int s = threadIdx.x & 15;
    int b = gid >> 9;
    int d = gid & 511;
    float Av = -expf(A_log[d * 16 + s]);
    float Dd = Dp[d];
    float h = 0.f;
    const float* db = dbc + (long long)b * LC * NXP + 16 + 2 * s;  // interleaved B,C
    const float* dl = delta + ((long long)b * LC) * DI + d;
    const float* uu = u     + ((long long)b * LC) * DI + d;
    float*       yy = y     + ((long long)b * LC) * DI + d;
    #pragma unroll 4
    for (int t = 0; t < LC; t++) {
        float de = __ldg(dl + (long long)t * DI);
        float uv = __ldg(uu + (long long)t * DI);
        float2 bc = __ldg((const float2*)(db + t * NXP));
        float dA = __expf(de * Av);
        h = fmaf(dA, h, de * uv * bc.x);
        float v = h * bc.y;
        v += __shfl_xor_sync(0xffffffffu, v, 8);
        v += __shfl_xor_sync(0xffffffffu, v, 4);
        v += __shfl_xor_sync(0xffffffffu, v, 2);
        v += __shfl_xor_sync(0xffffffffu, v, 1);
        if (s == 0) yy[(long long)t * DI] = fmaf(Dd, uv, v);
    }
}

// ---------------- gaussian masks ----------------
__global__ void dist2_kernel(int ref)
{
    int back = blockIdx.z;
    const float* y = g_ysc + (long long)back * SZ_U;
    float* dist = g_dist + back * (Bsz * LC);
    int b = blockIdx.y;
    int t = blockIdx.x * 8 + (threadIdx.x >> 5);
    int lane = threadIdx.x & 31;
    if (t >= LC) return;
    const float* yt = y + ((long long)b * LC + t) * DI;
    const float* yr = y + ((long long)b * LC + ref) * DI;
    float acc = 0.f;
    for (int d = lane; d < DI; d += 32) {
        float df = yt[d] - yr[d];
        acc = fmaf(df, df, acc);
    }
    #pragma unroll
    for (int o = 16; o; o >>= 1) acc += __shfl_xor_sync(0xffffffffu, acc, o);
    if (lane == 0) dist[b * LC + t] = sqrtf(fmaxf(acc, 1e-12f));
}

__global__ void dist_kernel(const float* __restrict__ y, float* __restrict__ dist, int ref)
{
    int b = blockIdx.y;
    int t = blockIdx.x * 8 + (threadIdx.x >> 5);
    int lane = threadIdx.x & 31;
    if (t >= LC) return;
    const float* yt = y + ((long long)b * LC + t) * DI;
    const float* yr = y + ((long long)b * LC + ref) * DI;
    float acc = 0.f;
    for (int d = lane; d < DI; d += 32) {
        float df = yt[d] - yr[d];
        acc = fmaf(df, df, acc);
    }
    #pragma unroll
    for (int o = 16; o; o >>= 1) acc += __shfl_xor_sync(0xffffffffu, acc, o);
    if (lane == 0) dist[b * LC + t] = sqrtf(fmaxf(acc, 1e-12f));
}

__device__ __forceinline__ void maskfin_body(const float* dist, float* m, int ref,
                                             float* red, int tid)
{
    float s = 0.f;
    for (int t = tid; t < LC; t += 512) s += dist[t];
    red[tid] = s; __syncthreads();
    for (int o = 256; o; o >>= 1) { if (tid < o) red[tid] += red[tid + o]; __syncthreads(); }
    float sigv = red[0] / (float)LC;
    __syncthreads();
    float si = ((float)ref * (float)(ref + 1) * 0.5f +
                (float)(LC - 1 - ref) * (float)(LC - ref) * 0.5f) / (float)LC;
    float c_i = 0.5f / (si * si);
    float c_v = 0.5f / (sigv * sigv);
    float nrm = 0.f;
    for (int t = tid; t < LC; t += 512) {
        float dt = (float)(t - ref);
        float dv = dist[t];
        float p = expf(-dt * dt * c_i - dv * dv * c_v);
        m[t] = p;
        nrm = fmaf(p, p, nrm);
    }
    red[tid] = nrm; __syncthreads();
    for (int o = 256; o; o >>= 1) { if (tid < o) red[tid] += red[tid + o]; __syncthreads(); }
    float inv = 1.f / fmaxf(sqrtf(red[0]), 1e-12f);
    __syncthreads();
    for (int t = tid; t < LC; t += 512) m[t] *= inv;
}

__global__ void maskfin2_kernel(int ref)
{
    __shared__ float red[512];
    int back = blockIdx.y;
    int b = blockIdx.x;
    const float* dist = g_dist + back * (Bsz * LC) + b * LC;
    float* m = (back ? g_mb : g_mf) + b * LC;
    maskfin_body(dist, m, ref, red, threadIdx.x);
}

__global__ void maskfin_kernel(const float* __restrict__ dist, float* __restrict__ m, int ref)
{
    __shared__ float red[512];
    int b = blockIdx.x;
    maskfin_body(dist + b * LC, m + b * LC, ref, red, threadIdx.x);
}

// y *= mc (in place) + bf16 split planes
__global__ void scale_y_kernel()
{
    int t = blockIdx.x, b = blockIdx.y, c = threadIdx.x;
    long long r = (long long)b * LC + t;
    float v = g_y[r * DI + c] * g_mc[b * LC + t];
    g_y[r * DI + c] = v;
    __nv_bfloat16 h, l; splitv(v, h, l);
    g_yh[r * DI + c] = h; g_yl[r * DI + c] = l;
}

// softmax over l per (b, token): fp32 Atok (B, Stok, LCP), pad zeroed
__global__ void softmax_kernel()
{
    __shared__ float sv[LC];
    __shared__ float red[256];
    int tt = blockIdx.x, b = blockIdx.y, tid = threadIdx.x;
    float mx = -1e30f;
    for (int l = tid; l < LC; l += 256) {
        float v = g_scores[((long long)b * LC + l) * Stok + tt];
        sv[l] = v; mx = fmaxf(mx, v);
    }
    red[tid] = mx; __syncthreads();
    for (int o = 128; o; o >>= 1) { if (tid < o) red[tid] = fmaxf(red[tid], red[tid + o]); __syncthreads(); }
    mx = red[0]; __syncthreads();
    float sum = 0.f;
    for (int l = tid; l < LC; l += 256) { float e = expf(sv[l] - mx); sv[l] = e; sum += e; }
    red[tid] = sum; __syncthreads();
    for (int o = 128; o; o >>= 1) { if (tid < o) red[tid] += red[tid + o]; __syncthreads(); }
    float inv = 1.f / red[0]; __syncthreads();
    long long base = ((long long)b * Stok + tt) * LCP;
    for (int l = tid; l < LC; l += 256) g_atok[base + l] = sv[l] * inv;
    if (tid < LCP - LC) g_atok[base + LC + tid] = 0.f;
}

// ---------------- host launcher ----------------
static inline int ceildiv(int a, int b) { return (a + b - 1) / b; }

extern "C" void kernel_launch(void* const* d_in, const int* in_sizes, int n_in,
                              void* d_out, int out_size)
{
    const float* x        = (const float*)d_in[0];
    const float* W_in_x   = (const float*)d_in[1];
    const float* W_in_z   = (const float*)d_in[2];
    const float* conv_w_f = (const float*)d_in[3];
    const float* conv_b_f = (const float*)d_in[4];
    const float* conv_w_b = (const float*)d_in[5];
    const float* conv_b_b = (const float*)d_in[6];
    const float* W_xp_f   = (const float*)d_in[7];
    const float* b_xp_f   = (const float*)d_in[8];
    const float* W_dt_f   = (const float*)d_in[9];
    const float* b_dt_f   = (const float*)d_in[10];
    const float* A_log_f  = (const float*)d_in[11];
    const float* D_f      = (const float*)d_in[12];
    const float* W_xp_b   = (const float*)d_in[13];
    const float* b_xp_b   = (const float*)d_in[14];
    const float* W_dt_b   = (const float*)d_in[15];
    const float* b_dt_b   = (const float*)d_in[16];
    const float* A_log_b  = (const float*)d_in[17];
    const float* D_b      = (const float*)d_in[18];
    const float* W_pro_to = (const float*)d_in[19];
    const float* b_pro_to = (const float*)d_in[20];
    const float* token_wA = (const float*)d_in[21];
    const float* token_wV = (const float*)d_in[22];
    const float* W_out    = (const float*)d_in[23];
    float* out = (float*)d_out;

    float *xi, *u, *dbc, *delta, *yy, *mc, *dist, *xpf, *zpacc;
    float *scores, *atok, *tyacc, *Tacc, *bxp, *bdt;
    cudaGetSymbolAddress((void**)&xi,    g_xi);
    cudaGetSymbolAddress((void**)&u,     g_u);
    cudaGetSymbolAddress((void**)&dbc,   g_dbc);
    cudaGetSymbolAddress((void**)&delta, g_delta);
    cudaGetSymbolAddress((void**)&yy,    g_y);
    cudaGetSymbolAddress((void**)&mc,    g_mc);
    cudaGetSymbolAddress((void**)&dist,  g_dist);
    cudaGetSymbolAddress((void**)&xpf,   g_xpf);
    cudaGetSymbolAddress((void**)&zpacc, g_zpacc);
    cudaGetSymbolAddress((void**)&scores, g_scores);
    cudaGetSymbolAddress((void**)&atok,  g_atok);
    cudaGetSymbolAddress((void**)&tyacc, g_tyacc);
    cudaGetSymbolAddress((void**)&Tacc,  g_Tacc);
    cudaGetSymbolAddress((void**)&bxp,   g_bxp);
    cudaGetSymbolAddress((void**)&bdt,   g_bdt);

    __nv_bfloat16 *xh,*xl,*Winxh,*Winxl,*Winzh,*Winzl,*Wxph,*Wxpl,*Wdth,*Wdtl;
    __nv_bfloat16 *Wproh,*Wprol,*wAh,*wAl,*wVh,*wVl,*Wouth,*Woutl,*yh2,*yl2;
    cudaGetSymbolAddress((void**)&xh, g_xh);         cudaGetSymbolAddress((void**)&xl, g_xl);
    cudaGetSymbolAddress((void**)&Winxh, g_Winx_h);  cudaGetSymbolAddress((void**)&Winxl, g_Winx_l);
    cudaGetSymbolAddress((void**)&Winzh, g_Winz_h);  cudaGetSymbolAddress((void**)&Winzl, g_Winz_l);
    cudaGetSymbolAddress((void**)&Wxph, g_Wxp_h);    cudaGetSymbolAddress((void**)&Wxpl, g_Wxp_l);
    cudaGetSymbolAddress((void**)&Wdth, g_Wdt_h);    cudaGetSymbolAddress((void**)&Wdtl, g_Wdt_l);
    cudaGetSymbolAddress((void**)&Wproh, g_Wpro_h);  cudaGetSymbolAddress((void**)&Wprol, g_Wpro_l);
    cudaGetSymbolAddress((void**)&wAh, g_wA_h);      cudaGetSymbolAddress((void**)&wAl, g_wA_l);
    cudaGetSymbolAddress((void**)&wVh, g_wV_h);      cudaGetSymbolAddress((void**)&wVl, g_wV_l);
    cudaGetSymbolAddress((void**)&Wouth, g_Wout_h);  cudaGetSymbolAddress((void**)&Woutl, g_Wout_l);
    cudaGetSymbolAddress((void**)&yh2, g_yh);        cudaGetSymbolAddress((void**)&yl2, g_yl);

    cudaFuncSetAttribute(hgemm_ca, cudaFuncAttributeMaxDynamicSharedMemorySize, CA_SMEM_BYTES);

    // 0) fused init: zero accums + weight splits (Wxp permuted) + x split + pooling
    init_kernel<<<ceildiv(INIT_TOT, 256), 256>>>(
        x, W_in_x, W_in_z, W_xp_f, W_xp_b, W_dt_f, W_dt_b, W_pro_to,
        token_wA, token_wV, W_out, b_xp_f, b_xp_b, b_dt_f, b_dt_b, out);

    // 1) xi = x @ W_in_x^T  (cp.async pipeline, pre-split planes)
    hgemm_ca<<<dim3(DI / 128, ceildiv(ML, 128)), 256, CA_SMEM_BYTES>>>(
        xh, xl, Winxh, Winxl, nullptr, xi, ML, DI, Dmod, Dmod, Dmod, DI);

    // 2) zpacc = xp @ W_in_z^T (split-K4; silu applied in gated out-GEMM)
    hgemm4<1,0><<<dim3(DI / 128, 4, 4), 256>>>(
        xpf, nullptr, Winzh, Winzl, nullptr, nullptr, zpacc,
        Bsz * Stok, DI, Dmod, Dmod, Dmod, DI, DI, 0, 4, 0, 0, 0, 0);

    // 3) conv + silu (both dirs, t-tiled)
    conv_silu2_kernel<<<dim3(ceildiv(LC, CT), Bsz, 2), DI>>>(
        xi, conv_w_f, conv_b_f, conv_w_b, conv_b_b);

    // 4) dbc = u @ W_xp^T + b  (merged dirs, split-K2, atomic; cols permuted)
    hgemm4<1,0><<<dim3(1, ceildiv(MC, 128), 4), 256>>>(
        u, nullptr, Wxph, Wxpl, bxp, nullptr, dbc,
        MC, 128, DI, DI, DI, NXP, NXP, 0, 2,
        (long long)SZ_U, (long long)128 * DI, (long long)SZ_DBC, 128);

    // 5) delta = softplus(dr @ W_dt^T + b_dt)  (merged dirs, K=16)
    hgemm4<1,0><<<dim3(DI / 128, ceildiv(MC, 128), 2), 256>>>(
        dbc, nullptr, Wdth, Wdtl, bdt, nullptr, delta,
        MC, DI, DRK, NXP, DRK, DI, DI, 2, 1,
        (long long)SZ_DBC, (long long)DI * DRK, (long long)SZ_U, DI);

    // 6) selective scans (both dirs, 16 lanes/channel, float2 B/C)
    scan2_kernel<<<dim3(Bsz * DI / 16, 2), 256>>>(A_log_f, D_f, A_log_b, D_b);

    // 7) masks ('last'), both dirs
    dist2_kernel<<<dim3(ceildiv(LC, 8), Bsz, 2), 256>>>(LC - 1);
    maskfin2_kernel<<<dim3(Bsz, 2), 512>>>(LC - 1);

    // 8) y = [yf*mf | yb*rev(mb)] @ W_pro^T + b  (concat fused into A-loader)
    hgemm4<1,2><<<dim3(DI / 128, ceildiv(MC, 128)), 256>>>(
        nullptr, nullptr, Wproh, Wprol, b_pro_to, nullptr, yy,
        MC, DI, 2 * DI, 2 * DI, 2 * DI, DI, DI, 0, 1, 0, 0, 0, 0);

    // 9) center mask; scale y + split planes
    dist_kernel<<<dim3(ceildiv(LC, 8), Bsz), 256>>>(yy, dist, (LC + 1) / 2);
    maskfin_kernel<<<Bsz, 512>>>(dist, mc, (LC + 1) / 2);
    scale_y_kernel<<<dim3(LC, Bsz), DI>>>();

    // 10) scores = y @ wA^T (split-K2, atomic); softmax -> Atok
    hgemm4<1,0><<<dim3(1, ceildiv(MC, 128), 2), 256>>>(
        yy, nullptr, wAh, wAl, nullptr, nullptr, scores,
        MC, 128, DI, DI, DI, Stok, Stok, 0, 2, 0, 0, 0, 0);
    softmax_kernel<<<dim3(Stok, Bsz), 256>>>();

    // 11) Ty = Atok @ y  (TB=0, batched over b, split-K5, atomic)
    hgemm4<0,0><<<dim3(DI / 128, 1, Bsz * 5), 256>>>(
        atok, nullptr, yh2, yl2, nullptr, nullptr, tyacc,
        Stok, DI, LCP, LCP, DI, DI, DI, 0, 5,
        (long long)Stok * LCP, (long long)LC * DI, (long long)Stok * DI, 0);

    // 12) Tacc = Ty @ wV  (TB=0, batched, split-K4, atomic)
    hgemm4<0,0><<<dim3(DI / 128, 1, Bsz * 4), 256>>>(
        tyacc, nullptr, wVh, wVl, nullptr, nullptr, Tacc,
        Stok, DI, DI, DI, DI, DI, DI, 0, 4,
        (long long)Stok * DI, 0, (long long)Stok * DI, 0);

    // 13) out = (Tacc * silu(zpacc)) @ W_out^T  (gated A, split-K4, atomic)
    hgemm4<1,1><<<dim3(Dmod / 128, 4, 4), 256>>>(
        Tacc, zpacc, Wouth, Woutl, nullptr, nullptr, out,
        Bsz * Stok, Dmod, DI, DI, DI, Dmod, Dmod, 0, 4, 0, 0, 0, 0);
}

// round 15
// speedup vs baseline: 1.3163x; 1.0239x over previous
#include <cuda_runtime.h>
#include <cuda_bf16.h>
#include <math.h>
#include <stdint.h>

// ---------------- problem constants ----------------
#define Bsz  8
#define Lseq 2049
#define Dmod 256
#define DI   512
#define DS   16
#define DRK  16
#define LB   1025
#define LC   1028
#define Stok 64
#define NXP  48
#define LCP  1040   // LC padded to 16
#define CT   16     // conv timesteps per block

#define SZ_U    (Bsz*LC*DI)
#define SZ_DBC  (Bsz*LC*NXP)
#define ML      (Bsz*Lseq)
#define MC      (Bsz*LC)

// ---------------- fp32 scratch ----------------
__device__ float g_xi[Bsz*Lseq*DI];
__device__ float g_u[2*SZ_U];          // f, b
__device__ float g_dbc[2*SZ_DBC];      // f, b (atomic accum; B/C interleaved cols)
__device__ float g_delta[2*SZ_U];
__device__ float g_ysc[2*SZ_U];        // scan outputs f, b
__device__ float g_y[Bsz*LC*DI];
__device__ float g_mf[Bsz*LC];
__device__ float g_mb[Bsz*LC];
__device__ float g_mc[Bsz*LC];
__device__ float g_dist[Bsz*LC*2];
__device__ float g_xpf[Bsz*Stok*Dmod];
__device__ float g_zpacc[Bsz*Stok*DI];     // atomic accum (pre-silu)
__device__ float g_scores[Bsz*LC*Stok];    // atomic accum
__device__ float g_atok[Bsz*Stok*LCP];
__device__ float g_tyacc[Bsz*Stok*DI];     // atomic accum
__device__ float g_Tacc[Bsz*Stok*DI];      // atomic accum (pre-gate)
__device__ float g_bxp[2*128];
__device__ float g_bdt[2*DI];

// ---------------- bf16 planes ----------------
__device__ __nv_bfloat16 g_xh[ML*Dmod],       g_xl[ML*Dmod];          // x pre-split
__device__ __nv_bfloat16 g_Winx_h[DI*Dmod],   g_Winx_l[DI*Dmod];
__device__ __nv_bfloat16 g_Winz_h[DI*Dmod],   g_Winz_l[DI*Dmod];
__device__ __nv_bfloat16 g_Wxp_h[2*128*DI],   g_Wxp_l[2*128*DI];      // rows permuted (B/C interleave)
__device__ __nv_bfloat16 g_Wdt_h[2*DI*DRK],   g_Wdt_l[2*DI*DRK];
__device__ __nv_bfloat16 g_Wpro_h[DI*2*DI],   g_Wpro_l[DI*2*DI];
__device__ __nv_bfloat16 g_wA_h[128*DI],      g_wA_l[128*DI];
__device__ __nv_bfloat16 g_wV_h[DI*DI],       g_wV_l[DI*DI];
__device__ __nv_bfloat16 g_Wout_h[Dmod*DI],   g_Wout_l[Dmod*DI];
__device__ __nv_bfloat16 g_ycath[Bsz*LC*2*DI], g_ycatl[Bsz*LC*2*DI];  // concat output
__device__ __nv_bfloat16 g_yh[Bsz*LC*DI+16*DI], g_yl[Bsz*LC*DI+16*DI]; // slack rows stay 0

__device__ __forceinline__ void splitv(float v, __nv_bfloat16& h, __nv_bfloat16& l) {
    h = __float2bfloat16(v);
    l = __float2bfloat16(v - __bfloat162float(h));
}

// dbc column permutation: rows 0-15 identity (dr); output row 16+2j <- B_j (src 16+j);
// output row 17+2j <- C_j (src 32+j); rows >= 48 zero.
__device__ __forceinline__ int wxp_srcrow(int r) {
    if (r < 16) return r;
    if (r >= 48) return -1;
    int q = r - 16;
    return (q & 1) ? (32 + (q >> 1)) : (16 + (q >> 1));
}

// ---------------- fused init: zero accums + weight splits + x split + pool ----------------
#define Z1 (Bsz*Stok*DI)
#define Z2 (2*SZ_DBC)
#define Z3 (Bsz*LC*Stok)
#define Z4 (Bsz*Stok*DI)
#define Z5 (Bsz*Stok*DI)
#define Z6 (Bsz*Stok*Dmod)
#define ZTOT (Z1+Z2+Z3+Z4+Z5+Z6)
#define WTOT 1393920
#define XTOT (ML*Dmod)
#define PTOT (Bsz*Stok*Dmod)
#define INIT_TOT (ZTOT + WTOT + XTOT + PTOT)

__global__ void init_kernel(const float* __restrict__ x,
                            const float* __restrict__ Winx, const float* __restrict__ Winz,
                            const float* __restrict__ Wxpf, const float* __restrict__ Wxpb,
                            const float* __restrict__ Wdtf, const float* __restrict__ Wdtb,
                            const float* __restrict__ Wpro, const float* __restrict__ wA,
                            const float* __restrict__ wV,   const float* __restrict__ Wout,
                            const float* __restrict__ bxpf, const float* __restrict__ bxpb,
                            const float* __restrict__ bdtf, const float* __restrict__ bdtb,
                            float* __restrict__ dout)
{
    long long i = (long long)blockIdx.x * 256 + threadIdx.x;
    __nv_bfloat16 h, l;
    if (i < Z1) { g_zpacc[i] = 0.f; return; }  i -= Z1;
    if (i < Z2) { g_dbc[i] = 0.f; return; }    i -= Z2;
    if (i < Z3) { g_scores[i] = 0.f; return; } i -= Z3;
    if (i < Z4) { g_tyacc[i] = 0.f; return; }  i -= Z4;
    if (i < Z5) { g_Tacc[i] = 0.f; return; }   i -= Z5;
    if (i < Z6) { dout[i] = 0.f; return; }     i -= Z6;
    if (i < 131072) { splitv(Winx[i], h, l); g_Winx_h[i] = h; g_Winx_l[i] = l; return; }
    i -= 131072;
    if (i < 131072) { splitv(Winz[i], h, l); g_Winz_h[i] = h; g_Winz_l[i] = l; return; }
    i -= 131072;
    if (i < 131072) { int dir = i >> 16, j = i & 65535;
        int r = j >> 9, c = j & 511;
        const float* W = dir ? Wxpb : Wxpf;
        int sr = wxp_srcrow(r);
        splitv(sr >= 0 ? W[sr * DI + c] : 0.f, h, l);
        g_Wxp_h[i] = h; g_Wxp_l[i] = l; return; }
    i -= 131072;
    if (i < 16384) { int dir = i >> 13, j = i & 8191;
        const float* W = dir ? Wdtb : Wdtf;
        splitv(W[j], h, l); g_Wdt_h[i] = h; g_Wdt_l[i] = l; return; }
    i -= 16384;
    if (i < 524288) { splitv(Wpro[i], h, l); g_Wpro_h[i] = h; g_Wpro_l[i] = l; return; }
    i -= 524288;
    if (i < 65536) { int r = i >> 9, c = i & 511;
        splitv(r < Stok ? wA[r * DI + c] : 0.f, h, l);
        g_wA_h[i] = h; g_wA_l[i] = l; return; }
    i -= 65536;
    if (i < 262144) { splitv(wV[i], h, l); g_wV_h[i] = h; g_wV_l[i] = l; return; }
    i -= 262144;
    if (i < 131072) { splitv(Wout[i], h, l); g_Wout_h[i] = h; g_Wout_l[i] = l; return; }
    i -= 131072;
    if (i < 256) { int dir = i >> 7, r = i & 127;
        const float* bsrc = dir ? bxpb : bxpf;
        int sr = wxp_srcrow(r);
        g_bxp[i] = (sr >= 0) ? bsrc[sr] : 0.f; return; }
    i -= 256;
    if (i < 1024) { int dir = i >> 9, r = i & 511;
        g_bdt[i] = dir ? bdtb[r] : bdtf[r]; return; }
    i -= 1024;
    if (i < XTOT) { splitv(x[i], h, l); g_xh[i] = h; g_xl[i] = l; return; }
    i -= XTOT;
    if (i < PTOT) {   // pooling: xp[b,s,d] = mean_l x[b, l in [s0,e), d]
        int d = (int)(i % Dmod);
        int rest = (int)(i / Dmod);
        int s = rest % Stok;
        int b = rest / Stok;
        int s0 = (s * Lseq) / Stok;
        int e  = ((s + 1) * Lseq + Stok - 1) / Stok;
        float acc = 0.f;
        for (int lq = s0; lq < e; lq++) acc += x[((long long)b * Lseq + lq) * Dmod + d];
        g_xpf[((long long)b * Stok + s) * Dmod + d] = acc / (float)(e - s0);
    }
}

// ---------------- shared helpers ----------------
#define SAS 24

__device__ __forceinline__ uint32_t s2u(const void* p) {
    return (uint32_t)__cvta_generic_to_shared(p);
}
__device__ __forceinline__ void ldsm4(uint32_t r[4], uint32_t addr) {
    asm volatile("ldmatrix.sync.aligned.m8n8.x4.shared.b16 {%0,%1,%2,%3}, [%4];"
                 : "=r"(r[0]), "=r"(r[1]), "=r"(r[2]), "=r"(r[3]) : "r"(addr));
}
__device__ __forceinline__ void mma16816(float c[4], const uint32_t a[4],
                                         uint32_t b0, uint32_t b1) {
    asm volatile(
        "mma.sync.aligned.m16n8k16.row.col.f32.bf16.bf16.f32 "
        "{%0,%1,%2,%3},{%4,%5,%6,%7},{%8,%9},{%0,%1,%2,%3};"
        : "+f"(c[0]), "+f"(c[1]), "+f"(c[2]), "+f"(c[3])
        : "r"(a[0]), "r"(a[1]), "r"(a[2]), "r"(a[3]), "r"(b0), "r"(b1));
}
__device__ __forceinline__ void cpasync16(uint32_t dst, const void* src, int szbytes) {
    asm volatile("cp.async.ca.shared.global [%0], [%1], 16, %2;"
                 :: "r"(dst), "l"(src), "r"(szbytes));
}

// =====================================================================
// hgemm4: C = A * op(B planes), 3-split bf16 MMA (round-6 core).
// AMODE: 0 = plain fp32 A; 1 = A * silu(Ag) elementwise.
// =====================================================================
template<int TB, int AMODE>
__global__ __launch_bounds__(256, 2)
void hgemm4(const float* __restrict__ A, const float* __restrict__ Ag,
            const __nv_bfloat16* __restrict__ Bh, const __nv_bfloat16* __restrict__ Bl,
            const float* __restrict__ bias, const float* __restrict__ emul,
            float* __restrict__ C,
            int M, int N, int K, int lda, int ldb, int ldc, int Nout, int act, int KS,
            long long sA, long long sB, long long sC, long long sBias)
{
    __shared__ __align__(16) __nv_bfloat16 As_hi[128][SAS];
    __shared__ __align__(16) __nv_bfloat16 As_lo[128][SAS];
    __shared__ __align__(16) __nv_bfloat16 Bs_hi[128][SAS];
    __shared__ __align__(16) __nv_bfloat16 Bs_lo[128][SAS];

    int bz  = blockIdx.z;
    int dir = bz / KS;
    int ks  = bz % KS;
    A  += dir * sA;
    Bh += dir * sB; Bl += dir * sB;
    if (bias) bias += dir * sBias;
    int kchunk = K / KS;
    int kb = ks * kchunk, ke = kb + kchunk;

    int tid  = threadIdx.x;
    int lane = tid & 31;
    int wid  = tid >> 5;
    int wm0  = (wid >> 2) * 64;
    int wn0  = (wid & 3) * 32;
    int row0 = blockIdx.y * 128;
    int col0 = blockIdx.x * 128;

    int lr = lane & 15;
    int lc = (lane >> 4) * 8;

    int ar = tid >> 1;
    int ac = (tid & 1) * 8;
    int gm = row0 + ar;
    bool mok = gm < M;
    const float* Ap = A + (long long)gm * lda + ac;
    const float* Gp = (AMODE == 1) ? (Ag + (long long)gm * lda + ac) : nullptr;

    const __nv_bfloat16 *Bph = nullptr, *Bpl = nullptr;
    int bkk = 0, bnc = 0;
    if (TB == 1) {
        Bph = Bh + (long long)(col0 + ar) * ldb + ac;
        Bpl = Bl + (long long)(col0 + ar) * ldb + ac;
    } else {
        bkk = tid >> 4;
        bnc = (tid & 15) * 8;
        Bph = Bh + col0 + bnc;
        Bpl = Bl + col0 + bnc;
    }

    float4 ra0 = make_float4(0,0,0,0), ra1 = make_float4(0,0,0,0);
    float4 rg0 = make_float4(0,0,0,0), rg1 = make_float4(0,0,0,0);
    uint4 rbh, rbl;

    if (mok) {
        ra0 = *(const float4*)(Ap + kb); ra1 = *(const float4*)(Ap + kb + 4);
        if (AMODE == 1) { rg0 = *(const float4*)(Gp + kb); rg1 = *(const float4*)(Gp + kb + 4); }
    }
    if (TB == 1) {
        rbh = *(const uint4*)(Bph + kb); rbl = *(const uint4*)(Bpl + kb);
    } else {
        rbh = *(const uint4*)(Bph + (long long)(kb + bkk) * ldb);
        rbl = *(const uint4*)(Bpl + (long long)(kb + bkk) * ldb);
    }

    float acc[4][4][4];
    #pragma unroll
    for (int i = 0; i < 4; i++)
        #pragma unroll
        for (int j = 0; j < 4; j++)
            #pragma unroll
            for (int q = 0; q < 4; q++) acc[i][j][q] = 0.f;

    for (int k0 = kb; k0 < ke; k0 += 16) {
        {
            float av[8] = {ra0.x, ra0.y, ra0.z, ra0.w, ra1.x, ra1.y, ra1.z, ra1.w};
            if (AMODE == 1) {
                float gv[8] = {rg0.x, rg0.y, rg0.z, rg0.w, rg1.x, rg1.y, rg1.z, rg1.w};
                #pragma unroll
                for (int j = 0; j < 8; j++) av[j] *= gv[j] / (1.f + expf(-gv[j]));
            }
            __nv_bfloat16 hh[8], ll[8];
            #pragma unroll
            for (int j = 0; j < 8; j++) splitv(av[j], hh[j], ll[j]);
            *(uint4*)&As_hi[ar][ac] = *(uint4*)hh;
            *(uint4*)&As_lo[ar][ac] = *(uint4*)ll;
        }
        if (TB == 1) {
            *(uint4*)&Bs_hi[ar][ac] = rbh;
            *(uint4*)&Bs_lo[ar][ac] = rbl;
        } else {
            __nv_bfloat16 th[8], tl[8];
            *(uint4*)th = rbh; *(uint4*)tl = rbl;
            #pragma unroll
            for (int j = 0; j < 8; j++) {
                Bs_hi[bnc + j][bkk] = th[j];
                Bs_lo[bnc + j][bkk] = tl[j];
            }
        }
        __syncthreads();

        if (k0 + 16 < ke) {
            int kn = k0 + 16;
            if (mok) {
                ra0 = *(const float4*)(Ap + kn);
                ra1 = *(const float4*)(Ap + kn + 4);
                if (AMODE == 1) {
                    rg0 = *(const float4*)(Gp + kn);
                    rg1 = *(const float4*)(Gp + kn + 4);
                }
            }
            if (TB == 1) {
                rbh = *(const uint4*)(Bph + kn);
                rbl = *(const uint4*)(Bpl + kn);
            } else {
                rbh = *(const uint4*)(Bph + (long long)(kn + bkk) * ldb);
                rbl = *(const uint4*)(Bpl + (long long)(kn + bkk) * ldb);
            }
        }

        uint32_t bhf[2][4], blf[2][4];
        #pragma unroll
        for (int ng = 0; ng < 2; ng++) {
            ldsm4(bhf[ng], s2u(&Bs_hi[wn0 + ng * 16 + lr][lc]));
            ldsm4(blf[ng], s2u(&Bs_lo[wn0 + ng * 16 + lr][lc]));
        }
        #pragma unroll
        for (int mt = 0; mt < 4; mt++) {
            uint32_t a_h[4], a_l[4];
            ldsm4(a_h, s2u(&As_hi[wm0 + mt * 16 + lr][lc]));
            ldsm4(a_l, s2u(&As_lo[wm0 + mt * 16 + lr][lc]));
            #pragma unroll
            for (int nt = 0; nt < 4; nt++) {
                int ng = nt >> 1, sl = nt & 1;
                mma16816(acc[mt][nt], a_h, bhf[ng][sl], bhf[ng][sl + 2]);
                mma16816(acc[mt][nt], a_h, blf[ng][sl], blf[ng][sl + 2]);
                mma16816(acc[mt][nt], a_l, bhf[ng][sl], bhf[ng][sl + 2]);
            }
        }
        __syncthreads();
    }

    int g = lane >> 2, t4 = lane & 3;
    #pragma unroll
    for (int mt = 0; mt < 4; mt++) {
        #pragma unroll
        for (int nt = 0; nt < 4; nt++) {
            int cb = col0 + wn0 + nt * 8 + 2 * t4;
            if (cb >= Nout) continue;
            float b0 = 0.f, b1 = 0.f;
            if (bias && (KS == 1 || ks == 0)) { b0 = bias[cb]; b1 = bias[cb + 1]; }
            #pragma unroll
            for (int hrow = 0; hrow < 2; hrow++) {
                int m = row0 + wm0 + mt * 16 + g + hrow * 8;
                if (m >= M) continue;
                float v0 = acc[mt][nt][hrow * 2 + 0] + b0;
                float v1 = acc[mt][nt][hrow * 2 + 1] + b1;
                long long co = dir * sC + (long long)m * ldc + cb;
                if (KS > 1) {
                    atomicAdd(C + co, v0);
                    atomicAdd(C + co + 1, v1);
                } else {
                    if (act == 1) {
                        v0 = v0 / (1.f + expf(-v0));
                        v1 = v1 / (1.f + expf(-v1));
                    } else if (act == 2) {
                        v0 = (v0 > 20.f) ? v0 : log1pf(expf(v0));
                        v1 = (v1 > 20.f) ? v1 : log1pf(expf(v1));
                    }
                    if (emul) { v0 *= emul[co]; v1 *= emul[co + 1]; }
                    *(float2*)(C + co) = make_float2(v0, v1);
                }
            }
        }
    }
}

// =====================================================================
// hgemm_ca: big-GEMM specialist (xi, ycat).
// =====================================================================
#define CA_PL  (128*SAS)
#define CA_STG (4*CA_PL)
#define CA_SMEM_BYTES (3*CA_STG*2)

__global__ __launch_bounds__(256, 2)
void hgemm_ca(const __nv_bfloat16* __restrict__ Ah, const __nv_bfloat16* __restrict__ Al,
              const __nv_bfloat16* __restrict__ Bh, const __nv_bfloat16* __restrict__ Bl,
              const float* __restrict__ bias, float* __restrict__ C,
              int M, int N, int K, int lda, int ldb, int ldc)
{
    extern __shared__ __align__(16) __nv_bfloat16 sm[];
    uint32_t smb = s2u(sm);

    int tid  = threadIdx.x;
    int lane = tid & 31;
    int wid  = tid >> 5;
    int wm0  = (wid >> 2) * 64;
    int wn0  = (wid & 3) * 32;
    int row0 = blockIdx.y * 128;
    int col0 = blockIdx.x * 128;

    int lr = lane & 15;
    int lc = (lane >> 4) * 8;

    int ar = tid >> 1;
    int ac = (tid & 1) * 8;
    int gm = row0 + ar;
    int asz = (gm < M) ? 16 : 0;
    const __nv_bfloat16* Aph = Ah + (long long)gm * lda + ac;
    const __nv_bfloat16* Apl = Al + (long long)gm * lda + ac;
    const __nv_bfloat16* Bph = Bh + (long long)(col0 + ar) * ldb + ac;
    const __nv_bfloat16* Bpl = Bl + (long long)(col0 + ar) * ldb + ac;

    uint32_t offA_h = (uint32_t)(0 * CA_PL + ar * SAS + ac) * 2;
    uint32_t offA_l = (uint32_t)(1 * CA_PL + ar * SAS + ac) * 2;
    uint32_t offB_h = (uint32_t)(2 * CA_PL + ar * SAS + ac) * 2;
    uint32_t offB_l = (uint32_t)(3 * CA_PL + ar * SAS + ac) * 2;

    float acc[4][4][4];
    #pragma unroll
    for (int i = 0; i < 4; i++)
        #pragma unroll
        for (int j = 0; j < 4; j++)
            #pragma unroll
            for (int q = 0; q < 4; q++) acc[i][j][q] = 0.f;

    {
        uint32_t sb = smb;
        cpasync16(sb + offA_h, Aph + 0, asz);
        cpasync16(sb + offA_l, Apl + 0, asz);
        cpasync16(sb + offB_h, Bph + 0, 16);
        cpasync16(sb + offB_l, Bpl + 0, 16);
        asm volatile("cp.async.commit_group;" ::: "memory");
    }
    if (16 < K) {
        uint32_t sb = smb + CA_STG * 2;
        cpasync16(sb + offA_h, Aph + 16, asz);
        cpasync16(sb + offA_l, Apl + 16, asz);
        cpasync16(sb + offB_h, Bph + 16, 16);
        cpasync16(sb + offB_l, Bpl + 16, 16);
        asm volatile("cp.async.commit_group;" ::: "memory");
    } else {
        asm volatile("cp.async.commit_group;" ::: "memory");
    }

    int cur = 0;
    for (int k0 = 0; k0 < K; k0 += 16) {
        asm volatile("cp.async.wait_group 1;" ::: "memory");
        __syncthreads();

        uint32_t sb = smb + (uint32_t)cur * (CA_STG * 2);

        uint32_t bhf[2][4], blf[2][4];
        #pragma unroll
        for (int ng = 0; ng < 2; ng++) {
            uint32_t rb = (uint32_t)(wn0 + ng * 16 + lr) * SAS + lc;
            ldsm4(bhf[ng], sb + (uint32_t)(2 * CA_PL) * 2 + rb * 2);
            ldsm4(blf[ng], sb + (uint32_t)(3 * CA_PL) * 2 + rb * 2);
        }
        #pragma unroll
        for (int mt = 0; mt < 4; mt++) {
            uint32_t raddr = (uint32_t)(wm0 + mt * 16 + lr) * SAS + lc;
            uint32_t a_h[4], a_l[4];
            ldsm4(a_h, sb + raddr * 2);
            ldsm4(a_l, sb + (uint32_t)(CA_PL) * 2 + raddr * 2);
            #pragma unroll
            for (int nt = 0; nt < 4; nt++) {
                int ng = nt >> 1, sl = nt & 1;
                mma16816(acc[mt][nt], a_h, bhf[ng][sl], bhf[ng][sl + 2]);
                mma16816(acc[mt][nt], a_h, blf[ng][sl], blf[ng][sl + 2]);
                mma16816(acc[mt][nt], a_l, bhf[ng][sl], bhf[ng][sl + 2]);
            }
        }

        int nk = k0 + 32;
        if (nk < K) {
            int nst = cur + 2; if (nst >= 3) nst -= 3;
            uint32_t nb = smb + (uint32_t)nst * (CA_STG * 2);
            cpasync16(nb + offA_h, Aph + nk, asz);
            cpasync16(nb + offA_l, Apl + nk, asz);
            cpasync16(nb + offB_h, Bph + nk, 16);
            cpasync16(nb + offB_l, Bpl + nk, 16);
        }
        asm volatile("cp.async.commit_group;" ::: "memory");

        cur++; if (cur == 3) cur = 0;
    }

    int g = lane >> 2, t4 = lane & 3;
    #pragma unroll
    for (int mt = 0; mt < 4; mt++) {
        #pragma unroll
        for (int nt = 0; nt < 4; nt++) {
            int cb = col0 + wn0 + nt * 8 + 2 * t4;
            float b0 = 0.f, b1 = 0.f;
            if (bias) { b0 = bias[cb]; b1 = bias[cb + 1]; }
            #pragma unroll
            for (int hrow = 0; hrow < 2; hrow++) {
                int m = row0 + wm0 + mt * 16 + g + hrow * 8;
                if (m >= M) continue;
                float v0 = acc[mt][nt][hrow * 2 + 0] + b0;
                float v1 = acc[mt][nt][hrow * 2 + 1] + b1;
                *(float2*)(C + (long long)m * ldc + cb) = make_float2(v0, v1);
            }
        }
    }
}

// ---------------- depthwise conv + SiLU, t-tiled (CT steps/block), both dirs ----------------
__global__ void conv_silu2_kernel(const float* __restrict__ xi,
                                  const float* __restrict__ wf, const float* __restrict__ bf,
                                  const float* __restrict__ wb, const float* __restrict__ bb)
{
    int t0 = blockIdx.x * CT;
    int b = blockIdx.y;
    int back = blockIdx.z;
    int c = threadIdx.x;
    const float* w  = back ? wb : wf;
    float bias      = back ? bb[c] : bf[c];
    float* out      = g_u + (long long)back * SZ_U;

    float w0 = w[c * 4 + 0], w1 = w[c * 4 + 1], w2 = w[c * 4 + 2], w3 = w[c * 4 + 3];

    float xv[CT + 3];
    #pragma unroll
    for (int j = 0; j < CT + 3; j++) {
        int i = t0 + j - 3;
        float v = 0.f;
        if (i >= 0 && i < LB) {
            int l = back ? (Lseq - 1 - i) : i;
            v = xi[((long long)b * Lseq + l) * DI + c];
        }
        xv[j] = v;
    }
    #pragma unroll
    for (int j = 0; j < CT; j++) {
        int t = t0 + j;
        if (t >= LC) break;
        float acc = bias;
        acc = fmaf(w0, xv[j],     acc);
        acc = fmaf(w1, xv[j + 1], acc);
        acc = fmaf(w2, xv[j + 2], acc);
        acc = fmaf(w3, xv[j + 3], acc);
        out[((long long)b * LC + t) * DI + c] = acc / (1.f + expf(-acc));
    }
}

// ---------------- selective scans: 16 lanes/channel, float2 B/C ----------------
__global__ __launch_bounds__(256)
void scan2_kernel(const float* __restrict__ A_log_f, const float* __restrict__ D_f,
                  const float* __restrict__ A_log_b, const float* __restrict__ D_b)
{
    int back = blockIdx.y;
    const float* u     = g_u     + (long long)back * SZ_U;
    const float* delta = g_delta + (long long)back * SZ_U;
    const float* dbc   = g_dbc   + (long long)back * SZ_DBC;
    const float* A_log = back ? A_log_b : A_log_f;
    const float* Dp    = back ? D_b : D_f;
    float* y           = g_ysc   + (long long)back * SZ_U;

    int gid = blockIdx.x * 16 + (threadIdx.x >> 4);
    int s = threadIdx.x & 15;
    int b = gid >> 9;
    int d = gid & 511;
    float Av = -expf(A_log[d * 16 + s]);
    float Dd = Dp[d];
    float h = 0.f;
    const float* db = dbc + (long long)b * LC * NXP + 16 + 2 * s;  // interleaved B,C
    const float* dl = delta + ((long long)b * LC) * DI + d;
    const float* uu = u     + ((long long)b * LC) * DI + d;
    float*       yy = y     + ((long long)b * LC) * DI + d;
    #pragma unroll 4
    for (int t = 0; t < LC; t++) {
        float de = __ldg(dl + (long long)t * DI);
        float uv = __ldg(uu + (long long)t * DI);
        float2 bc = __ldg((const float2*)(db + t * NXP));
        float dA = __expf(de * Av);
        h = fmaf(dA, h, de * uv * bc.x);
        float v = h * bc.y;
        v += __shfl_xor_sync(0xffffffffu, v, 8);
        v += __shfl_xor_sync(0xffffffffu, v, 4);
        v += __shfl_xor_sync(0xffffffffu, v, 2);
        v += __shfl_xor_sync(0xffffffffu, v, 1);
        if (s == 0) yy[(long long)t * DI] = fmaf(Dd, uv, v);
    }
}

// ---------------- gaussian masks ----------------
__global__ void dist2_kernel(int ref)
{
    int back = blockIdx.z;
    const float* y = g_ysc + (long long)back * SZ_U;
    float* dist = g_dist + back * (Bsz * LC);
    int b = blockIdx.y;
    int t = blockIdx.x * 8 + (threadIdx.x >> 5);
    int lane = threadIdx.x & 31;
    if (t >= LC) return;
    const float* yt = y + ((long long)b * LC + t) * DI;
    const float* yr = y + ((long long)b * LC + ref) * DI;
    float acc = 0.f;
    for (int d = lane; d < DI; d += 32) {
        float df = yt[d] - yr[d];
        acc = fmaf(df, df, acc);
    }
    #pragma unroll
    for (int o = 16; o; o >>= 1) acc += __shfl_xor_sync(0xffffffffu, acc, o);
    if (lane == 0) dist[b * LC + t] = sqrtf(fmaxf(acc, 1e-12f));
}

__global__ void dist_kernel(const float* __restrict__ y, float* __restrict__ dist, int ref)
{
    int b = blockIdx.y;
    int t = blockIdx.x * 8 + (threadIdx.x >> 5);
    int lane = threadIdx.x & 31;
    if (t >= LC) return;
    const float* yt = y + ((long long)b * LC + t) * DI;
    const float* yr = y + ((long long)b * LC + ref) * DI;
    float acc = 0.f;
    for (int d = lane; d < DI; d += 32) {
        float df = yt[d] - yr[d];
        acc = fmaf(df, df, acc);
    }
    #pragma unroll
    for (int o = 16; o; o >>= 1) acc += __shfl_xor_sync(0xffffffffu, acc, o);
    if (lane == 0) dist[b * LC + t] = sqrtf(fmaxf(acc, 1e-12f));
}

__device__ __forceinline__ void maskfin_body(const float* dist, float* m, int ref,
                                             float* red, int tid)
{
    float s = 0.f;
    for (int t = tid; t < LC; t += 512) s += dist[t];
    red[tid] = s; __syncthreads();
    for (int o = 256; o; o >>= 1) { if (tid < o) red[tid] += red[tid + o]; __syncthreads(); }
    float sigv = red[0] / (float)LC;
    __syncthreads();
    float si = ((float)ref * (float)(ref + 1) * 0.5f +
                (float)(LC - 1 - ref) * (float)(LC - ref) * 0.5f) / (float)LC;
    float c_i = 0.5f / (si * si);
    float c_v = 0.5f / (sigv * sigv);
    float nrm = 0.f;
    for (int t = tid; t < LC; t += 512) {
        float dt = (float)(t - ref);
        float dv = dist[t];
        float p = expf(-dt * dt * c_i - dv * dv * c_v);
        m[t] = p;
        nrm = fmaf(p, p, nrm);
    }
    red[tid] = nrm; __syncthreads();
    for (int o = 256; o; o >>= 1) { if (tid < o) red[tid] += red[tid + o]; __syncthreads(); }
    float inv = 1.f / fmaxf(sqrtf(red[0]), 1e-12f);
    __syncthreads();
    for (int t = tid; t < LC; t += 512) m[t] *= inv;
}

__global__ void maskfin2_kernel(int ref)
{
    __shared__ float red[512];
    int back = blockIdx.y;
    int b = blockIdx.x;
    const float* dist = g_dist + back * (Bsz * LC) + b * LC;
    float* m = (back ? g_mb : g_mf) + b * LC;
    maskfin_body(dist, m, ref, red, threadIdx.x);
}

__global__ void maskfin_kernel(const float* __restrict__ dist, float* __restrict__ m, int ref)
{
    __shared__ float red[512];
    int b = blockIdx.x;
    maskfin_body(dist + b * LC, m + b * LC, ref, red, threadIdx.x);
}

// ycat = [ y_f * m_f , y_b * reverse(m_b) ]  -> bf16 split planes
__global__ void concat_kernel()
{
    int t = blockIdx.x, b = blockIdx.y, c = threadIdx.x;
    long long r = (long long)b * LC + t;
    float v0 = g_ysc[r * DI + c] * g_mf[b * LC + t];
    float v1 = g_ysc[SZ_U + r * DI + c] * g_mb[b * LC + (LC - 1 - t)];
    __nv_bfloat16 h, l;
    splitv(v0, h, l);
    g_ycath[r * (2 * DI) + c] = h;      g_ycatl[r * (2 * DI) + c] = l;
    splitv(v1, h, l);
    g_ycath[r * (2 * DI) + DI + c] = h; g_ycatl[r * (2 * DI) + DI + c] = l;
}

// y *= mc (in place) + bf16 split planes
__global__ void scale_y_kernel()
{
    int t = blockIdx.x, b = blockIdx.y, c = threadIdx.x;
    long long r = (long long)b * LC + t;
    float v = g_y[r * DI + c] * g_mc[b * LC + t];
    g_y[r * DI + c] = v;
    __nv_bfloat16 h, l; splitv(v, h, l);
    g_yh[r * DI + c] = h; g_yl[r * DI + c] = l;
}

// softmax over l per (b, token): fp32 Atok (B, Stok, LCP), pad zeroed
__global__ void softmax_kernel()
{
    __shared__ float sv[LC];
    __shared__ float red[256];
    int tt = blockIdx.x, b = blockIdx.y, tid = threadIdx.x;
    float mx = -1e30f;
    for (int l = tid; l < LC; l += 256) {
        float v = g_scores[((long long)b * LC + l) * Stok + tt];
        sv[l] = v; mx = fmaxf(mx, v);
    }
    red[tid] = mx; __syncthreads();
    for (int o = 128; o; o >>= 1) { if (tid < o) red[tid] = fmaxf(red[tid], red[tid + o]); __syncthreads(); }
    mx = red[0]; __syncthreads();
    float sum = 0.f;
    for (int l = tid; l < LC; l += 256) { float e = expf(sv[l] - mx); sv[l] = e; sum += e; }
    red[tid] = sum; __syncthreads();
    for (int o = 128; o; o >>= 1) { if (tid < o) red[tid] += red[tid + o]; __syncthreads(); }
    float inv = 1.f / red[0]; __syncthreads();
    long long base = ((long long)b * Stok + tt) * LCP;
    for (int l = tid; l < LC; l += 256) g_atok[base + l] = sv[l] * inv;
    if (tid < LCP - LC) g_atok[base + LC + tid] = 0.f;
}

// ---------------- host launcher ----------------
static inline int ceildiv(int a, int b) { return (a + b - 1) / b; }

extern "C" void kernel_launch(void* const* d_in, const int* in_sizes, int n_in,
                              void* d_out, int out_size)
{
    const float* x        = (const float*)d_in[0];
    const float* W_in_x   = (const float*)d_in[1];
    const float* W_in_z   = (const float*)d_in[2];
    const float* conv_w_f = (const float*)d_in[3];
    const float* conv_b_f = (const float*)d_in[4];
    const float* conv_w_b = (const float*)d_in[5];
    const float* conv_b_b = (const float*)d_in[6];
    const float* W_xp_f   = (const float*)d_in[7];
    const float* b_xp_f   = (const float*)d_in[8];
    const float* W_dt_f   = (const float*)d_in[9];
    const float* b_dt_f   = (const float*)d_in[10];
    const float* A_log_f  = (const float*)d_in[11];
    const float* D_f      = (const float*)d_in[12];
    const float* W_xp_b   = (const float*)d_in[13];
    const float* b_xp_b   = (const float*)d_in[14];
    const float* W_dt_b   = (const float*)d_in[15];
    const float* b_dt_b   = (const float*)d_in[16];
    const float* A_log_b  = (const float*)d_in[17];
    const float* D_b      = (const float*)d_in[18];
    const float* W_pro_to = (const float*)d_in[19];
    const float* b_pro_to = (const float*)d_in[20];
    const float* token_wA = (const float*)d_in[21];
    const float* token_wV = (const float*)d_in[22];
    const float* W_out    = (const float*)d_in[23];
    float* out = (float*)d_out;

    float *xi, *u, *dbc, *delta, *yy, *mc, *dist, *xpf, *zpacc;
    float *scores, *atok, *tyacc, *Tacc, *bxp, *bdt;
    cudaGetSymbolAddress((void**)&xi,    g_xi);
    cudaGetSymbolAddress((void**)&u,     g_u);
    cudaGetSymbolAddress((void**)&dbc,   g_dbc);
    cudaGetSymbolAddress((void**)&delta, g_delta);
    cudaGetSymbolAddress((void**)&yy,    g_y);
    cudaGetSymbolAddress((void**)&mc,    g_mc);
    cudaGetSymbolAddress((void**)&dist,  g_dist);
    cudaGetSymbolAddress((void**)&xpf,   g_xpf);
    cudaGetSymbolAddress((void**)&zpacc, g_zpacc);
    cudaGetSymbolAddress((void**)&scores, g_scores);
    cudaGetSymbolAddress((void**)&atok,  g_atok);
    cudaGetSymbolAddress((void**)&tyacc, g_tyacc);
    cudaGetSymbolAddress((void**)&Tacc,  g_Tacc);
    cudaGetSymbolAddress((void**)&bxp,   g_bxp);
    cudaGetSymbolAddress((void**)&bdt,   g_bdt);

    __nv_bfloat16 *xh,*xl,*Winxh,*Winxl,*Winzh,*Winzl,*Wxph,*Wxpl,*Wdth,*Wdtl;
    __nv_bfloat16 *Wproh,*Wprol,*wAh,*wAl,*wVh,*wVl,*Wouth,*Woutl;
    __nv_bfloat16 *ycath,*ycatl,*yh2,*yl2;
    cudaGetSymbolAddress((void**)&xh, g_xh);         cudaGetSymbolAddress((void**)&xl, g_xl);
    cudaGetSymbolAddress((void**)&Winxh, g_Winx_h);  cudaGetSymbolAddress((void**)&Winxl, g_Winx_l);
    cudaGetSymbolAddress((void**)&Winzh, g_Winz_h);  cudaGetSymbolAddress((void**)&Winzl, g_Winz_l);
    cudaGetSymbolAddress((void**)&Wxph, g_Wxp_h);    cudaGetSymbolAddress((void**)&Wxpl, g_Wxp_l);
    cudaGetSymbolAddress((void**)&Wdth, g_Wdt_h);    cudaGetSymbolAddress((void**)&Wdtl, g_Wdt_l);
    cudaGetSymbolAddress((void**)&Wproh, g_Wpro_h);  cudaGetSymbolAddress((void**)&Wprol, g_Wpro_l);
    cudaGetSymbolAddress((void**)&wAh, g_wA_h);      cudaGetSymbolAddress((void**)&wAl, g_wA_l);
    cudaGetSymbolAddress((void**)&wVh, g_wV_h);      cudaGetSymbolAddress((void**)&wVl, g_wV_l);
    cudaGetSymbolAddress((void**)&Wouth, g_Wout_h);  cudaGetSymbolAddress((void**)&Woutl, g_Wout_l);
    cudaGetSymbolAddress((void**)&ycath, g_ycath);   cudaGetSymbolAddress((void**)&ycatl, g_ycatl);
    cudaGetSymbolAddress((void**)&yh2, g_yh);        cudaGetSymbolAddress((void**)&yl2, g_yl);

    cudaFuncSetAttribute(hgemm_ca, cudaFuncAttributeMaxDynamicSharedMemorySize, CA_SMEM_BYTES);

    // 0) fused init: zero accums + weight splits (Wxp permuted) + x split + pooling
    init_kernel<<<ceildiv(INIT_TOT, 256), 256>>>(
        x, W_in_x, W_in_z, W_xp_f, W_xp_b, W_dt_f, W_dt_b, W_pro_to,
        token_wA, token_wV, W_out, b_xp_f, b_xp_b, b_dt_f, b_dt_b, out);

    // 1) xi = x @ W_in_x^T  (cp.async pipeline, pre-split planes)
    hgemm_ca<<<dim3(DI / 128, ceildiv(ML, 128)), 256, CA_SMEM_BYTES>>>(
        xh, xl, Winxh, Winxl, nullptr, xi, ML, DI, Dmod, Dmod, Dmod, DI);

    // 2) zpacc = xp @ W_in_z^T (split-K4; silu applied in gated out-GEMM)
    hgemm4<1,0><<<dim3(DI / 128, 4, 4), 256>>>(
        xpf, nullptr, Winzh, Winzl, nullptr, nullptr, zpacc,
        Bsz * Stok, DI, Dmod, Dmod, Dmod, DI, DI, 0, 4, 0, 0, 0, 0);

    // 3) conv + silu (both dirs, t-tiled CT=16)
    conv_silu2_kernel<<<dim3(ceildiv(LC, CT), Bsz, 2), DI>>>(
        xi, conv_w_f, conv_b_f, conv_w_b, conv_b_b);

    // 4) dbc = u @ W_xp^T + b  (merged dirs, split-K2, atomic; cols permuted)
    hgemm4<1,0><<<dim3(1, ceildiv(MC, 128), 4), 256>>>(
        u, nullptr, Wxph, Wxpl, bxp, nullptr, dbc,
        MC, 128, DI, DI, DI, NXP, NXP, 0, 2,
        (long long)SZ_U, (long long)128 * DI, (long long)SZ_DBC, 128);

    // 5) delta = softplus(dr @ W_dt^T + b_dt)  (merged dirs, K=16)
    hgemm4<1,0><<<dim3(DI / 128, ceildiv(MC, 128), 2), 256>>>(
        dbc, nullptr, Wdth, Wdtl, bdt, nullptr, delta,
        MC, DI, DRK, NXP, DRK, DI, DI, 2, 1,
        (long long)SZ_DBC, (long long)DI * DRK, (long long)SZ_U, DI);

    // 6) selective scans (both dirs, 16 lanes/channel, float2 B/C)
    scan2_kernel<<<dim3(Bsz * DI / 16, 2), 256>>>(A_log_f, D_f, A_log_b, D_b);

    // 7) masks ('last'), both dirs
    dist2_kernel<<<dim3(ceildiv(LC, 8), Bsz, 2), 256>>>(LC - 1);
    maskfin2_kernel<<<dim3(Bsz, 2), 512>>>(LC - 1);

    // 8) ycat planes; y = ycat @ W_pro^T + b (cp.async pipeline)
    concat_kernel<<<dim3(LC, Bsz), DI>>>();
    hgemm_ca<<<dim3(DI / 128, ceildiv(MC, 128)), 256, CA_SMEM_BYTES>>>(
        ycath, ycatl, Wproh, Wprol, b_pro_to, yy, MC, DI, 2 * DI, 2 * DI, 2 * DI, DI);

    // 9) center mask; scale y + split planes
    dist_kernel<<<dim3(ceildiv(LC, 8), Bsz), 256>>>(yy, dist, (LC + 1) / 2);
    maskfin_kernel<<<Bsz, 512>>>(dist, mc, (LC + 1) / 2);
    scale_y_kernel<<<dim3(LC, Bsz), DI>>>();

    // 10) scores = y @ wA^T (split-K2, atomic); softmax -> Atok
    hgemm4<1,0><<<dim3(1, ceildiv(MC, 128), 2), 256>>>(
        yy, nullptr, wAh, wAl, nullptr, nullptr, scores,
        MC, 128, DI, DI, DI, Stok, Stok, 0, 2, 0, 0, 0, 0);
    softmax_kernel<<<dim3(Stok, Bsz), 256>>>();

    // 11) Ty = Atok @ y  (TB=0, batched over b, split-K5, atomic)
    hgemm4<0,0><<<dim3(DI / 128, 1, Bsz * 5), 256>>>(
        atok, nullptr, yh2, yl2, nullptr, nullptr, tyacc,
        Stok, DI, LCP, LCP, DI, DI, DI, 0, 5,
        (long long)Stok * LCP, (long long)LC * DI, (long long)Stok * DI, 0);

    // 12) Tacc = Ty @ wV  (TB=0, batched, split-K4, atomic)
    hgemm4<0,0><<<dim3(DI / 128, 1, Bsz * 4), 256>>>(
        tyacc, nullptr, wVh, wVl, nullptr, nullptr, Tacc,
        Stok, DI, DI, DI, DI, DI, DI, 0, 4,
        (long long)Stok * DI, 0, (long long)Stok * DI, 0);

    // 13) out = (Tacc * silu(zpacc)) @ W_out^T  (gated A, split-K4, atomic)
    hgemm4<1,1><<<dim3(Dmod / 128, 4, 4), 256>>>(
        Tacc, zpacc, Wouth, Woutl, nullptr, nullptr, out,
        Bsz * Stok, Dmod, DI, DI, DI, Dmod, Dmod, 0, 4, 0, 0, 0, 0);
}

// round 16
// speedup vs baseline: 1.3218x; 1.0042x over previous
#include <cuda_runtime.h>
#include <cuda_bf16.h>
#include <math.h>
#include <stdint.h>

// ---------------- problem constants ----------------
#define Bsz  8
#define Lseq 2049
#define Dmod 256
#define DI   512
#define DS   16
#define DRK  16
#define LB   1025
#define LC   1028
#define Stok 64
#define NXP  48
#define LCP  1040   // LC padded to 16
#define CT   16     // conv timesteps per block

#define SZ_U    (Bsz*LC*DI)
#define SZ_DBC  (Bsz*LC*NXP)
#define ML      (Bsz*Lseq)
#define MC      (Bsz*LC)

// ---------------- fp32 scratch ----------------
__device__ float g_xi[Bsz*Lseq*DI];
__device__ float g_u[2*SZ_U];          // f, b
__device__ float g_dbc[2*SZ_DBC];      // f, b (atomic accum; B/C interleaved cols)
__device__ float g_delta[2*SZ_U];
__device__ float g_ysc[2*SZ_U];        // scan outputs f, b
__device__ float g_y[Bsz*LC*DI];
__device__ float g_mf[Bsz*LC];
__device__ float g_mb[Bsz*LC];
__device__ float g_mc[Bsz*LC];
__device__ float g_dist[Bsz*LC*2];
__device__ float g_xpf[Bsz*Stok*Dmod];
__device__ float g_zpacc[Bsz*Stok*DI];     // atomic accum (pre-silu)
__device__ float g_scores[Bsz*LC*Stok];    // atomic accum
__device__ float g_atok[Bsz*Stok*LCP];
__device__ float g_tyacc[Bsz*Stok*DI];     // atomic accum
__device__ float g_Tacc[Bsz*Stok*DI];      // atomic accum (pre-gate)
__device__ float g_bxp[2*128];
__device__ float g_bdt[2*DI];

// ---------------- bf16 planes ----------------
__device__ __nv_bfloat16 g_xh[ML*Dmod],       g_xl[ML*Dmod];          // x pre-split
__device__ __nv_bfloat16 g_Winx_h[DI*Dmod],   g_Winx_l[DI*Dmod];
__device__ __nv_bfloat16 g_Winz_h[DI*Dmod],   g_Winz_l[DI*Dmod];
__device__ __nv_bfloat16 g_Wxp_h[2*128*DI],   g_Wxp_l[2*128*DI];      // rows permuted (B/C interleave)
__device__ __nv_bfloat16 g_Wdt_h[2*DI*DRK],   g_Wdt_l[2*DI*DRK];
__device__ __nv_bfloat16 g_Wpro_h[DI*2*DI],   g_Wpro_l[DI*2*DI];
__device__ __nv_bfloat16 g_wA_h[128*DI],      g_wA_l[128*DI];
__device__ __nv_bfloat16 g_wV_h[DI*DI],       g_wV_l[DI*DI];
__device__ __nv_bfloat16 g_Wout_h[Dmod*DI],   g_Wout_l[Dmod*DI];
__device__ __nv_bfloat16 g_ycath[Bsz*LC*2*DI], g_ycatl[Bsz*LC*2*DI];  // concat output
__device__ __nv_bfloat16 g_yh[Bsz*LC*DI+16*DI], g_yl[Bsz*LC*DI+16*DI]; // slack rows stay 0

__device__ __forceinline__ void splitv(float v, __nv_bfloat16& h, __nv_bfloat16& l) {
    h = __float2bfloat16(v);
    l = __float2bfloat16(v - __bfloat162float(h));
}

// dbc column permutation: rows 0-15 identity (dr); output row 16+2j <- B_j (src 16+j);
// output row 17+2j <- C_j (src 32+j); rows >= 48 zero.
__device__ __forceinline__ int wxp_srcrow(int r) {
    if (r < 16) return r;
    if (r >= 48) return -1;
    int q = r - 16;
    return (q & 1) ? (32 + (q >> 1)) : (16 + (q >> 1));
}

// ---------------- fused init: zero accums + weight splits + x split + pool ----------------
#define Z1 (Bsz*Stok*DI)
#define Z2 (2*SZ_DBC)
#define Z3 (Bsz*LC*Stok)
#define Z4 (Bsz*Stok*DI)
#define Z5 (Bsz*Stok*DI)
#define Z6 (Bsz*Stok*Dmod)
#define ZTOT (Z1+Z2+Z3+Z4+Z5+Z6)
#define WTOT 1393920
#define XTOT (ML*Dmod)
#define PTOT (Bsz*Stok*Dmod)
#define INIT_TOT (ZTOT + WTOT + XTOT + PTOT)

__global__ void init_kernel(const float* __restrict__ x,
                            const float* __restrict__ Winx, const float* __restrict__ Winz,
                            const float* __restrict__ Wxpf, const float* __restrict__ Wxpb,
                            const float* __restrict__ Wdtf, const float* __restrict__ Wdtb,
                            const float* __restrict__ Wpro, const float* __restrict__ wA,
                            const float* __restrict__ wV,   const float* __restrict__ Wout,
                            const float* __restrict__ bxpf, const float* __restrict__ bxpb,
                            const float* __restrict__ bdtf, const float* __restrict__ bdtb,
                            float* __restrict__ dout)
{
    long long i = (long long)blockIdx.x * 256 + threadIdx.x;
    __nv_bfloat16 h, l;
    if (i < Z1) { g_zpacc[i] = 0.f; return; }  i -= Z1;
    if (i < Z2) { g_dbc[i] = 0.f; return; }    i -= Z2;
    if (i < Z3) { g_scores[i] = 0.f; return; } i -= Z3;
    if (i < Z4) { g_tyacc[i] = 0.f; return; }  i -= Z4;
    if (i < Z5) { g_Tacc[i] = 0.f; return; }   i -= Z5;
    if (i < Z6) { dout[i] = 0.f; return; }     i -= Z6;
    if (i < 131072) { splitv(Winx[i], h, l); g_Winx_h[i] = h; g_Winx_l[i] = l; return; }
    i -= 131072;
    if (i < 131072) { splitv(Winz[i], h, l); g_Winz_h[i] = h; g_Winz_l[i] = l; return; }
    i -= 131072;
    if (i < 131072) { int dir = i >> 16, j = i & 65535;
        int r = j >> 9, c = j & 511;
        const float* W = dir ? Wxpb : Wxpf;
        int sr = wxp_srcrow(r);
        splitv(sr >= 0 ? W[sr * DI + c] : 0.f, h, l);
        g_Wxp_h[i] = h; g_Wxp_l[i] = l; return; }
    i -= 131072;
    if (i < 16384) { int dir = i >> 13, j = i & 8191;
        const float* W = dir ? Wdtb : Wdtf;
        splitv(W[j], h, l); g_Wdt_h[i] = h; g_Wdt_l[i] = l; return; }
    i -= 16384;
    if (i < 524288) { splitv(Wpro[i], h, l); g_Wpro_h[i] = h; g_Wpro_l[i] = l; return; }
    i -= 524288;
    if (i < 65536) { int r = i >> 9, c = i & 511;
        splitv(r < Stok ? wA[r * DI + c] : 0.f, h, l);
        g_wA_h[i] = h; g_wA_l[i] = l; return; }
    i -= 65536;
    if (i < 262144) { splitv(wV[i], h, l); g_wV_h[i] = h; g_wV_l[i] = l; return; }
    i -= 262144;
    if (i < 131072) { splitv(Wout[i], h, l); g_Wout_h[i] = h; g_Wout_l[i] = l; return; }
    i -= 131072;
    if (i < 256) { int dir = i >> 7, r = i & 127;
        const float* bsrc = dir ? bxpb : bxpf;
        int sr = wxp_srcrow(r);
        g_bxp[i] = (sr >= 0) ? bsrc[sr] : 0.f; return; }
    i -= 256;
    if (i < 1024) { int dir = i >> 9, r = i & 511;
        g_bdt[i] = dir ? bdtb[r] : bdtf[r]; return; }
    i -= 1024;
    if (i < XTOT) { splitv(x[i], h, l); g_xh[i] = h; g_xl[i] = l; return; }
    i -= XTOT;
    if (i < PTOT) {   // pooling: xp[b,s,d] = mean_l x[b, l in [s0,e), d]
        int d = (int)(i % Dmod);
        int rest = (int)(i / Dmod);
        int s = rest % Stok;
        int b = rest / Stok;
        int s0 = (s * Lseq) / Stok;
        int e  = ((s + 1) * Lseq + Stok - 1) / Stok;
        float acc = 0.f;
        for (int lq = s0; lq < e; lq++) acc += x[((long long)b * Lseq + lq) * Dmod + d];
        g_xpf[((long long)b * Stok + s) * Dmod + d] = acc / (float)(e - s0);
    }
}

// ---------------- shared helpers ----------------
#define SAS 24

__device__ __forceinline__ uint32_t s2u(const void* p) {
    return (uint32_t)__cvta_generic_to_shared(p);
}
__device__ __forceinline__ void ldsm4(uint32_t r[4], uint32_t addr) {
    asm volatile("ldmatrix.sync.aligned.m8n8.x4.shared.b16 {%0,%1,%2,%3}, [%4];"
                 : "=r"(r[0]), "=r"(r[1]), "=r"(r[2]), "=r"(r[3]) : "r"(addr));
}
__device__ __forceinline__ void mma16816(float c[4], const uint32_t a[4],
                                         uint32_t b0, uint32_t b1) {
    asm volatile(
        "mma.sync.aligned.m16n8k16.row.col.f32.bf16.bf16.f32 "
        "{%0,%1,%2,%3},{%4,%5,%6,%7},{%8,%9},{%0,%1,%2,%3};"
        : "+f"(c[0]), "+f"(c[1]), "+f"(c[2]), "+f"(c[3])
        : "r"(a[0]), "r"(a[1]), "r"(a[2]), "r"(a[3]), "r"(b0), "r"(b1));
}
__device__ __forceinline__ void cpasync16(uint32_t dst, const void* src, int szbytes) {
    asm volatile("cp.async.ca.shared.global [%0], [%1], 16, %2;"
                 :: "r"(dst), "l"(src), "r"(szbytes));
}

// =====================================================================
// hgemm4: C = A * op(B planes), 3-split bf16 MMA (round-6 core).
// AMODE: 0 = plain fp32 A; 1 = A * silu(Ag) elementwise.
// =====================================================================
template<int TB, int AMODE>
__global__ __launch_bounds__(256, 2)
void hgemm4(const float* __restrict__ A, const float* __restrict__ Ag,
            const __nv_bfloat16* __restrict__ Bh, const __nv_bfloat16* __restrict__ Bl,
            const float* __restrict__ bias, const float* __restrict__ emul,
            float* __restrict__ C,
            int M, int N, int K, int lda, int ldb, int ldc, int Nout, int act, int KS,
            long long sA, long long sB, long long sC, long long sBias)
{
    __shared__ __align__(16) __nv_bfloat16 As_hi[128][SAS];
    __shared__ __align__(16) __nv_bfloat16 As_lo[128][SAS];
    __shared__ __align__(16) __nv_bfloat16 Bs_hi[128][SAS];
    __shared__ __align__(16) __nv_bfloat16 Bs_lo[128][SAS];

    int bz  = blockIdx.z;
    int dir = bz / KS;
    int ks  = bz % KS;
    A  += dir * sA;
    Bh += dir * sB; Bl += dir * sB;
    if (bias) bias += dir * sBias;
    int kchunk = K / KS;
    int kb = ks * kchunk, ke = kb + kchunk;

    int tid  = threadIdx.x;
    int lane = tid & 31;
    int wid  = tid >> 5;
    int wm0  = (wid >> 2) * 64;
    int wn0  = (wid & 3) * 32;
    int row0 = blockIdx.y * 128;
    int col0 = blockIdx.x * 128;

    int lr = lane & 15;
    int lc = (lane >> 4) * 8;

    int ar = tid >> 1;
    int ac = (tid & 1) * 8;
    int gm = row0 + ar;
    bool mok = gm < M;
    const float* Ap = A + (long long)gm * lda + ac;
    const float* Gp = (AMODE == 1) ? (Ag + (long long)gm * lda + ac) : nullptr;

    const __nv_bfloat16 *Bph = nullptr, *Bpl = nullptr;
    int bkk = 0, bnc = 0;
    if (TB == 1) {
        Bph = Bh + (long long)(col0 + ar) * ldb + ac;
        Bpl = Bl + (long long)(col0 + ar) * ldb + ac;
    } else {
        bkk = tid >> 4;
        bnc = (tid & 15) * 8;
        Bph = Bh + col0 + bnc;
        Bpl = Bl + col0 + bnc;
    }

    float4 ra0 = make_float4(0,0,0,0), ra1 = make_float4(0,0,0,0);
    float4 rg0 = make_float4(0,0,0,0), rg1 = make_float4(0,0,0,0);
    uint4 rbh, rbl;

    if (mok) {
        ra0 = *(const float4*)(Ap + kb); ra1 = *(const float4*)(Ap + kb + 4);
        if (AMODE == 1) { rg0 = *(const float4*)(Gp + kb); rg1 = *(const float4*)(Gp + kb + 4); }
    }
    if (TB == 1) {
        rbh = *(const uint4*)(Bph + kb); rbl = *(const uint4*)(Bpl + kb);
    } else {
        rbh = *(const uint4*)(Bph + (long long)(kb + bkk) * ldb);
        rbl = *(const uint4*)(Bpl + (long long)(kb + bkk) * ldb);
    }

    float acc[4][4][4];
    #pragma unroll
    for (int i = 0; i < 4; i++)
        #pragma unroll
        for (int j = 0; j < 4; j++)
            #pragma unroll
            for (int q = 0; q < 4; q++) acc[i][j][q] = 0.f;

    for (int k0 = kb; k0 < ke; k0 += 16) {
        {
            float av[8] = {ra0.x, ra0.y, ra0.z, ra0.w, ra1.x, ra1.y, ra1.z, ra1.w};
            if (AMODE == 1) {
                float gv[8] = {rg0.x, rg0.y, rg0.z, rg0.w, rg1.x, rg1.y, rg1.z, rg1.w};
                #pragma unroll
                for (int j = 0; j < 8; j++) av[j] *= gv[j] / (1.f + expf(-gv[j]));
            }
            __nv_bfloat16 hh[8], ll[8];
            #pragma unroll
            for (int j = 0; j < 8; j++) splitv(av[j], hh[j], ll[j]);
            *(uint4*)&As_hi[ar][ac] = *(uint4*)hh;
            *(uint4*)&As_lo[ar][ac] = *(uint4*)ll;
        }
        if (TB == 1) {
            *(uint4*)&Bs_hi[ar][ac] = rbh;
            *(uint4*)&Bs_lo[ar][ac] = rbl;
        } else {
            __nv_bfloat16 th[8], tl[8];
            *(uint4*)th = rbh; *(uint4*)tl = rbl;
            #pragma unroll
            for (int j = 0; j < 8; j++) {
                Bs_hi[bnc + j][bkk] = th[j];
                Bs_lo[bnc + j][bkk] = tl[j];
            }
        }
        __syncthreads();

        if (k0 + 16 < ke) {
            int kn = k0 + 16;
            if (mok) {
                ra0 = *(const float4*)(Ap + kn);
                ra1 = *(const float4*)(Ap + kn + 4);
                if (AMODE == 1) {
                    rg0 = *(const float4*)(Gp + kn);
                    rg1 = *(const float4*)(Gp + kn + 4);
                }
            }
            if (TB == 1) {
                rbh = *(const uint4*)(Bph + kn);
                rbl = *(const uint4*)(Bpl + kn);
            } else {
                rbh = *(const uint4*)(Bph + (long long)(kn + bkk) * ldb);
                rbl = *(const uint4*)(Bpl + (long long)(kn + bkk) * ldb);
            }
        }

        uint32_t bhf[2][4], blf[2][4];
        #pragma unroll
        for (int ng = 0; ng < 2; ng++) {
            ldsm4(bhf[ng], s2u(&Bs_hi[wn0 + ng * 16 + lr][lc]));
            ldsm4(blf[ng], s2u(&Bs_lo[wn0 + ng * 16 + lr][lc]));
        }
        #pragma unroll
        for (int mt = 0; mt < 4; mt++) {
            uint32_t a_h[4], a_l[4];
            ldsm4(a_h, s2u(&As_hi[wm0 + mt * 16 + lr][lc]));
            ldsm4(a_l, s2u(&As_lo[wm0 + mt * 16 + lr][lc]));
            #pragma unroll
            for (int nt = 0; nt < 4; nt++) {
                int ng = nt >> 1, sl = nt & 1;
                mma16816(acc[mt][nt], a_h, bhf[ng][sl], bhf[ng][sl + 2]);
                mma16816(acc[mt][nt], a_h, blf[ng][sl], blf[ng][sl + 2]);
                mma16816(acc[mt][nt], a_l, bhf[ng][sl], bhf[ng][sl + 2]);
            }
        }
        __syncthreads();
    }

    int g = lane >> 2, t4 = lane & 3;
    #pragma unroll
    for (int mt = 0; mt < 4; mt++) {
        #pragma unroll
        for (int nt = 0; nt < 4; nt++) {
            int cb = col0 + wn0 + nt * 8 + 2 * t4;
            if (cb >= Nout) continue;
            float b0 = 0.f, b1 = 0.f;
            if (bias && (KS == 1 || ks == 0)) { b0 = bias[cb]; b1 = bias[cb + 1]; }
            #pragma unroll
            for (int hrow = 0; hrow < 2; hrow++) {
                int m = row0 + wm0 + mt * 16 + g + hrow * 8;
                if (m >= M) continue;
                float v0 = acc[mt][nt][hrow * 2 + 0] + b0;
                float v1 = acc[mt][nt][hrow * 2 + 1] + b1;
                long long co = dir * sC + (long long)m * ldc + cb;
                if (KS > 1) {
                    atomicAdd(C + co, v0);
                    atomicAdd(C + co + 1, v1);
                } else {
                    if (act == 1) {
                        v0 = v0 / (1.f + expf(-v0));
                        v1 = v1 / (1.f + expf(-v1));
                    } else if (act == 2) {
                        v0 = (v0 > 20.f) ? v0 : log1pf(expf(v0));
                        v1 = (v1 > 20.f) ? v1 : log1pf(expf(v1));
                    }
                    if (emul) { v0 *= emul[co]; v1 *= emul[co + 1]; }
                    *(float2*)(C + co) = make_float2(v0, v1);
                }
            }
        }
    }
}

// =====================================================================
// hgemm_ca: big-GEMM specialist (xi, ycat).
// =====================================================================
#define CA_PL  (128*SAS)
#define CA_STG (4*CA_PL)
#define CA_SMEM_BYTES (3*CA_STG*2)

__global__ __launch_bounds__(256, 2)
void hgemm_ca(const __nv_bfloat16* __restrict__ Ah, const __nv_bfloat16* __restrict__ Al,
              const __nv_bfloat16* __restrict__ Bh, const __nv_bfloat16* __restrict__ Bl,
              const float* __restrict__ bias, float* __restrict__ C,
              int M, int N, int K, int lda, int ldb, int ldc)
{
    extern __shared__ __align__(16) __nv_bfloat16 sm[];
    uint32_t smb = s2u(sm);

    int tid  = threadIdx.x;
    int lane = tid & 31;
    int wid  = tid >> 5;
    int wm0  = (wid >> 2) * 64;
    int wn0  = (wid & 3) * 32;
    int row0 = blockIdx.y * 128;
    int col0 = blockIdx.x * 128;

    int lr = lane & 15;
    int lc = (lane >> 4) * 8;

    int ar = tid >> 1;
    int ac = (tid & 1) * 8;
    int gm = row0 + ar;
    int asz = (gm < M) ? 16 : 0;
    const __nv_bfloat16* Aph = Ah + (long long)gm * lda + ac;
    const __nv_bfloat16* Apl = Al + (long long)gm * lda + ac;
    const __nv_bfloat16* Bph = Bh + (long long)(col0 + ar) * ldb + ac;
    const __nv_bfloat16* Bpl = Bl + (long long)(col0 + ar) * ldb + ac;

    uint32_t offA_h = (uint32_t)(0 * CA_PL + ar * SAS + ac) * 2;
    uint32_t offA_l = (uint32_t)(1 * CA_PL + ar * SAS + ac) * 2;
    uint32_t offB_h = (uint32_t)(2 * CA_PL + ar * SAS + ac) * 2;
    uint32_t offB_l = (uint32_t)(3 * CA_PL + ar * SAS + ac) * 2;

    float acc[4][4][4];
    #pragma unroll
    for (int i = 0; i < 4; i++)
        #pragma unroll
        for (int j = 0; j < 4; j++)
            #pragma unroll
            for (int q = 0; q < 4; q++) acc[i][j][q] = 0.f;

    {
        uint32_t sb = smb;
        cpasync16(sb + offA_h, Aph + 0, asz);
        cpasync16(sb + offA_l, Apl + 0, asz);
        cpasync16(sb + offB_h, Bph + 0, 16);
        cpasync16(sb + offB_l, Bpl + 0, 16);
        asm volatile("cp.async.commit_group;" ::: "memory");
    }
    if (16 < K) {
        uint32_t sb = smb + CA_STG * 2;
        cpasync16(sb + offA_h, Aph + 16, asz);
        cpasync16(sb + offA_l, Apl + 16, asz);
        cpasync16(sb + offB_h, Bph + 16, 16);
        cpasync16(sb + offB_l, Bpl + 16, 16);
        asm volatile("cp.async.commit_group;" ::: "memory");
    } else {
        asm volatile("cp.async.commit_group;" ::: "memory");
    }

    int cur = 0;
    for (int k0 = 0; k0 < K; k0 += 16) {
        asm volatile("cp.async.wait_group 1;" ::: "memory");
        __syncthreads();

        uint32_t sb = smb + (uint32_t)cur * (CA_STG * 2);

        uint32_t bhf[2][4], blf[2][4];
        #pragma unroll
        for (int ng = 0; ng < 2; ng++) {
            uint32_t rb = (uint32_t)(wn0 + ng * 16 + lr) * SAS + lc;
            ldsm4(bhf[ng], sb + (uint32_t)(2 * CA_PL) * 2 + rb * 2);
            ldsm4(blf[ng], sb + (uint32_t)(3 * CA_PL) * 2 + rb * 2);
        }
        #pragma unroll
        for (int mt = 0; mt < 4; mt++) {
            uint32_t raddr = (uint32_t)(wm0 + mt * 16 + lr) * SAS + lc;
            uint32_t a_h[4], a_l[4];
            ldsm4(a_h, sb + raddr * 2);
            ldsm4(a_l, sb + (uint32_t)(CA_PL) * 2 + raddr * 2);
            #pragma unroll
            for (int nt = 0; nt < 4; nt++) {
                int ng = nt >> 1, sl = nt & 1;
                mma16816(acc[mt][nt], a_h, bhf[ng][sl], bhf[ng][sl + 2]);
                mma16816(acc[mt][nt], a_h, blf[ng][sl], blf[ng][sl + 2]);
                mma16816(acc[mt][nt], a_l, bhf[ng][sl], bhf[ng][sl + 2]);
            }
        }

        int nk = k0 + 32;
        if (nk < K) {
            int nst = cur + 2; if (nst >= 3) nst -= 3;
            uint32_t nb = smb + (uint32_t)nst * (CA_STG * 2);
            cpasync16(nb + offA_h, Aph + nk, asz);
            cpasync16(nb + offA_l, Apl + nk, asz);
            cpasync16(nb + offB_h, Bph + nk, 16);
            cpasync16(nb + offB_l, Bpl + nk, 16);
        }
        asm volatile("cp.async.commit_group;" ::: "memory");

        cur++; if (cur == 3) cur = 0;
    }

    int g = lane >> 2, t4 = lane & 3;
    #pragma unroll
    for (int mt = 0; mt < 4; mt++) {
        #pragma unroll
        for (int nt = 0; nt < 4; nt++) {
            int cb = col0 + wn0 + nt * 8 + 2 * t4;
            float b0 = 0.f, b1 = 0.f;
            if (bias) { b0 = bias[cb]; b1 = bias[cb + 1]; }
            #pragma unroll
            for (int hrow = 0; hrow < 2; hrow++) {
                int m = row0 + wm0 + mt * 16 + g + hrow * 8;
                if (m >= M) continue;
                float v0 = acc[mt][nt][hrow * 2 + 0] + b0;
                float v1 = acc[mt][nt][hrow * 2 + 1] + b1;
                *(float2*)(C + (long long)m * ldc + cb) = make_float2(v0, v1);
            }
        }
    }
}

// ---------------- depthwise conv + SiLU, t-tiled (CT steps/block), both dirs ----------------
__global__ void conv_silu2_kernel(const float* __restrict__ xi,
                                  const float* __restrict__ wf, const float* __restrict__ bf,
                                  const float* __restrict__ wb, const float* __restrict__ bb)
{
    int t0 = blockIdx.x * CT;
    int b = blockIdx.y;
    int back = blockIdx.z;
    int c = threadIdx.x;
    const float* w  = back ? wb : wf;
    float bias      = back ? bb[c] : bf[c];
    float* out      = g_u + (long long)back * SZ_U;

    float w0 = w[c * 4 + 0], w1 = w[c * 4 + 1], w2 = w[c * 4 + 2], w3 = w[c * 4 + 3];

    float xv[CT + 3];
    #pragma unroll
    for (int j = 0; j < CT + 3; j++) {
        int i = t0 + j - 3;
        float v = 0.f;
        if (i >= 0 && i < LB) {
            int l = back ? (Lseq - 1 - i) : i;
            v = xi[((long long)b * Lseq + l) * DI + c];
        }
        xv[j] = v;
    }
    #pragma unroll
    for (int j = 0; j < CT; j++) {
        int t = t0 + j;
        if (t >= LC) break;
        float acc = bias;
        acc = fmaf(w0, xv[j],     acc);
        acc = fmaf(w1, xv[j + 1], acc);
        acc = fmaf(w2, xv[j + 2], acc);
        acc = fmaf(w3, xv[j + 3], acc);
        out[((long long)b * LC + t) * DI + c] = acc / (1.f + expf(-acc));
    }
}

// ---------------- selective scans: 16 lanes/channel, float2 B/C ----------------
__global__ __launch_bounds__(256)
void scan2_kernel(const float* __restrict__ A_log_f, const float* __restrict__ D_f,
                  const float* __restrict__ A_log_b, const float* __restrict__ D_b)
{
    int back = blockIdx.y;
    const float* u     = g_u     + (long long)back * SZ_U;
    const float* delta = g_delta + (long long)back * SZ_U;
    const float* dbc   = g_dbc   + (long long)back * SZ_DBC;
    const float* A_log = back ? A_log_b : A_log_f;
    const float* Dp    = back ? D_b : D_f;
    float* y           = g_ysc   + (long long)back * SZ_U;

    int gid = blockIdx.x * 16 + (threadIdx.x >> 4);
    int s = threadIdx.x & 15;
    int b = gid >> 9;
    int d = gid & 511;
    float Av = -expf(A_log[d * 16 + s]);
    float Dd = Dp[d];
    float h = 0.f;
    const float* db = dbc + (long long)b * LC * NXP + 16 + 2 * s;  // interleaved B,C
    const float* dl = delta + ((long long)b * LC) * DI + d;
    const float* uu = u     + ((long long)b * LC) * DI + d;
    float*       yy = y     + ((long long)b * LC) * DI + d;
    #pragma unroll 4
    for (int t = 0; t < LC; t++) {
        float de = __ldg(dl + (long long)t * DI);
        float uv = __ldg(uu + (long long)t * DI);
        float2 bc = __ldg((const float2*)(db + t * NXP));
        float dA = __expf(de * Av);
        h = fmaf(dA, h, de * uv * bc.x);
        float v = h * bc.y;
        v += __shfl_xor_sync(0xffffffffu, v, 8);
        v += __shfl_xor_sync(0xffffffffu, v, 4);
        v += __shfl_xor_sync(0xffffffffu, v, 2);
        v += __shfl_xor_sync(0xffffffffu, v, 1);
        if (s == 0) yy[(long long)t * DI] = fmaf(Dd, uv, v);
    }
}

// ---------------- gaussian masks ----------------
__global__ void dist2_kernel(int ref)
{
    int back = blockIdx.z;
    const float* y = g_ysc + (long long)back * SZ_U;
    float* dist = g_dist + back * (Bsz * LC);
    int b = blockIdx.y;
    int t = blockIdx.x * 8 + (threadIdx.x >> 5);
    int lane = threadIdx.x & 31;
    if (t >= LC) return;
    const float* yt = y + ((long long)b * LC + t) * DI;
    const float* yr = y + ((long long)b * LC + ref) * DI;
    float acc = 0.f;
    for (int d = lane; d < DI; d += 32) {
        float df = yt[d] - yr[d];
        acc = fmaf(df, df, acc);
    }
    #pragma unroll
    for (int o = 16; o; o >>= 1) acc += __shfl_xor_sync(0xffffffffu, acc, o);
    if (lane == 0) dist[b * LC + t] = sqrtf(fmaxf(acc, 1e-12f));
}

__global__ void dist_kernel(const float* __restrict__ y, float* __restrict__ dist, int ref)
{
    int b = blockIdx.y;
    int t = blockIdx.x * 8 + (threadIdx.x >> 5);
    int lane = threadIdx.x & 31;
    if (t >= LC) return;
    const float* yt = y + ((long long)b * LC + t) * DI;
    const float* yr = y + ((long long)b * LC + ref) * DI;
    float acc = 0.f;
    for (int d = lane; d < DI; d += 32) {
        float df = yt[d] - yr[d];
        acc = fmaf(df, df, acc);
    }
    #pragma unroll
    for (int o = 16; o; o >>= 1) acc += __shfl_xor_sync(0xffffffffu, acc, o);
    if (lane == 0) dist[b * LC + t] = sqrtf(fmaxf(acc, 1e-12f));
}

__device__ __forceinline__ void maskfin_body(const float* dist, float* m, int ref,
                                             float* red, int tid)
{
    float s = 0.f;
    for (int t = tid; t < LC; t += 512) s += dist[t];
    red[tid] = s; __syncthreads();
    for (int o = 256; o; o >>= 1) { if (tid < o) red[tid] += red[tid + o]; __syncthreads(); }
    float sigv = red[0] / (float)LC;
    __syncthreads();
    float si = ((float)ref * (float)(ref + 1) * 0.5f +
                (float)(LC - 1 - ref) * (float)(LC - ref) * 0.5f) / (float)LC;
    float c_i = 0.5f / (si * si);
    float c_v = 0.5f / (sigv * sigv);
    float nrm = 0.f;
    for (int t = tid; t < LC; t += 512) {
        float dt = (float)(t - ref);
        float dv = dist[t];
        float p = expf(-dt * dt * c_i - dv * dv * c_v);
        m[t] = p;
        nrm = fmaf(p, p, nrm);
    }
    red[tid] = nrm; __syncthreads();
    for (int o = 256; o; o >>= 1) { if (tid < o) red[tid] += red[tid + o]; __syncthreads(); }
    float inv = 1.f / fmaxf(sqrtf(red[0]), 1e-12f);
    __syncthreads();
    for (int t = tid; t < LC; t += 512) m[t] *= inv;
}

__global__ void maskfin2_kernel(int ref)
{
    __shared__ float red[512];
    int back = blockIdx.y;
    int b = blockIdx.x;
    const float* dist = g_dist + back * (Bsz * LC) + b * LC;
    float* m = (back ? g_mb : g_mf) + b * LC;
    maskfin_body(dist, m, ref, red, threadIdx.x);
}

__global__ void maskfin_kernel(const float* __restrict__ dist, float* __restrict__ m, int ref)
{
    __shared__ float red[512];
    int b = blockIdx.x;
    maskfin_body(dist + b * LC, m + b * LC, ref, red, threadIdx.x);
}

// ycat = [ y_f * m_f , y_b * reverse(m_b) ]  -> bf16 split planes
__global__ void concat_kernel()
{
    int t = blockIdx.x, b = blockIdx.y, c = threadIdx.x;
    long long r = (long long)b * LC + t;
    float v0 = g_ysc[r * DI + c] * g_mf[b * LC + t];
    float v1 = g_ysc[SZ_U + r * DI + c] * g_mb[b * LC + (LC - 1 - t)];
    __nv_bfloat16 h, l;
    splitv(v0, h, l);
    g_ycath[r * (2 * DI) + c] = h;      g_ycatl[r * (2 * DI) + c] = l;
    splitv(v1, h, l);
    g_ycath[r * (2 * DI) + DI + c] = h; g_ycatl[r * (2 * DI) + DI + c] = l;
}

// y *= mc (in place) + bf16 split planes
__global__ void scale_y_kernel()
{
    int t = blockIdx.x, b = blockIdx.y, c = threadIdx.x;
    long long r = (long long)b * LC + t;
    float v = g_y[r * DI + c] * g_mc[b * LC + t];
    g_y[r * DI + c] = v;
    __nv_bfloat16 h, l; splitv(v, h, l);
    g_yh[r * DI + c] = h; g_yl[r * DI + c] = l;
}

// softmax over l per (b, token): fp32 Atok (B, Stok, LCP), pad zeroed
__global__ void softmax_kernel()
{
    __shared__ float sv[LC];
    __shared__ float red[256];
    int tt = blockIdx.x, b = blockIdx.y, tid = threadIdx.x;
    float mx = -1e30f;
    for (int l = tid; l < LC; l += 256) {
        float v = g_scores[((long long)b * LC + l) * Stok + tt];
        sv[l] = v; mx = fmaxf(mx, v);
    }
    red[tid] = mx; __syncthreads();
    for (int o = 128; o; o >>= 1) { if (tid < o) red[tid] = fmaxf(red[tid], red[tid + o]); __syncthreads(); }
    mx = red[0]; __syncthreads();
    float sum = 0.f;
    for (int l = tid; l < LC; l += 256) { float e = expf(sv[l] - mx); sv[l] = e; sum += e; }
    red[tid] = sum; __syncthreads();
    for (int o = 128; o; o >>= 1) { if (tid < o) red[tid] += red[tid + o]; __syncthreads(); }
    float inv = 1.f / red[0]; __syncthreads();
    long long base = ((long long)b * Stok + tt) * LCP;
    for (int l = tid; l < LC; l += 256) g_atok[base + l] = sv[l] * inv;
    if (tid < LCP - LC) g_atok[base + LC + tid] = 0.f;
}

// ---------------- host launcher ----------------
static inline int ceildiv(int a, int b) { return (a + b - 1) / b; }

extern "C" void kernel_launch(void* const* d_in, const int* in_sizes, int n_in,
                              void* d_out, int out_size)
{
    const float* x        = (const float*)d_in[0];
    const float* W_in_x   = (const float*)d_in[1];
    const float* W_in_z   = (const float*)d_in[2];
    const float* conv_w_f = (const float*)d_in[3];
    const float* conv_b_f = (const float*)d_in[4];
    const float* conv_w_b = (const float*)d_in[5];
    const float* conv_b_b = (const float*)d_in[6];
    const float* W_xp_f   = (const float*)d_in[7];
    const float* b_xp_f   = (const float*)d_in[8];
    const float* W_dt_f   = (const float*)d_in[9];
    const float* b_dt_f   = (const float*)d_in[10];
    const float* A_log_f  = (const float*)d_in[11];
    const float* D_f      = (const float*)d_in[12];
    const float* W_xp_b   = (const float*)d_in[13];
    const float* b_xp_b   = (const float*)d_in[14];
    const float* W_dt_b   = (const float*)d_in[15];
    const float* b_dt_b   = (const float*)d_in[16];
    const float* A_log_b  = (const float*)d_in[17];
    const float* D_b      = (const float*)d_in[18];
    const float* W_pro_to = (const float*)d_in[19];
    const float* b_pro_to = (const float*)d_in[20];
    const float* token_wA = (const float*)d_in[21];
    const float* token_wV = (const float*)d_in[22];
    const float* W_out    = (const float*)d_in[23];
    float* out = (float*)d_out;

    // one-time side stream + fork/join events (created on the first,
    // non-captured correctness call; per-call work is identical thereafter)
    static cudaStream_t s_side = nullptr;
    static cudaEvent_t  s_fork = nullptr, s_join = nullptr;
    if (s_side == nullptr) {
        cudaStreamCreateWithFlags(&s_side, cudaStreamNonBlocking);
        cudaEventCreateWithFlags(&s_fork, cudaEventDisableTiming);
        cudaEventCreateWithFlags(&s_join, cudaEventDisableTiming);
    }

    float *xi, *u, *dbc, *delta, *yy, *mc, *dist, *xpf, *zpacc;
    float *scores, *atok, *tyacc, *Tacc, *bxp, *bdt;
    cudaGetSymbolAddress((void**)&xi,    g_xi);
    cudaGetSymbolAddress((void**)&u,     g_u);
    cudaGetSymbolAddress((void**)&dbc,   g_dbc);
    cudaGetSymbolAddress((void**)&delta, g_delta);
    cudaGetSymbolAddress((void**)&yy,    g_y);
    cudaGetSymbolAddress((void**)&mc,    g_mc);
    cudaGetSymbolAddress((void**)&dist,  g_dist);
    cudaGetSymbolAddress((void**)&xpf,   g_xpf);
    cudaGetSymbolAddress((void**)&zpacc, g_zpacc);
    cudaGetSymbolAddress((void**)&scores, g_scores);
    cudaGetSymbolAddress((void**)&atok,  g_atok);
    cudaGetSymbolAddress((void**)&tyacc, g_tyacc);
    cudaGetSymbolAddress((void**)&Tacc,  g_Tacc);
    cudaGetSymbolAddress((void**)&bxp,   g_bxp);
    cudaGetSymbolAddress((void**)&bdt,   g_bdt);

    __nv_bfloat16 *xh,*xl,*Winxh,*Winxl,*Winzh,*Winzl,*Wxph,*Wxpl,*Wdth,*Wdtl;
    __nv_bfloat16 *Wproh,*Wprol,*wAh,*wAl,*wVh,*wVl,*Wouth,*Woutl;
    __nv_bfloat16 *ycath,*ycatl,*yh2,*yl2;
    cudaGetSymbolAddress((void**)&xh, g_xh);         cudaGetSymbolAddress((void**)&xl, g_xl);
    cudaGetSymbolAddress((void**)&Winxh, g_Winx_h);  cudaGetSymbolAddress((void**)&Winxl, g_Winx_l);
    cudaGetSymbolAddress((void**)&Winzh, g_Winz_h);  cudaGetSymbolAddress((void**)&Winzl, g_Winz_l);
    cudaGetSymbolAddress((void**)&Wxph, g_Wxp_h);    cudaGetSymbolAddress((void**)&Wxpl, g_Wxp_l);
    cudaGetSymbolAddress((void**)&Wdth, g_Wdt_h);    cudaGetSymbolAddress((void**)&Wdtl, g_Wdt_l);
    cudaGetSymbolAddress((void**)&Wproh, g_Wpro_h);  cudaGetSymbolAddress((void**)&Wprol, g_Wpro_l);
    cudaGetSymbolAddress((void**)&wAh, g_wA_h);      cudaGetSymbolAddress((void**)&wAl, g_wA_l);
    cudaGetSymbolAddress((void**)&wVh, g_wV_h);      cudaGetSymbolAddress((void**)&wVl, g_wV_l);
    cudaGetSymbolAddress((void**)&Wouth, g_Wout_h);  cudaGetSymbolAddress((void**)&Woutl, g_Wout_l);
    cudaGetSymbolAddress((void**)&ycath, g_ycath);   cudaGetSymbolAddress((void**)&ycatl, g_ycatl);
    cudaGetSymbolAddress((void**)&yh2, g_yh);        cudaGetSymbolAddress((void**)&yl2, g_yl);

    cudaFuncSetAttribute(hgemm_ca, cudaFuncAttributeMaxDynamicSharedMemorySize, CA_SMEM_BYTES);

    // 0) fused init: zero accums + weight splits (Wxp permuted) + x split + pooling
    init_kernel<<<ceildiv(INIT_TOT, 256), 256>>>(
        x, W_in_x, W_in_z, W_xp_f, W_xp_b, W_dt_f, W_dt_b, W_pro_to,
        token_wA, token_wV, W_out, b_xp_f, b_xp_b, b_dt_f, b_dt_b, out);

    // fork: zp GEMM runs on the side stream, off the critical path
    cudaEventRecord(s_fork, 0);
    cudaStreamWaitEvent(s_side, s_fork, 0);

    // 2) zpacc = xp @ W_in_z^T (split-K4; silu applied in gated out-GEMM) [side stream]
    hgemm4<1,0><<<dim3(DI / 128, 4, 4), 256, 0, s_side>>>(
        xpf, nullptr, Winzh, Winzl, nullptr, nullptr, zpacc,
        Bsz * Stok, DI, Dmod, Dmod, Dmod, DI, DI, 0, 4, 0, 0, 0, 0);
    cudaEventRecord(s_join, s_side);

    // 1) xi = x @ W_in_x^T  (cp.async pipeline, pre-split planes)
    hgemm_ca<<<dim3(DI / 128, ceildiv(ML, 128)), 256, CA_SMEM_BYTES>>>(
        xh, xl, Winxh, Winxl, nullptr, xi, ML, DI, Dmod, Dmod, Dmod, DI);

    // 3) conv + silu (both dirs, t-tiled CT=16)
    conv_silu2_kernel<<<dim3(ceildiv(LC, CT), Bsz, 2), DI>>>(
        xi, conv_w_f, conv_b_f, conv_w_b, conv_b_b);

    // 4) dbc = u @ W_xp^T + b  (merged dirs, split-K2, atomic; cols permuted)
    hgemm4<1,0><<<dim3(1, ceildiv(MC, 128), 4), 256>>>(
        u, nullptr, Wxph, Wxpl, bxp, nullptr, dbc,
        MC, 128, DI, DI, DI, NXP, NXP, 0, 2,
        (long long)SZ_U, (long long)128 * DI, (long long)SZ_DBC, 128);

    // 5) delta = softplus(dr @ W_dt^T + b_dt)  (merged dirs, K=16)
    hgemm4<1,0><<<dim3(DI / 128, ceildiv(MC, 128), 2), 256>>>(
        dbc, nullptr, Wdth, Wdtl, bdt, nullptr, delta,
        MC, DI, DRK, NXP, DRK, DI, DI, 2, 1,
        (long long)SZ_DBC, (long long)DI * DRK, (long long)SZ_U, DI);

    // 6) selective scans (both dirs, 16 lanes/channel, float2 B/C)
    scan2_kernel<<<dim3(Bsz * DI / 16, 2), 256>>>(A_log_f, D_f, A_log_b, D_b);

    // 7) masks ('last'), both dirs
    dist2_kernel<<<dim3(ceildiv(LC, 8), Bsz, 2), 256>>>(LC - 1);
    maskfin2_kernel<<<dim3(Bsz, 2), 512>>>(LC - 1);

    // 8) ycat planes; y = ycat @ W_pro^T + b (cp.async pipeline)
    concat_kernel<<<dim3(LC, Bsz), DI>>>();
    hgemm_ca<<<dim3(DI / 128, ceildiv(MC, 128)), 256, CA_SMEM_BYTES>>>(
        ycath, ycatl, Wproh, Wprol, b_pro_to, yy, MC, DI, 2 * DI, 2 * DI, 2 * DI, DI);

    // 9) center mask; scale y + split planes
    dist_kernel<<<dim3(ceildiv(LC, 8), Bsz), 256>>>(yy, dist, (LC + 1) / 2);
    maskfin_kernel<<<Bsz, 512>>>(dist, mc, (LC + 1) / 2);
    scale_y_kernel<<<dim3(LC, Bsz), DI>>>();

    // 10) scores = y @ wA^T (split-K2, atomic); softmax -> Atok
    hgemm4<1,0><<<dim3(1, ceildiv(MC, 128), 2), 256>>>(
        yy, nullptr, wAh, wAl, nullptr, nullptr, scores,
        MC, 128, DI, DI, DI, Stok, Stok, 0, 2, 0, 0, 0, 0);
    softmax_kernel<<<dim3(Stok, Bsz), 256>>>();

    // 11) Ty = Atok @ y  (TB=0, batched over b, split-K5, atomic)
    hgemm4<0,0><<<dim3(DI / 128, 1, Bsz * 5), 256>>>(
        atok, nullptr, yh2, yl2, nullptr, nullptr, tyacc,
        Stok, DI, LCP, LCP, DI, DI, DI, 0, 5,
        (long long)Stok * LCP, (long long)LC * DI, (long long)Stok * DI, 0);

    // 12) Tacc = Ty @ wV  (TB=0, batched, split-K4, atomic)
    hgemm4<0,0><<<dim3(DI / 128, 1, Bsz * 4), 256>>>(
        tyacc, nullptr, wVh, wVl, nullptr, nullptr, Tacc,
        Stok, DI, DI, DI, DI, DI, DI, 0, 4,
        (long long)Stok * DI, 0, (long long)Stok * DI, 0);

    // join: zpacc must be complete before the gated out-GEMM
    cudaStreamWaitEvent(0, s_join, 0);

    // 13) out = (Tacc * silu(zpacc)) @ W_out^T  (gated A, split-K4, atomic)
    hgemm4<1,1><<<dim3(Dmod / 128, 4, 4), 256>>>(
        Tacc, zpacc, Wouth, Woutl, nullptr, nullptr, out,
        Bsz * Stok, Dmod, DI, DI, DI, Dmod, Dmod, 0, 4, 0, 0, 0, 0);
}

// round 17
// speedup vs baseline: 1.3614x; 1.0300x over previous
#include <cuda_runtime.h>
#include <cuda_bf16.h>
#include <math.h>
#include <stdint.h>

// ---------------- problem constants ----------------
#define Bsz  8
#define Lseq 2049
#define Dmod 256
#define DI   512
#define DS   16
#define DRK  16
#define LB   1025
#define LC   1028
#define Stok 64
#define NXP  48
#define LCP  1040   // LC padded to 16
#define CT   16     // conv timesteps per block

#define SZ_U    (Bsz*LC*DI)
#define SZ_DBC  (Bsz*LC*NXP)
#define ML      (Bsz*Lseq)
#define MC      (Bsz*LC)

// ---------------- fp32 scratch ----------------
__device__ float g_xi[Bsz*Lseq*DI];
__device__ float g_u[2*SZ_U];          // f, b
__device__ float g_dbc[2*SZ_DBC];      // f, b (atomic accum; B/C interleaved cols)
__device__ float g_delta[2*SZ_U];
__device__ float g_ysc[2*SZ_U];        // scan outputs f, b
__device__ float g_y[Bsz*LC*DI];       // raw y (pre center-mask)
__device__ float g_mf[Bsz*LC];
__device__ float g_mb[Bsz*LC];
__device__ float g_mc[Bsz*LC];
__device__ float g_dist[Bsz*LC*2];
__device__ float g_xpf[Bsz*Stok*Dmod];
__device__ float g_zpacc[Bsz*Stok*DI];     // atomic accum (pre-silu)
__device__ float g_scores[Bsz*LC*Stok];    // atomic accum (raw y scores)
__device__ float g_atok[Bsz*Stok*LCP];     // softmax * mc folded in
__device__ float g_tyacc[Bsz*Stok*DI];     // atomic accum
__device__ float g_Tacc[Bsz*Stok*DI];      // atomic accum (pre-gate)
__device__ float g_bxp[2*128];
__device__ float g_bdt[2*DI];

// ---------------- bf16 planes ----------------
__device__ __nv_bfloat16 g_xh[ML*Dmod],       g_xl[ML*Dmod];          // x pre-split
__device__ __nv_bfloat16 g_Winx_h[DI*Dmod],   g_Winx_l[DI*Dmod];
__device__ __nv_bfloat16 g_Winz_h[DI*Dmod],   g_Winz_l[DI*Dmod];
__device__ __nv_bfloat16 g_Wxp_h[2*128*DI],   g_Wxp_l[2*128*DI];      // rows permuted (B/C interleave)
__device__ __nv_bfloat16 g_Wdt_h[2*DI*DRK],   g_Wdt_l[2*DI*DRK];
__device__ __nv_bfloat16 g_Wpro_h[DI*2*DI],   g_Wpro_l[DI*2*DI];
__device__ __nv_bfloat16 g_wA_h[128*DI],      g_wA_l[128*DI];
__device__ __nv_bfloat16 g_wV_h[DI*DI],       g_wV_l[DI*DI];
__device__ __nv_bfloat16 g_Wout_h[Dmod*DI],   g_Wout_l[Dmod*DI];
__device__ __nv_bfloat16 g_ycath[Bsz*LC*2*DI], g_ycatl[Bsz*LC*2*DI];  // concat output
__device__ __nv_bfloat16 g_yh[Bsz*LC*DI+16*DI], g_yl[Bsz*LC*DI+16*DI]; // raw y planes; slack rows stay 0

__device__ __forceinline__ void splitv(float v, __nv_bfloat16& h, __nv_bfloat16& l) {
    h = __float2bfloat16(v);
    l = __float2bfloat16(v - __bfloat162float(h));
}

// dbc column permutation: rows 0-15 identity (dr); output row 16+2j <- B_j (src 16+j);
// output row 17+2j <- C_j (src 32+j); rows >= 48 zero.
__device__ __forceinline__ int wxp_srcrow(int r) {
    if (r < 16) return r;
    if (r >= 48) return -1;
    int q = r - 16;
    return (q & 1) ? (32 + (q >> 1)) : (16 + (q >> 1));
}

// ---------------- fused init: zero accums + weight splits + x split + pool ----------------
#define Z1 (Bsz*Stok*DI)
#define Z2 (2*SZ_DBC)
#define Z3 (Bsz*LC*Stok)
#define Z4 (Bsz*Stok*DI)
#define Z5 (Bsz*Stok*DI)
#define Z6 (Bsz*Stok*Dmod)
#define ZTOT (Z1+Z2+Z3+Z4+Z5+Z6)
#define WTOT 1393920
#define XTOT (ML*Dmod)
#define PTOT (Bsz*Stok*Dmod)
#define INIT_TOT (ZTOT + WTOT + XTOT + PTOT)

__global__ void init_kernel(const float* __restrict__ x,
                            const float* __restrict__ Winx, const float* __restrict__ Winz,
                            const float* __restrict__ Wxpf, const float* __restrict__ Wxpb,
                            const float* __restrict__ Wdtf, const float* __restrict__ Wdtb,
                            const float* __restrict__ Wpro, const float* __restrict__ wA,
                            const float* __restrict__ wV,   const float* __restrict__ Wout,
                            const float* __restrict__ bxpf, const float* __restrict__ bxpb,
                            const float* __restrict__ bdtf, const float* __restrict__ bdtb,
                            float* __restrict__ dout)
{
    long long i = (long long)blockIdx.x * 256 + threadIdx.x;
    __nv_bfloat16 h, l;
    if (i < Z1) { g_zpacc[i] = 0.f; return; }  i -= Z1;
    if (i < Z2) { g_dbc[i] = 0.f; return; }    i -= Z2;
    if (i < Z3) { g_scores[i] = 0.f; return; } i -= Z3;
    if (i < Z4) { g_tyacc[i] = 0.f; return; }  i -= Z4;
    if (i < Z5) { g_Tacc[i] = 0.f; return; }   i -= Z5;
    if (i < Z6) { dout[i] = 0.f; return; }     i -= Z6;
    if (i < 131072) { splitv(Winx[i], h, l); g_Winx_h[i] = h; g_Winx_l[i] = l; return; }
    i -= 131072;
    if (i < 131072) { splitv(Winz[i], h, l); g_Winz_h[i] = h; g_Winz_l[i] = l; return; }
    i -= 131072;
    if (i < 131072) { int dir = i >> 16, j = i & 65535;
        int r = j >> 9, c = j & 511;
        const float* W = dir ? Wxpb : Wxpf;
        int sr = wxp_srcrow(r);
        splitv(sr >= 0 ? W[sr * DI + c] : 0.f, h, l);
        g_Wxp_h[i] = h; g_Wxp_l[i] = l; return; }
    i -= 131072;
    if (i < 16384) { int dir = i >> 13, j = i & 8191;
        const float* W = dir ? Wdtb : Wdtf;
        splitv(W[j], h, l); g_Wdt_h[i] = h; g_Wdt_l[i] = l; return; }
    i -= 16384;
    if (i < 524288) { splitv(Wpro[i], h, l); g_Wpro_h[i] = h; g_Wpro_l[i] = l; return; }
    i -= 524288;
    if (i < 65536) { int r = i >> 9, c = i & 511;
        splitv(r < Stok ? wA[r * DI + c] : 0.f, h, l);
        g_wA_h[i] = h; g_wA_l[i] = l; return; }
    i -= 65536;
    if (i < 262144) { splitv(wV[i], h, l); g_wV_h[i] = h; g_wV_l[i] = l; return; }
    i -= 262144;
    if (i < 131072) { splitv(Wout[i], h, l); g_Wout_h[i] = h; g_Wout_l[i] = l; return; }
    i -= 131072;
    if (i < 256) { int dir = i >> 7, r = i & 127;
        const float* bsrc = dir ? bxpb : bxpf;
        int sr = wxp_srcrow(r);
        g_bxp[i] = (sr >= 0) ? bsrc[sr] : 0.f; return; }
    i -= 256;
    if (i < 1024) { int dir = i >> 9, r = i & 511;
        g_bdt[i] = dir ? bdtb[r] : bdtf[r]; return; }
    i -= 1024;
    if (i < XTOT) { splitv(x[i], h, l); g_xh[i] = h; g_xl[i] = l; return; }
    i -= XTOT;
    if (i < PTOT) {   // pooling: xp[b,s,d] = mean_l x[b, l in [s0,e), d]
        int d = (int)(i % Dmod);
        int rest = (int)(i / Dmod);
        int s = rest % Stok;
        int b = rest / Stok;
        int s0 = (s * Lseq) / Stok;
        int e  = ((s + 1) * Lseq + Stok - 1) / Stok;
        float acc = 0.f;
        for (int lq = s0; lq < e; lq++) acc += x[((long long)b * Lseq + lq) * Dmod + d];
        g_xpf[((long long)b * Stok + s) * Dmod + d] = acc / (float)(e - s0);
    }
}

// ---------------- shared helpers ----------------
#define SAS 24

__device__ __forceinline__ uint32_t s2u(const void* p) {
    return (uint32_t)__cvta_generic_to_shared(p);
}
__device__ __forceinline__ void ldsm4(uint32_t r[4], uint32_t addr) {
    asm volatile("ldmatrix.sync.aligned.m8n8.x4.shared.b16 {%0,%1,%2,%3}, [%4];"
                 : "=r"(r[0]), "=r"(r[1]), "=r"(r[2]), "=r"(r[3]) : "r"(addr));
}
__device__ __forceinline__ void mma16816(float c[4], const uint32_t a[4],
                                         uint32_t b0, uint32_t b1) {
    asm volatile(
        "mma.sync.aligned.m16n8k16.row.col.f32.bf16.bf16.f32 "
        "{%0,%1,%2,%3},{%4,%5,%6,%7},{%8,%9},{%0,%1,%2,%3};"
        : "+f"(c[0]), "+f"(c[1]), "+f"(c[2]), "+f"(c[3])
        : "r"(a[0]), "r"(a[1]), "r"(a[2]), "r"(a[3]), "r"(b0), "r"(b1));
}
__device__ __forceinline__ void cpasync16(uint32_t dst, const void* src, int szbytes) {
    asm volatile("cp.async.ca.shared.global [%0], [%1], 16, %2;"
                 :: "r"(dst), "l"(src), "r"(szbytes));
}

// =====================================================================
// hgemm4: C = A * op(B planes), 3-split bf16 MMA (round-6 core).
// AMODE: 0 = plain fp32 A; 1 = A * silu(Ag) elementwise.
// =====================================================================
template<int TB, int AMODE>
__global__ __launch_bounds__(256, 2)
void hgemm4(const float* __restrict__ A, const float* __restrict__ Ag,
            const __nv_bfloat16* __restrict__ Bh, const __nv_bfloat16* __restrict__ Bl,
            const float* __restrict__ bias, const float* __restrict__ emul,
            float* __restrict__ C,
            int M, int N, int K, int lda, int ldb, int ldc, int Nout, int act, int KS,
            long long sA, long long sB, long long sC, long long sBias)
{
    __shared__ __align__(16) __nv_bfloat16 As_hi[128][SAS];
    __shared__ __align__(16) __nv_bfloat16 As_lo[128][SAS];
    __shared__ __align__(16) __nv_bfloat16 Bs_hi[128][SAS];
    __shared__ __align__(16) __nv_bfloat16 Bs_lo[128][SAS];

    int bz  = blockIdx.z;
    int dir = bz / KS;
    int ks  = bz % KS;
    A  += dir * sA;
    Bh += dir * sB; Bl += dir * sB;
    if (bias) bias += dir * sBias;
    int kchunk = K / KS;
    int kb = ks * kchunk, ke = kb + kchunk;

    int tid  = threadIdx.x;
    int lane = tid & 31;
    int wid  = tid >> 5;
    int wm0  = (wid >> 2) * 64;
    int wn0  = (wid & 3) * 32;
    int row0 = blockIdx.y * 128;
    int col0 = blockIdx.x * 128;

    int lr = lane & 15;
    int lc = (lane >> 4) * 8;

    int ar = tid >> 1;
    int ac = (tid & 1) * 8;
    int gm = row0 + ar;
    bool mok = gm < M;
    const float* Ap = A + (long long)gm * lda + ac;
    const float* Gp = (AMODE == 1) ? (Ag + (long long)gm * lda + ac) : nullptr;

    const __nv_bfloat16 *Bph = nullptr, *Bpl = nullptr;
    int bkk = 0, bnc = 0;
    if (TB == 1) {
        Bph = Bh + (long long)(col0 + ar) * ldb + ac;
        Bpl = Bl + (long long)(col0 + ar) * ldb + ac;
    } else {
        bkk = tid >> 4;
        bnc = (tid & 15) * 8;
        Bph = Bh + col0 + bnc;
        Bpl = Bl + col0 + bnc;
    }

    float4 ra0 = make_float4(0,0,0,0), ra1 = make_float4(0,0,0,0);
    float4 rg0 = make_float4(0,0,0,0), rg1 = make_float4(0,0,0,0);
    uint4 rbh, rbl;

    if (mok) {
        ra0 = *(const float4*)(Ap + kb); ra1 = *(const float4*)(Ap + kb + 4);
        if (AMODE == 1) { rg0 = *(const float4*)(Gp + kb); rg1 = *(const float4*)(Gp + kb + 4); }
    }
    if (TB == 1) {
        rbh = *(const uint4*)(Bph + kb); rbl = *(const uint4*)(Bpl + kb);
    } else {
        rbh = *(const uint4*)(Bph + (long long)(kb + bkk) * ldb);
        rbl = *(const uint4*)(Bpl + (long long)(kb + bkk) * ldb);
    }

    float acc[4][4][4];
    #pragma unroll
    for (int i = 0; i < 4; i++)
        #pragma unroll
        for (int j = 0; j < 4; j++)
            #pragma unroll
            for (int q = 0; q < 4; q++) acc[i][j][q] = 0.f;

    for (int k0 = kb; k0 < ke; k0 += 16) {
        {
            float av[8] = {ra0.x, ra0.y, ra0.z, ra0.w, ra1.x, ra1.y, ra1.z, ra1.w};
            if (AMODE == 1) {
                float gv[8] = {rg0.x, rg0.y, rg0.z, rg0.w, rg1.x, rg1.y, rg1.z, rg1.w};
                #pragma unroll
                for (int j = 0; j < 8; j++) av[j] *= gv[j] / (1.f + expf(-gv[j]));
            }
            __nv_bfloat16 hh[8], ll[8];
            #pragma unroll
            for (int j = 0; j < 8; j++) splitv(av[j], hh[j], ll[j]);
            *(uint4*)&As_hi[ar][ac] = *(uint4*)hh;
            *(uint4*)&As_lo[ar][ac] = *(uint4*)ll;
        }
        if (TB == 1) {
            *(uint4*)&Bs_hi[ar][ac] = rbh;
            *(uint4*)&Bs_lo[ar][ac] = rbl;
        } else {
            __nv_bfloat16 th[8], tl[8];
            *(uint4*)th = rbh; *(uint4*)tl = rbl;
            #pragma unroll
            for (int j = 0; j < 8; j++) {
                Bs_hi[bnc + j][bkk] = th[j];
                Bs_lo[bnc + j][bkk] = tl[j];
            }
        }
        __syncthreads();

        if (k0 + 16 < ke) {
            int kn = k0 + 16;
            if (mok) {
                ra0 = *(const float4*)(Ap + kn);
                ra1 = *(const float4*)(Ap + kn + 4);
                if (AMODE == 1) {
                    rg0 = *(const float4*)(Gp + kn);
                    rg1 = *(const float4*)(Gp + kn + 4);
                }
            }
            if (TB == 1) {
                rbh = *(const uint4*)(Bph + kn);
                rbl = *(const uint4*)(Bpl + kn);
            } else {
                rbh = *(const uint4*)(Bph + (long long)(kn + bkk) * ldb);
                rbl = *(const uint4*)(Bpl + (long long)(kn + bkk) * ldb);
            }
        }

        uint32_t bhf[2][4], blf[2][4];
        #pragma unroll
        for (int ng = 0; ng < 2; ng++) {
            ldsm4(bhf[ng], s2u(&Bs_hi[wn0 + ng * 16 + lr][lc]));
            ldsm4(blf[ng], s2u(&Bs_lo[wn0 + ng * 16 + lr][lc]));
        }
        #pragma unroll
        for (int mt = 0; mt < 4; mt++) {
            uint32_t a_h[4], a_l[4];
            ldsm4(a_h, s2u(&As_hi[wm0 + mt * 16 + lr][lc]));
            ldsm4(a_l, s2u(&As_lo[wm0 + mt * 16 + lr][lc]));
            #pragma unroll
            for (int nt = 0; nt < 4; nt++) {
                int ng = nt >> 1, sl = nt & 1;
                mma16816(acc[mt][nt], a_h, bhf[ng][sl], bhf[ng][sl + 2]);
                mma16816(acc[mt][nt], a_h, blf[ng][sl], blf[ng][sl + 2]);
                mma16816(acc[mt][nt], a_l, bhf[ng][sl], bhf[ng][sl + 2]);
            }
        }
        __syncthreads();
    }

    int g = lane >> 2, t4 = lane & 3;
    #pragma unroll
    for (int mt = 0; mt < 4; mt++) {
        #pragma unroll
        for (int nt = 0; nt < 4; nt++) {
            int cb = col0 + wn0 + nt * 8 + 2 * t4;
            if (cb >= Nout) continue;
            float b0 = 0.f, b1 = 0.f;
            if (bias && (KS == 1 || ks == 0)) { b0 = bias[cb]; b1 = bias[cb + 1]; }
            #pragma unroll
            for (int hrow = 0; hrow < 2; hrow++) {
                int m = row0 + wm0 + mt * 16 + g + hrow * 8;
                if (m >= M) continue;
                float v0 = acc[mt][nt][hrow * 2 + 0] + b0;
                float v1 = acc[mt][nt][hrow * 2 + 1] + b1;
                long long co = dir * sC + (long long)m * ldc + cb;
                if (KS > 1) {
                    atomicAdd(C + co, v0);
                    atomicAdd(C + co + 1, v1);
                } else {
                    if (act == 1) {
                        v0 = v0 / (1.f + expf(-v0));
                        v1 = v1 / (1.f + expf(-v1));
                    } else if (act == 2) {
                        v0 = (v0 > 20.f) ? v0 : log1pf(expf(v0));
                        v1 = (v1 > 20.f) ? v1 : log1pf(expf(v1));
                    }
                    if (emul) { v0 *= emul[co]; v1 *= emul[co + 1]; }
                    *(float2*)(C + co) = make_float2(v0, v1);
                }
            }
        }
    }
}

// =====================================================================
// hgemm_ca: big-GEMM specialist (xi, ycat). Optional bf16 split-plane
// outputs Ch/Cl (each C element written exactly once; same layout as C).
// =====================================================================
#define CA_PL  (128*SAS)
#define CA_STG (4*CA_PL)
#define CA_SMEM_BYTES (3*CA_STG*2)

__global__ __launch_bounds__(256, 2)
void hgemm_ca(const __nv_bfloat16* __restrict__ Ah, const __nv_bfloat16* __restrict__ Al,
              const __nv_bfloat16* __restrict__ Bh, const __nv_bfloat16* __restrict__ Bl,
              const float* __restrict__ bias, float* __restrict__ C,
              __nv_bfloat16* __restrict__ Ch, __nv_bfloat16* __restrict__ Cl,
              int M, int N, int K, int lda, int ldb, int ldc)
{
    extern __shared__ __align__(16) __nv_bfloat16 sm[];
    uint32_t smb = s2u(sm);

    int tid  = threadIdx.x;
    int lane = tid & 31;
    int wid  = tid >> 5;
    int wm0  = (wid >> 2) * 64;
    int wn0  = (wid & 3) * 32;
    int row0 = blockIdx.y * 128;
    int col0 = blockIdx.x * 128;

    int lr = lane & 15;
    int lc = (lane >> 4) * 8;

    int ar = tid >> 1;
    int ac = (tid & 1) * 8;
    int gm = row0 + ar;
    int asz = (gm < M) ? 16 : 0;
    const __nv_bfloat16* Aph = Ah + (long long)gm * lda + ac;
    const __nv_bfloat16* Apl = Al + (long long)gm * lda + ac;
    const __nv_bfloat16* Bph = Bh + (long long)(col0 + ar) * ldb + ac;
    const __nv_bfloat16* Bpl = Bl + (long long)(col0 + ar) * ldb + ac;

    uint32_t offA_h = (uint32_t)(0 * CA_PL + ar * SAS + ac) * 2;
    uint32_t offA_l = (uint32_t)(1 * CA_PL + ar * SAS + ac) * 2;
    uint32_t offB_h = (uint32_t)(2 * CA_PL + ar * SAS + ac) * 2;
    uint32_t offB_l = (uint32_t)(3 * CA_PL + ar * SAS + ac) * 2;

    float acc[4][4][4];
    #pragma unroll
    for (int i = 0; i < 4; i++)
        #pragma unroll
        for (int j = 0; j < 4; j++)
            #pragma unroll
            for (int q = 0; q < 4; q++) acc[i][j][q] = 0.f;

    {
        uint32_t sb = smb;
        cpasync16(sb + offA_h, Aph + 0, asz);
        cpasync16(sb + offA_l, Apl + 0, asz);
        cpasync16(sb + offB_h, Bph + 0, 16);
        cpasync16(sb + offB_l, Bpl + 0, 16);
        asm volatile("cp.async.commit_group;" ::: "memory");
    }
    if (16 < K) {
        uint32_t sb = smb + CA_STG * 2;
        cpasync16(sb + offA_h, Aph + 16, asz);
        cpasync16(sb + offA_l, Apl + 16, asz);
        cpasync16(sb + offB_h, Bph + 16, 16);
        cpasync16(sb + offB_l, Bpl + 16, 16);
        asm volatile("cp.async.commit_group;" ::: "memory");
    } else {
        asm volatile("cp.async.commit_group;" ::: "memory");
    }

    int cur = 0;
    for (int k0 = 0; k0 < K; k0 += 16) {
        asm volatile("cp.async.wait_group 1;" ::: "memory");
        __syncthreads();

        uint32_t sb = smb + (uint32_t)cur * (CA_STG * 2);

        uint32_t bhf[2][4], blf[2][4];
        #pragma unroll
        for (int ng = 0; ng < 2; ng++) {
            uint32_t rb = (uint32_t)(wn0 + ng * 16 + lr) * SAS + lc;
            ldsm4(bhf[ng], sb + (uint32_t)(2 * CA_PL) * 2 + rb * 2);
            ldsm4(blf[ng], sb + (uint32_t)(3 * CA_PL) * 2 + rb * 2);
        }
        #pragma unroll
        for (int mt = 0; mt < 4; mt++) {
            uint32_t raddr = (uint32_t)(wm0 + mt * 16 + lr) * SAS + lc;
            uint32_t a_h[4], a_l[4];
            ldsm4(a_h, sb + raddr * 2);
            ldsm4(a_l, sb + (uint32_t)(CA_PL) * 2 + raddr * 2);
            #pragma unroll
            for (int nt = 0; nt < 4; nt++) {
                int ng = nt >> 1, sl = nt & 1;
                mma16816(acc[mt][nt], a_h, bhf[ng][sl], bhf[ng][sl + 2]);
                mma16816(acc[mt][nt], a_h, blf[ng][sl], blf[ng][sl + 2]);
                mma16816(acc[mt][nt], a_l, bhf[ng][sl], bhf[ng][sl + 2]);
            }
        }

        int nk = k0 + 32;
        if (nk < K) {
            int nst = cur + 2; if (nst >= 3) nst -= 3;
            uint32_t nb = smb + (uint32_t)nst * (CA_STG * 2);
            cpasync16(nb + offA_h, Aph + nk, asz);
            cpasync16(nb + offA_l, Apl + nk, asz);
            cpasync16(nb + offB_h, Bph + nk, 16);
            cpasync16(nb + offB_l, Bpl + nk, 16);
        }
        asm volatile("cp.async.commit_group;" ::: "memory");

        cur++; if (cur == 3) cur = 0;
    }

    int g = lane >> 2, t4 = lane & 3;
    #pragma unroll
    for (int mt = 0; mt < 4; mt++) {
        #pragma unroll
        for (int nt = 0; nt < 4; nt++) {
            int cb = col0 + wn0 + nt * 8 + 2 * t4;
            float b0 = 0.f, b1 = 0.f;
            if (bias) { b0 = bias[cb]; b1 = bias[cb + 1]; }
            #pragma unroll
            for (int hrow = 0; hrow < 2; hrow++) {
                int m = row0 + wm0 + mt * 16 + g + hrow * 8;
                if (m >= M) continue;
                float v0 = acc[mt][nt][hrow * 2 + 0] + b0;
                float v1 = acc[mt][nt][hrow * 2 + 1] + b1;
                long long co = (long long)m * ldc + cb;
                *(float2*)(C + co) = make_float2(v0, v1);
                if (Ch) {
                    __nv_bfloat16 h0, l0, h1, l1;
                    splitv(v0, h0, l0); splitv(v1, h1, l1);
                    *(__nv_bfloat162*)(Ch + co) = __nv_bfloat162(h0, h1);
                    *(__nv_bfloat162*)(Cl + co) = __nv_bfloat162(l0, l1);
                }
            }
        }
    }
}

// ---------------- depthwise conv + SiLU, t-tiled (CT steps/block), both dirs ----------------
__global__ void conv_silu2_kernel(const float* __restrict__ xi,
                                  const float* __restrict__ wf, const float* __restrict__ bf,
                                  const float* __restrict__ wb, const float* __restrict__ bb)
{
    int t0 = blockIdx.x * CT;
    int b = blockIdx.y;
    int back = blockIdx.z;
    int c = threadIdx.x;
    const float* w  = back ? wb : wf;
    float bias      = back ? bb[c] : bf[c];
    float* out      = g_u + (long long)back * SZ_U;

    float w0 = w[c * 4 + 0], w1 = w[c * 4 + 1], w2 = w[c * 4 + 2], w3 = w[c * 4 + 3];

    float xv[CT + 3];
    #pragma unroll
    for (int j = 0; j < CT + 3; j++) {
        int i = t0 + j - 3;
        float v = 0.f;
        if (i >= 0 && i < LB) {
            int l = back ? (Lseq - 1 - i) : i;
            v = xi[((long long)b * Lseq + l) * DI + c];
        }
        xv[j] = v;
    }
    #pragma unroll
    for (int j = 0; j < CT; j++) {
        int t = t0 + j;
        if (t >= LC) break;
        float acc = bias;
        acc = fmaf(w0, xv[j],     acc);
        acc = fmaf(w1, xv[j + 1], acc);
        acc = fmaf(w2, xv[j + 2], acc);
        acc = fmaf(w3, xv[j + 3], acc);
        out[((long long)b * LC + t) * DI + c] = acc / (1.f + expf(-acc));
    }
}

// ---------------- selective scans: 16 lanes/channel, float2 B/C ----------------
__global__ __launch_bounds__(256)
void scan2_kernel(const float* __restrict__ A_log_f, const float* __restrict__ D_f,
                  const float* __restrict__ A_log_b, const float* __restrict__ D_b)
{
    int back = blockIdx.y;
    const float* u     = g_u     + (long long)back * SZ_U;
    const float* delta = g_delta + (long long)back * SZ_U;
    const float* dbc   = g_dbc   + (long long)back * SZ_DBC;
    const float* A_log = back ? A_log_b : A_log_f;
    const float* Dp    = back ? D_b : D_f;
    float* y           = g_ysc   + (long long)back * SZ_U;

    int gid = blockIdx.x * 16 + (threadIdx.x >> 4);
    int s = threadIdx.x & 15;
    int b = gid >> 9;
    int d = gid & 511;
    float Av = -expf(A_log[d * 16 + s]);
    float Dd = Dp[d];
    float h = 0.f;
    const float* db = dbc + (long long)b * LC * NXP + 16 + 2 * s;  // interleaved B,C
    const float* dl = delta + ((long long)b * LC) * DI + d;
    const float* uu = u     + ((long long)b * LC) * DI + d;
    float*       yy = y     + ((long long)b * LC) * DI + d;
    #pragma unroll 4
    for (int t = 0; t < LC; t++) {
        float de = __ldg(dl + (long long)t * DI);
        float uv = __ldg(uu + (long long)t * DI);
        float2 bc = __ldg((const float2*)(db + t * NXP));
        float dA = __expf(de * Av);
        h = fmaf(dA, h, de * uv * bc.x);
        float v = h * bc.y;
        v += __shfl_xor_sync(0xffffffffu, v, 8);
        v += __shfl_xor_sync(0xffffffffu, v, 4);
        v += __shfl_xor_sync(0xffffffffu, v, 2);
        v += __shfl_xor_sync(0xffffffffu, v, 1);
        if (s == 0) yy[(long long)t * DI] = fmaf(Dd, uv, v);
    }
}

// ---------------- gaussian masks ----------------
__global__ void dist2_kernel(int ref)
{
    int back = blockIdx.z;
    const float* y = g_ysc + (long long)back * SZ_U;
    float* dist = g_dist + back * (Bsz * LC);
    int b = blockIdx.y;
    int t = blockIdx.x * 8 + (threadIdx.x >> 5);
    int lane = threadIdx.x & 31;
    if (t >= LC) return;
    const float* yt = y + ((long long)b * LC + t) * DI;
    const float* yr = y + ((long long)b * LC + ref) * DI;
    float acc = 0.f;
    for (int d = lane; d < DI; d += 32) {
        float df = yt[d] - yr[d];
        acc = fmaf(df, df, acc);
    }
    #pragma unroll
    for (int o = 16; o; o >>= 1) acc += __shfl_xor_sync(0xffffffffu, acc, o);
    if (lane == 0) dist[b * LC + t] = sqrtf(fmaxf(acc, 1e-12f));
}

__global__ void dist_kernel(const float* __restrict__ y, float* __restrict__ dist, int ref)
{
    int b = blockIdx.y;
    int t = blockIdx.x * 8 + (threadIdx.x >> 5);
    int lane = threadIdx.x & 31;
    if (t >= LC) return;
    const float* yt = y + ((long long)b * LC + t) * DI;
    const float* yr = y + ((long long)b * LC + ref) * DI;
    float acc = 0.f;
    for (int d = lane; d < DI; d += 32) {
        float df = yt[d] - yr[d];
        acc = fmaf(df, df, acc);
    }
    #pragma unroll
    for (int o = 16; o; o >>= 1) acc += __shfl_xor_sync(0xffffffffu, acc, o);
    if (lane == 0) dist[b * LC + t] = sqrtf(fmaxf(acc, 1e-12f));
}

__device__ __forceinline__ void maskfin_body(const float* dist, float* m, int ref,
                                             float* red, int tid)
{
    float s = 0.f;
    for (int t = tid; t < LC; t += 512) s += dist[t];
    red[tid] = s; __syncthreads();
    for (int o = 256; o; o >>= 1) { if (tid < o) red[tid] += red[tid + o]; __syncthreads(); }
    float sigv = red[0] / (float)LC;
    __syncthreads();
    float si = ((float)ref * (float)(ref + 1) * 0.5f +
                (float)(LC - 1 - ref) * (float)(LC - ref) * 0.5f) / (float)LC;
    float c_i = 0.5f / (si * si);
    float c_v = 0.5f / (sigv * sigv);
    float nrm = 0.f;
    for (int t = tid; t < LC; t += 512) {
        float dt = (float)(t - ref);
        float dv = dist[t];
        float p = expf(-dt * dt * c_i - dv * dv * c_v);
        m[t] = p;
        nrm = fmaf(p, p, nrm);
    }
    red[tid] = nrm; __syncthreads();
    for (int o = 256; o; o >>= 1) { if (tid < o) red[tid] += red[tid + o]; __syncthreads(); }
    float inv = 1.f / fmaxf(sqrtf(red[0]), 1e-12f);
    __syncthreads();
    for (int t = tid; t < LC; t += 512) m[t] *= inv;
}

__global__ void maskfin2_kernel(int ref)
{
    __shared__ float red[512];
    int back = blockIdx.y;
    int b = blockIdx.x;
    const float* dist = g_dist + back * (Bsz * LC) + b * LC;
    float* m = (back ? g_mb : g_mf) + b * LC;
    maskfin_body(dist, m, ref, red, threadIdx.x);
}

__global__ void maskfin_kernel(const float* __restrict__ dist, float* __restrict__ m, int ref)
{
    __shared__ float red[512];
    int b = blockIdx.x;
    maskfin_body(dist + b * LC, m + b * LC, ref, red, threadIdx.x);
}

// ycat = [ y_f * m_f , y_b * reverse(m_b) ]  -> bf16 split planes
__global__ void concat_kernel()
{
    int t = blockIdx.x, b = blockIdx.y, c = threadIdx.x;
    long long r = (long long)b * LC + t;
    float v0 = g_ysc[r * DI + c] * g_mf[b * LC + t];
    float v1 = g_ysc[SZ_U + r * DI + c] * g_mb[b * LC + (LC - 1 - t)];
    __nv_bfloat16 h, l;
    splitv(v0, h, l);
    g_ycath[r * (2 * DI) + c] = h;      g_ycatl[r * (2 * DI) + c] = l;
    splitv(v1, h, l);
    g_ycath[r * (2 * DI) + DI + c] = h; g_ycatl[r * (2 * DI) + DI + c] = l;
}

// softmax over l per (b, token): reads raw scores, folds mc in on both
// input (scores_scaled = mc*raw) and output (atok' = softmax * mc).
__global__ void softmax_kernel()
{
    __shared__ float sv[LC];
    __shared__ float red[256];
    int tt = blockIdx.x, b = blockIdx.y, tid = threadIdx.x;
    float mx = -1e30f;
    for (int l = tid; l < LC; l += 256) {
        float v = g_scores[((long long)b * LC + l) * Stok + tt] * g_mc[b * LC + l];
        sv[l] = v; mx = fmaxf(mx, v);
    }
    red[tid] = mx; __syncthreads();
    for (int o = 128; o; o >>= 1) { if (tid < o) red[tid] = fmaxf(red[tid], red[tid + o]); __syncthreads(); }
    mx = red[0]; __syncthreads();
    float sum = 0.f;
    for (int l = tid; l < LC; l += 256) { float e = expf(sv[l] - mx); sv[l] = e; sum += e; }
    red[tid] = sum; __syncthreads();
    for (int o = 128; o; o >>= 1) { if (tid < o) red[tid] += red[tid + o]; __syncthreads(); }
    float inv = 1.f / red[0]; __syncthreads();
    long long base = ((long long)b * Stok + tt) * LCP;
    for (int l = tid; l < LC; l += 256)
        g_atok[base + l] = sv[l] * inv * g_mc[b * LC + l];
    if (tid < LCP - LC) g_atok[base + LC + tid] = 0.f;
}

// ---------------- host launcher ----------------
static inline int ceildiv(int a, int b) { return (a + b - 1) / b; }

extern "C" void kernel_launch(void* const* d_in, const int* in_sizes, int n_in,
                              void* d_out, int out_size)
{
    const float* x        = (const float*)d_in[0];
    const float* W_in_x   = (const float*)d_in[1];
    const float* W_in_z   = (const float*)d_in[2];
    const float* conv_w_f = (const float*)d_in[3];
    const float* conv_b_f = (const float*)d_in[4];
    const float* conv_w_b = (const float*)d_in[5];
    const float* conv_b_b = (const float*)d_in[6];
    const float* W_xp_f   = (const float*)d_in[7];
    const float* b_xp_f   = (const float*)d_in[8];
    const float* W_dt_f   = (const float*)d_in[9];
    const float* b_dt_f   = (const float*)d_in[10];
    const float* A_log_f  = (const float*)d_in[11];
    const float* D_f      = (const float*)d_in[12];
    const float* W_xp_b   = (const float*)d_in[13];
    const float* b_xp_b   = (const float*)d_in[14];
    const float* W_dt_b   = (const float*)d_in[15];
    const float* b_dt_b   = (const float*)d_in[16];
    const float* A_log_b  = (const float*)d_in[17];
    const float* D_b      = (const float*)d_in[18];
    const float* W_pro_to = (const float*)d_in[19];
    const float* b_pro_to = (const float*)d_in[20];
    const float* token_wA = (const float*)d_in[21];
    const float* token_wV = (const float*)d_in[22];
    const float* W_out    = (const float*)d_in[23];
    float* out = (float*)d_out;

    // one-time side stream + fork/join events (created on the first,
    // non-captured correctness call; per-call work is identical thereafter)
    static cudaStream_t s_side = nullptr;
    static cudaEvent_t  s_fork = nullptr, s_join = nullptr;
    static cudaEvent_t  s_fork2 = nullptr, s_join2 = nullptr;
    if (s_side == nullptr) {
        cudaStreamCreateWithFlags(&s_side, cudaStreamNonBlocking);
        cudaEventCreateWithFlags(&s_fork, cudaEventDisableTiming);
        cudaEventCreateWithFlags(&s_join, cudaEventDisableTiming);
        cudaEventCreateWithFlags(&s_fork2, cudaEventDisableTiming);
        cudaEventCreateWithFlags(&s_join2, cudaEventDisableTiming);
    }

    float *xi, *u, *dbc, *delta, *yy, *mc, *dist, *xpf, *zpacc;
    float *scores, *atok, *tyacc, *Tacc, *bxp, *bdt;
    cudaGetSymbolAddress((void**)&xi,    g_xi);
    cudaGetSymbolAddress((void**)&u,     g_u);
    cudaGetSymbolAddress((void**)&dbc,   g_dbc);
    cudaGetSymbolAddress((void**)&delta, g_delta);
    cudaGetSymbolAddress((void**)&yy,    g_y);
    cudaGetSymbolAddress((void**)&mc,    g_mc);
    cudaGetSymbolAddress((void**)&dist,  g_dist);
    cudaGetSymbolAddress((void**)&xpf,   g_xpf);
    cudaGetSymbolAddress((void**)&zpacc, g_zpacc);
    cudaGetSymbolAddress((void**)&scores, g_scores);
    cudaGetSymbolAddress((void**)&atok,  g_atok);
    cudaGetSymbolAddress((void**)&tyacc, g_tyacc);
    cudaGetSymbolAddress((void**)&Tacc,  g_Tacc);
    cudaGetSymbolAddress((void**)&bxp,   g_bxp);
    cudaGetSymbolAddress((void**)&bdt,   g_bdt);

    __nv_bfloat16 *xh,*xl,*Winxh,*Winxl,*Winzh,*Winzl,*Wxph,*Wxpl,*Wdth,*Wdtl;
    __nv_bfloat16 *Wproh,*Wprol,*wAh,*wAl,*wVh,*wVl,*Wouth,*Woutl;
    __nv_bfloat16 *ycath,*ycatl,*yh2,*yl2;
    cudaGetSymbolAddress((void**)&xh, g_xh);         cudaGetSymbolAddress((void**)&xl, g_xl);
    cudaGetSymbolAddress((void**)&Winxh, g_Winx_h);  cudaGetSymbolAddress((void**)&Winxl, g_Winx_l);
    cudaGetSymbolAddress((void**)&Winzh, g_Winz_h);  cudaGetSymbolAddress((void**)&Winzl, g_Winz_l);
    cudaGetSymbolAddress((void**)&Wxph, g_Wxp_h);    cudaGetSymbolAddress((void**)&Wxpl, g_Wxp_l);
    cudaGetSymbolAddress((void**)&Wdth, g_Wdt_h);    cudaGetSymbolAddress((void**)&Wdtl, g_Wdt_l);
    cudaGetSymbolAddress((void**)&Wproh, g_Wpro_h);  cudaGetSymbolAddress((void**)&Wprol, g_Wpro_l);
    cudaGetSymbolAddress((void**)&wAh, g_wA_h);      cudaGetSymbolAddress((void**)&wAl, g_wA_l);
    cudaGetSymbolAddress((void**)&wVh, g_wV_h);      cudaGetSymbolAddress((void**)&wVl, g_wV_l);
    cudaGetSymbolAddress((void**)&Wouth, g_Wout_h);  cudaGetSymbolAddress((void**)&Woutl, g_Wout_l);
    cudaGetSymbolAddress((void**)&ycath, g_ycath);   cudaGetSymbolAddress((void**)&ycatl, g_ycatl);
    cudaGetSymbolAddress((void**)&yh2, g_yh);        cudaGetSymbolAddress((void**)&yl2, g_yl);

    cudaFuncSetAttribute(hgemm_ca, cudaFuncAttributeMaxDynamicSharedMemorySize, CA_SMEM_BYTES);

    // 0) fused init: zero accums + weight splits (Wxp permuted) + x split + pooling
    init_kernel<<<ceildiv(INIT_TOT, 256), 256>>>(
        x, W_in_x, W_in_z, W_xp_f, W_xp_b, W_dt_f, W_dt_b, W_pro_to,
        token_wA, token_wV, W_out, b_xp_f, b_xp_b, b_dt_f, b_dt_b, out);

    // fork 1: zp GEMM on the side stream, off the critical path
    cudaEventRecord(s_fork, 0);
    cudaStreamWaitEvent(s_side, s_fork, 0);
    hgemm4<1,0><<<dim3(DI / 128, 4, 4), 256, 0, s_side>>>(
        xpf, nullptr, Winzh, Winzl, nullptr, nullptr, zpacc,
        Bsz * Stok, DI, Dmod, Dmod, Dmod, DI, DI, 0, 4, 0, 0, 0, 0);
    cudaEventRecord(s_join, s_side);

    // 1) xi = x @ W_in_x^T  (cp.async pipeline, pre-split planes)
    hgemm_ca<<<dim3(DI / 128, ceildiv(ML, 128)), 256, CA_SMEM_BYTES>>>(
        xh, xl, Winxh, Winxl, nullptr, xi, nullptr, nullptr,
        ML, DI, Dmod, Dmod, Dmod, DI);

    // 3) conv + silu (both dirs, t-tiled CT=16)
    conv_silu2_kernel<<<dim3(ceildiv(LC, CT), Bsz, 2), DI>>>(
        xi, conv_w_f, conv_b_f, conv_w_b, conv_b_b);

    // 4) dbc = u @ W_xp^T + b  (merged dirs, split-K2, atomic; cols permuted)
    hgemm4<1,0><<<dim3(1, ceildiv(MC, 128), 4), 256>>>(
        u, nullptr, Wxph, Wxpl, bxp, nullptr, dbc,
        MC, 128, DI, DI, DI, NXP, NXP, 0, 2,
        (long long)SZ_U, (long long)128 * DI, (long long)SZ_DBC, 128);

    // 5) delta = softplus(dr @ W_dt^T + b_dt)  (merged dirs, K=16)
    hgemm4<1,0><<<dim3(DI / 128, ceildiv(MC, 128), 2), 256>>>(
        dbc, nullptr, Wdth, Wdtl, bdt, nullptr, delta,
        MC, DI, DRK, NXP, DRK, DI, DI, 2, 1,
        (long long)SZ_DBC, (long long)DI * DRK, (long long)SZ_U, DI);

    // 6) selective scans (both dirs, 16 lanes/channel, float2 B/C)
    scan2_kernel<<<dim3(Bsz * DI / 16, 2), 256>>>(A_log_f, D_f, A_log_b, D_b);

    // 7) masks ('last'), both dirs
    dist2_kernel<<<dim3(ceildiv(LC, 8), Bsz, 2), 256>>>(LC - 1);
    maskfin2_kernel<<<dim3(Bsz, 2), 512>>>(LC - 1);

    // 8) ycat planes; y = ycat @ W_pro^T + b (cp.async pipeline)
    //    epilogue also emits raw-y split planes (yh/yl)
    concat_kernel<<<dim3(LC, Bsz), DI>>>();
    hgemm_ca<<<dim3(DI / 128, ceildiv(MC, 128)), 256, CA_SMEM_BYTES>>>(
        ycath, ycatl, Wproh, Wprol, b_pro_to, yy, yh2, yl2,
        MC, DI, 2 * DI, 2 * DI, 2 * DI, DI);

    // fork 2: scores_raw = y_raw @ wA^T on the side stream, concurrent
    // with dist/maskfin on the main stream (mc folded into softmax).
    cudaEventRecord(s_fork2, 0);
    cudaStreamWaitEvent(s_side, s_fork2, 0);
    hgemm4<1,0><<<dim3(1, ceildiv(MC, 128), 2), 256, 0, s_side>>>(
        yy, nullptr, wAh, wAl, nullptr, nullptr, scores,
        MC, 128, DI, DI, DI, Stok, Stok, 0, 2, 0, 0, 0, 0);
    cudaEventRecord(s_join2, s_side);

    // 9) center mask from raw y (main stream)
    dist_kernel<<<dim3(ceildiv(LC, 8), Bsz), 256>>>(yy, dist, (LC + 1) / 2);
    maskfin_kernel<<<Bsz, 512>>>(dist, mc, (LC + 1) / 2);

    // join 2: scores must be complete before softmax
    cudaStreamWaitEvent(0, s_join2, 0);

    // 10) softmax (mc-aware) -> atok' = softmax(mc*raw) * mc
    softmax_kernel<<<dim3(Stok, Bsz), 256>>>();

    // 11) Ty = atok' @ y_raw  (TB=0, batched over b, split-K5, atomic)
    hgemm4<0,0><<<dim3(DI / 128, 1, Bsz * 5), 256>>>(
        atok, nullptr, yh2, yl2, nullptr, nullptr, tyacc,
        Stok, DI, LCP, LCP, DI, DI, DI, 0, 5,
        (long long)Stok * LCP, (long long)LC * DI, (long long)Stok * DI, 0);

    // 12) Tacc = Ty @ wV  (TB=0, batched, split-K4, atomic)
    hgemm4<0,0><<<dim3(DI / 128, 1, Bsz * 4), 256>>>(
        tyacc, nullptr, wVh, wVl, nullptr, nullptr, Tacc,
        Stok, DI, DI, DI, DI, DI, DI, 0, 4,
        (long long)Stok * DI, 0, (long long)Stok * DI, 0);

    // join 1: zpacc must be complete before the gated out-GEMM
    cudaStreamWaitEvent(0, s_join, 0);

    // 13) out = (Tacc * silu(zpacc)) @ W_out^T  (gated A, split-K4, atomic)
    hgemm4<1,1><<<dim3(Dmod / 128, 4, 4), 256>>>(
        Tacc, zpacc, Wouth, Woutl, nullptr, nullptr, out,
        Bsz * Stok, Dmod, DI, DI, DI, Dmod, Dmod, 0, 4, 0, 0, 0, 0);
}